// round 1
// baseline (speedup 1.0000x reference)
#include <cuda_runtime.h>
#include <math.h>

#define S_LEN 2048
#define DIM 3072
#define HEADS 24
#define HEAD_DIM 128
#define MLP_H 12288

// ---------------- scratch (device globals; no allocs allowed) ----------------
__device__ float g_silu[DIM];
__device__ float g_emb[3 * DIM];
__device__ float g_nh[S_LEN * DIM];
__device__ float g_mlp[S_LEN * MLP_H];
__device__ float g_q[S_LEN * DIM];
__device__ float g_k[S_LEN * DIM];
__device__ float g_v[S_LEN * DIM];
__device__ float g_attn[S_LEN * DIM];
__device__ float g_c[S_LEN * DIM];

// ---------------- small elementwise kernels ----------------
__global__ void silu_kernel(const float* __restrict__ temb, float* __restrict__ out) {
    int i = blockIdx.x * blockDim.x + threadIdx.x;
    if (i < DIM) {
        float v = temb[i];
        out[i] = v / (1.f + __expf(-v));
    }
}

// emb[j] = dot(silu(temb), norm_w[j,:]) + norm_b[j]
__global__ __launch_bounds__(128) void emb_gemv(const float* __restrict__ sil,
                                                const float* __restrict__ w,
                                                const float* __restrict__ b,
                                                float* __restrict__ emb) {
    int jrow = blockIdx.x;
    const float* wr = w + (size_t)jrow * DIM;
    int tid = threadIdx.x;
    float s = 0.f;
    for (int i = tid * 4; i < DIM; i += 512) {
        float4 a = *(const float4*)(sil + i);
        float4 ww = *(const float4*)(wr + i);
        s += a.x * ww.x + a.y * ww.y + a.z * ww.z + a.w * ww.w;
    }
    for (int o = 16; o > 0; o >>= 1) s += __shfl_xor_sync(0xffffffffu, s, o);
    __shared__ float sm[4];
    if ((tid & 31) == 0) sm[tid >> 5] = s;
    __syncthreads();
    if (tid == 0) emb[jrow] = sm[0] + sm[1] + sm[2] + sm[3] + b[jrow];
}

// LayerNorm + adaLN modulate: nh = ln(x)*(1+scale) + shift
__global__ __launch_bounds__(256) void ln_mod(const float* __restrict__ x,
                                              const float* __restrict__ emb,
                                              float* __restrict__ nh) {
    int srow = blockIdx.x;
    int tid = threadIdx.x;
    const float* row = x + (size_t)srow * DIM;
    float sum = 0.f, sq = 0.f;
    for (int i = tid * 4; i < DIM; i += 1024) {
        float4 v = *(const float4*)(row + i);
        sum += v.x + v.y + v.z + v.w;
        sq  += v.x * v.x + v.y * v.y + v.z * v.z + v.w * v.w;
    }
    for (int o = 16; o > 0; o >>= 1) {
        sum += __shfl_xor_sync(0xffffffffu, sum, o);
        sq  += __shfl_xor_sync(0xffffffffu, sq, o);
    }
    __shared__ float s1[8], s2[8];
    if ((tid & 31) == 0) { s1[tid >> 5] = sum; s2[tid >> 5] = sq; }
    __syncthreads();
    sum = 0.f; sq = 0.f;
#pragma unroll
    for (int w = 0; w < 8; w++) { sum += s1[w]; sq += s2[w]; }
    float mean = sum * (1.f / DIM);
    float var = sq * (1.f / DIM) - mean * mean;
    float rstd = rsqrtf(var + 1e-6f);
    float* orow = nh + (size_t)srow * DIM;
    for (int i = tid * 4; i < DIM; i += 1024) {
        float4 v = *(const float4*)(row + i);
        float4 sc = *(const float4*)(emb + DIM + i);
        float4 sh = *(const float4*)(emb + i);
        float4 o;
        o.x = (v.x - mean) * rstd * (1.f + sc.x) + sh.x;
        o.y = (v.y - mean) * rstd * (1.f + sc.y) + sh.y;
        o.z = (v.z - mean) * rstd * (1.f + sc.z) + sh.z;
        o.w = (v.w - mean) * rstd * (1.f + sc.w) + sh.w;
        *(float4*)(orow + i) = o;
    }
}

// ---------------- generic NT GEMM: C[m,n] = sum_k A[m,k]*B[n,k] (+bias)(+gelu)(+=C) ----
#define BM 128
#define BN 64
#define BK 16

__global__ __launch_bounds__(256) void gemm_nt(const float* __restrict__ A, int lda,
                                               const float* __restrict__ B, int ldb,
                                               float* __restrict__ C, int ldc,
                                               int K,
                                               const float* __restrict__ bias,
                                               int act, int accum) {
    __shared__ float As[BK][BM];
    __shared__ float Bs[BK][BN];
    int bm0 = blockIdx.y * BM;
    int bn0 = blockIdx.x * BN;
    int tid = threadIdx.x;
    int ty = tid >> 4;   // 0..15
    int tx = tid & 15;   // 0..15

    float acc[8][4];
#pragma unroll
    for (int i = 0; i < 8; i++)
#pragma unroll
        for (int j = 0; j < 4; j++) acc[i][j] = 0.f;

    for (int k0 = 0; k0 < K; k0 += BK) {
#pragma unroll
        for (int i = 0; i < 2; i++) {
            int idx = tid + i * 256;         // 0..511 float4s of A tile
            int row = idx >> 2;
            int k4 = idx & 3;
            float4 t = *(const float4*)(A + (size_t)(bm0 + row) * lda + k0 + k4 * 4);
            As[k4 * 4 + 0][row] = t.x;
            As[k4 * 4 + 1][row] = t.y;
            As[k4 * 4 + 2][row] = t.z;
            As[k4 * 4 + 3][row] = t.w;
        }
        {
            int row = tid >> 2;
            int k4 = tid & 3;
            float4 t = *(const float4*)(B + (size_t)(bn0 + row) * ldb + k0 + k4 * 4);
            Bs[k4 * 4 + 0][row] = t.x;
            Bs[k4 * 4 + 1][row] = t.y;
            Bs[k4 * 4 + 2][row] = t.z;
            Bs[k4 * 4 + 3][row] = t.w;
        }
        __syncthreads();
#pragma unroll
        for (int k = 0; k < BK; k++) {
            float4 a0 = *(const float4*)&As[k][ty * 8];
            float4 a1 = *(const float4*)&As[k][ty * 8 + 4];
            float4 b  = *(const float4*)&Bs[k][tx * 4];
            float av[8] = {a0.x, a0.y, a0.z, a0.w, a1.x, a1.y, a1.z, a1.w};
            float bv[4] = {b.x, b.y, b.z, b.w};
#pragma unroll
            for (int i = 0; i < 8; i++)
#pragma unroll
                for (int j = 0; j < 4; j++) acc[i][j] += av[i] * bv[j];
        }
        __syncthreads();
    }

    // epilogue
#pragma unroll
    for (int i = 0; i < 8; i++) {
        int m = bm0 + ty * 8 + i;
        float* cp = C + (size_t)m * ldc + bn0 + tx * 4;
        float4 v = make_float4(acc[i][0], acc[i][1], acc[i][2], acc[i][3]);
        if (accum) {
            float4 old = *(const float4*)cp;
            v.x += old.x; v.y += old.y; v.z += old.z; v.w += old.w;
        }
        if (bias) {
            float4 bb = *(const float4*)(bias + bn0 + tx * 4);
            v.x += bb.x; v.y += bb.y; v.z += bb.z; v.w += bb.w;
        }
        if (act == 1) {  // gelu tanh approx
            float vs[4] = {v.x, v.y, v.z, v.w};
#pragma unroll
            for (int j = 0; j < 4; j++) {
                float x = vs[j];
                float inner = 0.7978845608028654f * (x + 0.044715f * x * x * x);
                vs[j] = 0.5f * x * (1.f + tanhf(inner));
            }
            v = make_float4(vs[0], vs[1], vs[2], vs[3]);
        }
        *(float4*)cp = v;
    }
}

// ---------------- RMSNorm + RoPE for q and k ----------------
__global__ __launch_bounds__(128) void rmsrope(float* __restrict__ Q, float* __restrict__ Kp,
                                               const float* __restrict__ rc,
                                               const float* __restrict__ rs,
                                               const float* __restrict__ wq,
                                               const float* __restrict__ wk) {
    int s = blockIdx.x, h = blockIdx.y;
    int d = threadIdx.x;  // 0..127
    int lane = d & 31, wid = d >> 5;
    __shared__ float red[4];
    float cosd = rc[s * HEAD_DIM + d];
    float sind = rs[s * HEAD_DIM + d];
    size_t off = (size_t)s * DIM + h * HEAD_DIM + d;

    // Q
    {
        float v = Q[off];
        float ss = v * v;
        for (int o = 16; o > 0; o >>= 1) ss += __shfl_xor_sync(0xffffffffu, ss, o);
        if (lane == 0) red[wid] = ss;
        __syncthreads();
        float tot = red[0] + red[1] + red[2] + red[3];
        float xn = v * rsqrtf(tot * (1.f / HEAD_DIM) + 1e-6f) * wq[d];
        float part = __shfl_xor_sync(0xffffffffu, xn, 1);
        float rot = (d & 1) ? part : -part;
        Q[off] = xn * cosd + rot * sind;
        __syncthreads();
    }
    // K
    {
        float v = Kp[off];
        float ss = v * v;
        for (int o = 16; o > 0; o >>= 1) ss += __shfl_xor_sync(0xffffffffu, ss, o);
        if (lane == 0) red[wid] = ss;
        __syncthreads();
        float tot = red[0] + red[1] + red[2] + red[3];
        float xn = v * rsqrtf(tot * (1.f / HEAD_DIM) + 1e-6f) * wk[d];
        float part = __shfl_xor_sync(0xffffffffu, xn, 1);
        float rot = (d & 1) ? part : -part;
        Kp[off] = xn * cosd + rot * sind;
    }
}

// ---------------- fp32 flash attention ----------------
#define FA_BR 64
#define FA_BC 32

__global__ __launch_bounds__(256) void flash_attn(const float* __restrict__ Q,
                                                  const float* __restrict__ K,
                                                  const float* __restrict__ V,
                                                  float* __restrict__ O) {
    int h = blockIdx.y;
    int s0 = blockIdx.x * FA_BR;
    int tid = threadIdx.x;
    int r = tid >> 2;  // 0..63 row within q tile
    int j = tid & 3;   // dim quarter (32 dims)

    __shared__ float Ks[FA_BC][HEAD_DIM];
    __shared__ float Vs[FA_BC][HEAD_DIM];

    const float scale = 0.08838834764831845f;  // 1/sqrt(128)
    float q[32];
    {
        const float* qrow = Q + (size_t)(s0 + r) * DIM + h * HEAD_DIM + j * 32;
#pragma unroll
        for (int d4 = 0; d4 < 8; d4++) {
            float4 t = *(const float4*)(qrow + d4 * 4);
            q[d4 * 4 + 0] = t.x * scale;
            q[d4 * 4 + 1] = t.y * scale;
            q[d4 * 4 + 2] = t.z * scale;
            q[d4 * 4 + 3] = t.w * scale;
        }
    }
    float acc[32];
#pragma unroll
    for (int d = 0; d < 32; d++) acc[d] = 0.f;
    float m = -1e30f, l = 0.f;

    for (int kt = 0; kt < S_LEN; kt += FA_BC) {
        // load K,V tiles: 32x128 floats each -> 4 float4 per thread each
#pragma unroll
        for (int i = 0; i < 4; i++) {
            int idx = tid + i * 256;   // float4 index 0..1023
            int c = idx >> 5;          // row in tile
            int d4 = idx & 31;
            size_t goff = (size_t)(kt + c) * DIM + h * HEAD_DIM + d4 * 4;
            *(float4*)&Ks[c][d4 * 4] = *(const float4*)(K + goff);
            *(float4*)&Vs[c][d4 * 4] = *(const float4*)(V + goff);
        }
        __syncthreads();

        float sc[FA_BC];
#pragma unroll
        for (int c = 0; c < FA_BC; c++) {
            float s = 0.f;
#pragma unroll
            for (int d4 = 0; d4 < 8; d4++) {
                float4 kk = *(const float4*)&Ks[c][j * 32 + d4 * 4];
                s += q[d4 * 4 + 0] * kk.x + q[d4 * 4 + 1] * kk.y +
                     q[d4 * 4 + 2] * kk.z + q[d4 * 4 + 3] * kk.w;
            }
            s += __shfl_xor_sync(0xffffffffu, s, 1);
            s += __shfl_xor_sync(0xffffffffu, s, 2);
            sc[c] = s;
        }

        float mnew = m;
#pragma unroll
        for (int c = 0; c < FA_BC; c++) mnew = fmaxf(mnew, sc[c]);
        float corr = __expf(m - mnew);
        m = mnew;
        l *= corr;
#pragma unroll
        for (int d = 0; d < 32; d++) acc[d] *= corr;

#pragma unroll
        for (int c = 0; c < FA_BC; c++) {
            float p = __expf(sc[c] - mnew);
            l += p;
#pragma unroll
            for (int d4 = 0; d4 < 8; d4++) {
                float4 vv = *(const float4*)&Vs[c][j * 32 + d4 * 4];
                acc[d4 * 4 + 0] += p * vv.x;
                acc[d4 * 4 + 1] += p * vv.y;
                acc[d4 * 4 + 2] += p * vv.z;
                acc[d4 * 4 + 3] += p * vv.w;
            }
        }
        __syncthreads();
    }

    float inv = 1.f / l;
    float* orow = O + (size_t)(s0 + r) * DIM + h * HEAD_DIM + j * 32;
#pragma unroll
    for (int d4 = 0; d4 < 8; d4++) {
        float4 o = make_float4(acc[d4 * 4 + 0] * inv, acc[d4 * 4 + 1] * inv,
                               acc[d4 * 4 + 2] * inv, acc[d4 * 4 + 3] * inv);
        *(float4*)(orow + d4 * 4) = o;
    }
}

// ---------------- final: out = hidden + gate * (c + out_b) ----------------
__global__ void final_residual(const float* __restrict__ hidden, const float* __restrict__ c,
                               const float* __restrict__ emb, const float* __restrict__ ob,
                               float* __restrict__ out) {
    size_t i4 = (size_t)blockIdx.x * blockDim.x + threadIdx.x;
    size_t i = i4 * 4;
    if (i >= (size_t)S_LEN * DIM) return;
    int col = (int)(i % DIM);
    float4 hh = *(const float4*)(hidden + i);
    float4 cc = *(const float4*)(c + i);
    float4 g = *(const float4*)(emb + 2 * DIM + col);
    float4 bb = *(const float4*)(ob + col);
    float4 o;
    o.x = hh.x + g.x * (cc.x + bb.x);
    o.y = hh.y + g.y * (cc.y + bb.y);
    o.z = hh.z + g.z * (cc.z + bb.z);
    o.w = hh.w + g.w * (cc.w + bb.w);
    *(float4*)(out + i) = o;
}

// ---------------- launch ----------------
extern "C" void kernel_launch(void* const* d_in, const int* in_sizes, int n_in,
                              void* d_out, int out_size) {
    const float* hidden   = (const float*)d_in[0];
    const float* temb     = (const float*)d_in[1];
    const float* rope_cos = (const float*)d_in[2];
    const float* rope_sin = (const float*)d_in[3];
    const float* norm_w   = (const float*)d_in[4];
    const float* norm_b   = (const float*)d_in[5];
    const float* mlp_w    = (const float*)d_in[6];
    const float* mlp_b    = (const float*)d_in[7];
    const float* q_w      = (const float*)d_in[8];
    const float* q_b      = (const float*)d_in[9];
    const float* k_w      = (const float*)d_in[10];
    const float* k_b      = (const float*)d_in[11];
    const float* v_w      = (const float*)d_in[12];
    const float* v_b      = (const float*)d_in[13];
    const float* rms_q_w  = (const float*)d_in[14];
    const float* rms_k_w  = (const float*)d_in[15];
    const float* out_w    = (const float*)d_in[16];
    const float* out_b    = (const float*)d_in[17];
    float* out = (float*)d_out;

    float *silu_p, *emb_p, *nh_p, *mlp_p, *q_p, *k_p, *v_p, *attn_p, *c_p;
    cudaGetSymbolAddress((void**)&silu_p, g_silu);
    cudaGetSymbolAddress((void**)&emb_p, g_emb);
    cudaGetSymbolAddress((void**)&nh_p, g_nh);
    cudaGetSymbolAddress((void**)&mlp_p, g_mlp);
    cudaGetSymbolAddress((void**)&q_p, g_q);
    cudaGetSymbolAddress((void**)&k_p, g_k);
    cudaGetSymbolAddress((void**)&v_p, g_v);
    cudaGetSymbolAddress((void**)&attn_p, g_attn);
    cudaGetSymbolAddress((void**)&c_p, g_c);

    // 1. silu(temb)
    silu_kernel<<<(DIM + 255) / 256, 256>>>(temb, silu_p);
    // 2. adaLN embedding GEMV: emb = silu(temb) @ norm_w^T + norm_b
    emb_gemv<<<3 * DIM, 128>>>(silu_p, norm_w, norm_b, emb_p);
    // 3. LayerNorm + modulate
    ln_mod<<<S_LEN, 256>>>(hidden, emb_p, nh_p);
    // 4. MLP GEMM + GELU
    gemm_nt<<<dim3(MLP_H / BN, S_LEN / BM), 256>>>(nh_p, DIM, mlp_w, DIM, mlp_p, MLP_H,
                                                   DIM, mlp_b, 1, 0);
    // 5-7. Q,K,V GEMMs
    gemm_nt<<<dim3(DIM / BN, S_LEN / BM), 256>>>(nh_p, DIM, q_w, DIM, q_p, DIM, DIM, q_b, 0, 0);
    gemm_nt<<<dim3(DIM / BN, S_LEN / BM), 256>>>(nh_p, DIM, k_w, DIM, k_p, DIM, DIM, k_b, 0, 0);
    gemm_nt<<<dim3(DIM / BN, S_LEN / BM), 256>>>(nh_p, DIM, v_w, DIM, v_p, DIM, DIM, v_b, 0, 0);
    // 8. RMSNorm + RoPE on q,k
    rmsrope<<<dim3(S_LEN, HEADS), HEAD_DIM>>>(q_p, k_p, rope_cos, rope_sin, rms_q_w, rms_k_w);
    // 9. flash attention
    flash_attn<<<dim3(S_LEN / FA_BR, HEADS), 256>>>(q_p, k_p, v_p, attn_p);
    // 10. out-proj part 1: C = attn @ out_w[:, :3072]^T
    gemm_nt<<<dim3(DIM / BN, S_LEN / BM), 256>>>(attn_p, DIM, out_w, DIM + MLP_H, c_p, DIM,
                                                 DIM, nullptr, 0, 0);
    // 11. out-proj part 2: C += mlp @ out_w[:, 3072:]^T
    gemm_nt<<<dim3(DIM / BN, S_LEN / BM), 256>>>(mlp_p, MLP_H, out_w + DIM, DIM + MLP_H, c_p,
                                                 DIM, MLP_H, nullptr, 0, 1);
    // 12. residual + gate epilogue
    final_residual<<<(S_LEN * DIM / 4 + 255) / 256, 256>>>(hidden, c_p, emb_p, out_b, out);
}

// round 3
// speedup vs baseline: 1.5106x; 1.5106x over previous
#include <cuda_runtime.h>
#include <cuda_bf16.h>
#include <cstdint>
#include <math.h>

#define S_LEN 2048
#define DIM 3072
#define HEADS 24
#define HEAD_DIM 128
#define MLP_H 12288
#define CAT_K (DIM + MLP_H)   // 15360

// ---------------- scratch (device globals; no runtime allocs allowed) -------
#define ALN __align__(128)
__device__ ALN float g_silu[DIM];
__device__ ALN float g_emb[3 * DIM];
__device__ ALN float g_q[S_LEN * DIM];
__device__ ALN float g_k[S_LEN * DIM];
__device__ ALN float g_v[S_LEN * DIM];
__device__ ALN float g_attn[S_LEN * DIM];
__device__ ALN __nv_bfloat16 g_nh_h[S_LEN * DIM];
__device__ ALN __nv_bfloat16 g_nh_l[S_LEN * DIM];
__device__ ALN __nv_bfloat16 g_wq_h[DIM * DIM];
__device__ ALN __nv_bfloat16 g_wq_l[DIM * DIM];
__device__ ALN __nv_bfloat16 g_wk_h[DIM * DIM];
__device__ ALN __nv_bfloat16 g_wk_l[DIM * DIM];
__device__ ALN __nv_bfloat16 g_wv_h[DIM * DIM];
__device__ ALN __nv_bfloat16 g_wv_l[DIM * DIM];
__device__ ALN __nv_bfloat16 g_wm_h[MLP_H * DIM];
__device__ ALN __nv_bfloat16 g_wm_l[MLP_H * DIM];
__device__ ALN __nv_bfloat16 g_wo_h[DIM * CAT_K];
__device__ ALN __nv_bfloat16 g_wo_l[DIM * CAT_K];
__device__ ALN __nv_bfloat16 g_cat_h[S_LEN * CAT_K];
__device__ ALN __nv_bfloat16 g_cat_l[S_LEN * CAT_K];

// ---------------- PTX helpers ----------------
__device__ __forceinline__ uint32_t smem_u32(const void* p) {
    uint32_t a;
    asm("{ .reg .u64 t; cvta.to.shared.u64 t, %1; cvt.u32.u64 %0, t; }" : "=r"(a) : "l"(p));
    return a;
}
__device__ __forceinline__ void cpa16(uint32_t s, const void* g) {
    asm volatile("cp.async.cg.shared.global [%0], [%1], 16;" :: "r"(s), "l"(g));
}
__device__ __forceinline__ void cpa_commit() { asm volatile("cp.async.commit_group;" ::: "memory"); }
template <int N>
__device__ __forceinline__ void cpa_wait() { asm volatile("cp.async.wait_group %0;" :: "n"(N) : "memory"); }

__device__ __forceinline__ void ldsm_x4(uint32_t* r, uint32_t addr) {
    asm volatile("ldmatrix.sync.aligned.m8n8.x4.shared.b16 {%0,%1,%2,%3}, [%4];"
                 : "=r"(r[0]), "=r"(r[1]), "=r"(r[2]), "=r"(r[3]) : "r"(addr));
}
__device__ __forceinline__ void mma16816(float* d, const uint32_t* a, const uint32_t* b) {
    asm volatile(
        "mma.sync.aligned.m16n8k16.row.col.f32.bf16.bf16.f32 "
        "{%0,%1,%2,%3}, {%4,%5,%6,%7}, {%8,%9}, {%0,%1,%2,%3};"
        : "+f"(d[0]), "+f"(d[1]), "+f"(d[2]), "+f"(d[3])
        : "r"(a[0]), "r"(a[1]), "r"(a[2]), "r"(a[3]), "r"(b[0]), "r"(b[1]));
}

__device__ __forceinline__ float geluf(float x) {
    float inner = 0.7978845608028654f * (x + 0.044715f * x * x * x);
    return 0.5f * x * (1.f + tanhf(inner));
}
__device__ __forceinline__ void split_bf(float v, __nv_bfloat16& h, __nv_bfloat16& l) {
    h = __float2bfloat16(v);
    l = __float2bfloat16(v - __bfloat162float(h));
}

// ---------------- mma.sync split-bf16 GEMM ----------------
// C[m,n] = sum_k A[m,k]*B[n,k]; A,B as bf16 hi/lo pairs (K-major).
// MODE 0: Cf = acc + bias                 (QKV)
// MODE 1: split(gelu(acc+bias)) -> Ch/Cl at col offset ccol0 (MLP->cat)
// MODE 2: Cf = hidden + gate*(acc+bias)   (out-proj + residual)
#define BK 32
#define PITCH 40                       // bf16 per smem row (32 data + 8 pad)
#define MAT_BYTES (128 * PITCH * 2)    // 10240
#define STAGE_BYTES (4 * MAT_BYTES)    // Ah, Al, Bh, Bl = 40960
#define GEMM_SMEM (3 * STAGE_BYTES)    // 122880

// copy 128 rows x 32 bf16 (K-major) into padded smem tile
__device__ __forceinline__ void load_mat(uint32_t dst, const __nv_bfloat16* g, int ld,
                                         int row0, int k0, int tid) {
    const __nv_bfloat16* gp = g + (size_t)row0 * ld + k0;
#pragma unroll
    for (int i = 0; i < 2; i++) {
        int idx = tid + i * 256;          // 0..511
        int row = idx >> 2;
        int c4 = idx & 3;
        cpa16(dst + row * (PITCH * 2) + c4 * 16, gp + (size_t)row * ld + c4 * 8);
    }
}

template <int MODE>
__global__ __launch_bounds__(256, 1)
void gemm_mma(const __nv_bfloat16* __restrict__ Ah, const __nv_bfloat16* __restrict__ Al,
              const __nv_bfloat16* __restrict__ Bh, const __nv_bfloat16* __restrict__ Bl,
              int Mtot, int Ktot, int lda, int ldb,
              const float* __restrict__ bias,
              float* __restrict__ Cf, int ldc,
              __nv_bfloat16* __restrict__ Ch, __nv_bfloat16* __restrict__ Cl,
              int ldch, int ccol0,
              const float* __restrict__ hidden, const float* __restrict__ gate) {
    extern __shared__ char smem[];
    uint32_t sb = smem_u32(smem);
    int tid = threadIdx.x;
    int warp = tid >> 5, lane = tid & 31;
    int wm = warp & 1;        // 0..1 -> 64-row half
    int wn = warp >> 1;       // 0..3 -> 32-col quarter

    int mtiles = Mtot >> 7;
    int bm0 = (blockIdx.x % mtiles) << 7;
    int bn0 = (blockIdx.x / mtiles) << 7;

    float acc[4][4][4];
#pragma unroll
    for (int i = 0; i < 4; i++)
#pragma unroll
        for (int j = 0; j < 4; j++)
#pragma unroll
            for (int c = 0; c < 4; c++) acc[i][j][c] = 0.f;

    const int iters = Ktot / BK;

    // prologue: stages 0 and 1
#pragma unroll
    for (int s = 0; s < 2; s++) {
        uint32_t st = sb + s * STAGE_BYTES;
        load_mat(st, Ah, lda, bm0, s * BK, tid);
        load_mat(st + MAT_BYTES, Al, lda, bm0, s * BK, tid);
        load_mat(st + 2 * MAT_BYTES, Bh, ldb, bn0, s * BK, tid);
        load_mat(st + 3 * MAT_BYTES, Bl, ldb, bn0, s * BK, tid);
        cpa_commit();
    }

    // precomputed intra-tile ldmatrix offsets
    // A: row = wm*64 + mi*16 + (lane&15), byte col = ((lane>>4)*8 + kk*16)*2
    uint32_t a_off = (uint32_t)(wm * 64 + (lane & 15)) * (PITCH * 2) + ((lane >> 4) * 8) * 2;
    // B: row = wn*32 + p*16 + ((lane>>4)&1)*8 + (lane&7), byte col = (((lane>>3)&1)*8 + kk*16)*2
    uint32_t b_off = (uint32_t)(wn * 32 + ((lane >> 4) & 1) * 8 + (lane & 7)) * (PITCH * 2)
                   + (((lane >> 3) & 1) * 8) * 2;

    for (int it = 0; it < iters; ++it) {
        int s = it % 3;
        if (it + 1 < iters) cpa_wait<1>(); else cpa_wait<0>();
        __syncthreads();

        if (it + 2 < iters) {
            int s2 = (it + 2) % 3;
            uint32_t st = sb + s2 * STAGE_BYTES;
            int k0 = (it + 2) * BK;
            load_mat(st, Ah, lda, bm0, k0, tid);
            load_mat(st + MAT_BYTES, Al, lda, bm0, k0, tid);
            load_mat(st + 2 * MAT_BYTES, Bh, ldb, bn0, k0, tid);
            load_mat(st + 3 * MAT_BYTES, Bl, ldb, bn0, k0, tid);
            cpa_commit();
        }

        uint32_t stg = sb + s * STAGE_BYTES;
#pragma unroll
        for (int kk = 0; kk < 2; kk++) {
            uint32_t kb = kk * 32;  // 16 bf16 = 32 bytes
            uint32_t ah[4][4], al[4][4], bh[2][4], bl[2][4];
#pragma unroll
            for (int mi = 0; mi < 4; mi++) {
                uint32_t addr = stg + a_off + (uint32_t)mi * 16 * (PITCH * 2) + kb;
                ldsm_x4(ah[mi], addr);
                ldsm_x4(al[mi], addr + MAT_BYTES);
            }
#pragma unroll
            for (int p = 0; p < 2; p++) {
                uint32_t addr = stg + 2 * MAT_BYTES + b_off + (uint32_t)p * 16 * (PITCH * 2) + kb;
                ldsm_x4(bh[p], addr);
                ldsm_x4(bl[p], addr + MAT_BYTES);
            }
#pragma unroll
            for (int mi = 0; mi < 4; mi++) {
#pragma unroll
                for (int ni = 0; ni < 4; ni++) {
                    const uint32_t* bfh = &bh[ni >> 1][(ni & 1) * 2];
                    const uint32_t* bfl = &bl[ni >> 1][(ni & 1) * 2];
                    mma16816(acc[mi][ni], ah[mi], bfh);   // hi*hi
                    mma16816(acc[mi][ni], al[mi], bfh);   // lo*hi
                    mma16816(acc[mi][ni], ah[mi], bfl);   // hi*lo
                }
            }
        }
    }

    // ---------------- epilogue ----------------
    int rq = lane >> 2;            // 0..7
    int cq = (lane & 3) * 2;       // 0,2,4,6
#pragma unroll
    for (int mi = 0; mi < 4; mi++) {
#pragma unroll
        for (int ni = 0; ni < 4; ni++) {
            int n = bn0 + wn * 32 + ni * 8 + cq;
#pragma unroll
            for (int half = 0; half < 2; half++) {
                size_t m = (size_t)bm0 + wm * 64 + mi * 16 + rq + half * 8;
                float v0 = acc[mi][ni][half * 2 + 0];
                float v1 = acc[mi][ni][half * 2 + 1];
                if (MODE == 0) {
                    float2 o = make_float2(v0 + bias[n], v1 + bias[n + 1]);
                    *(float2*)(Cf + m * ldc + n) = o;
                } else if (MODE == 1) {
                    float g0 = geluf(v0 + bias[n]);
                    float g1 = geluf(v1 + bias[n + 1]);
                    __nv_bfloat162 h, l;
                    split_bf(g0, h.x, l.x);
                    split_bf(g1, h.y, l.y);
                    *(__nv_bfloat162*)(Ch + m * ldch + ccol0 + n) = h;
                    *(__nv_bfloat162*)(Cl + m * ldch + ccol0 + n) = l;
                } else {
                    const float* hp = hidden + m * ldc + n;
                    float2 hv = *(const float2*)hp;
                    float2 o;
                    o.x = hv.x + gate[n] * (v0 + bias[n]);
                    o.y = hv.y + gate[n + 1] * (v1 + bias[n + 1]);
                    *(float2*)(Cf + m * ldc + n) = o;
                }
            }
        }
    }
}

// ---------------- elementwise / small kernels ----------------
__global__ void silu_kernel(const float* __restrict__ temb, float* __restrict__ out) {
    int i = blockIdx.x * blockDim.x + threadIdx.x;
    if (i < DIM) {
        float v = temb[i];
        out[i] = v / (1.f + __expf(-v));
    }
}

__global__ __launch_bounds__(128) void emb_gemv(const float* __restrict__ sil,
                                                const float* __restrict__ w,
                                                const float* __restrict__ b,
                                                float* __restrict__ emb) {
    int jrow = blockIdx.x;
    const float* wr = w + (size_t)jrow * DIM;
    int tid = threadIdx.x;
    float s = 0.f;
    for (int i = tid * 4; i < DIM; i += 512) {
        float4 a = *(const float4*)(sil + i);
        float4 ww = *(const float4*)(wr + i);
        s += a.x * ww.x + a.y * ww.y + a.z * ww.z + a.w * ww.w;
    }
    for (int o = 16; o > 0; o >>= 1) s += __shfl_xor_sync(0xffffffffu, s, o);
    __shared__ float sm[4];
    if ((tid & 31) == 0) sm[tid >> 5] = s;
    __syncthreads();
    if (tid == 0) emb[jrow] = sm[0] + sm[1] + sm[2] + sm[3] + b[jrow];
}

// LayerNorm + adaLN modulate, emits bf16 hi/lo directly
__global__ __launch_bounds__(256) void ln_mod(const float* __restrict__ x,
                                              const float* __restrict__ emb,
                                              __nv_bfloat16* __restrict__ nh_h,
                                              __nv_bfloat16* __restrict__ nh_l) {
    int srow = blockIdx.x;
    int tid = threadIdx.x;
    const float* row = x + (size_t)srow * DIM;
    float sum = 0.f, sq = 0.f;
    for (int i = tid * 4; i < DIM; i += 1024) {
        float4 v = *(const float4*)(row + i);
        sum += v.x + v.y + v.z + v.w;
        sq += v.x * v.x + v.y * v.y + v.z * v.z + v.w * v.w;
    }
    for (int o = 16; o > 0; o >>= 1) {
        sum += __shfl_xor_sync(0xffffffffu, sum, o);
        sq += __shfl_xor_sync(0xffffffffu, sq, o);
    }
    __shared__ float s1[8], s2[8];
    if ((tid & 31) == 0) { s1[tid >> 5] = sum; s2[tid >> 5] = sq; }
    __syncthreads();
    sum = 0.f; sq = 0.f;
#pragma unroll
    for (int w = 0; w < 8; w++) { sum += s1[w]; sq += s2[w]; }
    float mean = sum * (1.f / DIM);
    float var = sq * (1.f / DIM) - mean * mean;
    float rstd = rsqrtf(var + 1e-6f);
    __nv_bfloat16* oh = nh_h + (size_t)srow * DIM;
    __nv_bfloat16* ol = nh_l + (size_t)srow * DIM;
    for (int i = tid * 4; i < DIM; i += 1024) {
        float4 v = *(const float4*)(row + i);
        float4 sc = *(const float4*)(emb + DIM + i);
        float4 sh = *(const float4*)(emb + i);
        float o0 = (v.x - mean) * rstd * (1.f + sc.x) + sh.x;
        float o1 = (v.y - mean) * rstd * (1.f + sc.y) + sh.y;
        float o2 = (v.z - mean) * rstd * (1.f + sc.z) + sh.z;
        float o3 = (v.w - mean) * rstd * (1.f + sc.w) + sh.w;
        __nv_bfloat162 h0, l0, h1, l1;
        split_bf(o0, h0.x, l0.x); split_bf(o1, h0.y, l0.y);
        split_bf(o2, h1.x, l1.x); split_bf(o3, h1.y, l1.y);
        *(__nv_bfloat162*)(oh + i) = h0;
        *(__nv_bfloat162*)(oh + i + 2) = h1;
        *(__nv_bfloat162*)(ol + i) = l0;
        *(__nv_bfloat162*)(ol + i + 2) = l1;
    }
}

// fp32 -> bf16 hi/lo split (vectorized)
__global__ void cvt_split(const float* __restrict__ x, __nv_bfloat16* __restrict__ hi,
                          __nv_bfloat16* __restrict__ lo, long n) {
    long i = ((long)blockIdx.x * blockDim.x + threadIdx.x) * 4;
    if (i >= n) return;
    float4 v = *(const float4*)(x + i);
    __nv_bfloat162 h0, l0, h1, l1;
    split_bf(v.x, h0.x, l0.x); split_bf(v.y, h0.y, l0.y);
    split_bf(v.z, h1.x, l1.x); split_bf(v.w, h1.y, l1.y);
    *(__nv_bfloat162*)(hi + i) = h0;
    *(__nv_bfloat162*)(hi + i + 2) = h1;
    *(__nv_bfloat162*)(lo + i) = l0;
    *(__nv_bfloat162*)(lo + i + 2) = l1;
}

// attn fp32 -> hi/lo into cat buffer cols [0, DIM)
__global__ void cvt_attn_cat(const float* __restrict__ a, __nv_bfloat16* __restrict__ ch,
                             __nv_bfloat16* __restrict__ cl) {
    int i4 = blockIdx.x * blockDim.x + threadIdx.x;
    if (i4 >= S_LEN * DIM / 4) return;
    int row = i4 / (DIM / 4);
    int c4 = i4 - row * (DIM / 4);
    float4 v = *(const float4*)(a + (size_t)row * DIM + c4 * 4);
    size_t d = (size_t)row * CAT_K + c4 * 4;
    __nv_bfloat162 h0, l0, h1, l1;
    split_bf(v.x, h0.x, l0.x); split_bf(v.y, h0.y, l0.y);
    split_bf(v.z, h1.x, l1.x); split_bf(v.w, h1.y, l1.y);
    *(__nv_bfloat162*)(ch + d) = h0;
    *(__nv_bfloat162*)(ch + d + 2) = h1;
    *(__nv_bfloat162*)(cl + d) = l0;
    *(__nv_bfloat162*)(cl + d + 2) = l1;
}

// ---------------- RMSNorm + RoPE ----------------
__global__ __launch_bounds__(128) void rmsrope(float* __restrict__ Q, float* __restrict__ Kp,
                                               const float* __restrict__ rc,
                                               const float* __restrict__ rs,
                                               const float* __restrict__ wq,
                                               const float* __restrict__ wk) {
    int s = blockIdx.x, h = blockIdx.y;
    int d = threadIdx.x;
    int lane = d & 31, wid = d >> 5;
    __shared__ float red[4];
    float cosd = rc[s * HEAD_DIM + d];
    float sind = rs[s * HEAD_DIM + d];
    size_t off = (size_t)s * DIM + h * HEAD_DIM + d;
    {
        float v = Q[off];
        float ss = v * v;
        for (int o = 16; o > 0; o >>= 1) ss += __shfl_xor_sync(0xffffffffu, ss, o);
        if (lane == 0) red[wid] = ss;
        __syncthreads();
        float tot = red[0] + red[1] + red[2] + red[3];
        float xn = v * rsqrtf(tot * (1.f / HEAD_DIM) + 1e-6f) * wq[d];
        float part = __shfl_xor_sync(0xffffffffu, xn, 1);
        float rot = (d & 1) ? part : -part;
        Q[off] = xn * cosd + rot * sind;
        __syncthreads();
    }
    {
        float v = Kp[off];
        float ss = v * v;
        for (int o = 16; o > 0; o >>= 1) ss += __shfl_xor_sync(0xffffffffu, ss, o);
        if (lane == 0) red[wid] = ss;
        __syncthreads();
        float tot = red[0] + red[1] + red[2] + red[3];
        float xn = v * rsqrtf(tot * (1.f / HEAD_DIM) + 1e-6f) * wk[d];
        float part = __shfl_xor_sync(0xffffffffu, xn, 1);
        float rot = (d & 1) ? part : -part;
        Kp[off] = xn * cosd + rot * sind;
    }
}

// ---------------- fp32 flash attention ----------------
#define FA_BR 64
#define FA_BC 32

__global__ __launch_bounds__(256) void flash_attn(const float* __restrict__ Q,
                                                  const float* __restrict__ K,
                                                  const float* __restrict__ V,
                                                  float* __restrict__ O) {
    int h = blockIdx.y;
    int s0 = blockIdx.x * FA_BR;
    int tid = threadIdx.x;
    int r = tid >> 2;
    int j = tid & 3;

    __shared__ float Ks[FA_BC][HEAD_DIM];
    __shared__ float Vs[FA_BC][HEAD_DIM];

    const float scale = 0.08838834764831845f;
    float q[32];
    {
        const float* qrow = Q + (size_t)(s0 + r) * DIM + h * HEAD_DIM + j * 32;
#pragma unroll
        for (int d4 = 0; d4 < 8; d4++) {
            float4 t = *(const float4*)(qrow + d4 * 4);
            q[d4 * 4 + 0] = t.x * scale;
            q[d4 * 4 + 1] = t.y * scale;
            q[d4 * 4 + 2] = t.z * scale;
            q[d4 * 4 + 3] = t.w * scale;
        }
    }
    float acc[32];
#pragma unroll
    for (int d = 0; d < 32; d++) acc[d] = 0.f;
    float m = -1e30f, l = 0.f;

    for (int kt = 0; kt < S_LEN; kt += FA_BC) {
#pragma unroll
        for (int i = 0; i < 4; i++) {
            int idx = tid + i * 256;
            int c = idx >> 5;
            int d4 = idx & 31;
            size_t goff = (size_t)(kt + c) * DIM + h * HEAD_DIM + d4 * 4;
            *(float4*)&Ks[c][d4 * 4] = *(const float4*)(K + goff);
            *(float4*)&Vs[c][d4 * 4] = *(const float4*)(V + goff);
        }
        __syncthreads();

        float sc[FA_BC];
#pragma unroll
        for (int c = 0; c < FA_BC; c++) {
            float s = 0.f;
#pragma unroll
            for (int d4 = 0; d4 < 8; d4++) {
                float4 kk = *(const float4*)&Ks[c][j * 32 + d4 * 4];
                s += q[d4 * 4 + 0] * kk.x + q[d4 * 4 + 1] * kk.y +
                     q[d4 * 4 + 2] * kk.z + q[d4 * 4 + 3] * kk.w;
            }
            s += __shfl_xor_sync(0xffffffffu, s, 1);
            s += __shfl_xor_sync(0xffffffffu, s, 2);
            sc[c] = s;
        }

        float mnew = m;
#pragma unroll
        for (int c = 0; c < FA_BC; c++) mnew = fmaxf(mnew, sc[c]);
        float corr = __expf(m - mnew);
        m = mnew;
        l *= corr;
#pragma unroll
        for (int d = 0; d < 32; d++) acc[d] *= corr;

#pragma unroll
        for (int c = 0; c < FA_BC; c++) {
            float p = __expf(sc[c] - mnew);
            l += p;
#pragma unroll
            for (int d4 = 0; d4 < 8; d4++) {
                float4 vv = *(const float4*)&Vs[c][j * 32 + d4 * 4];
                acc[d4 * 4 + 0] += p * vv.x;
                acc[d4 * 4 + 1] += p * vv.y;
                acc[d4 * 4 + 2] += p * vv.z;
                acc[d4 * 4 + 3] += p * vv.w;
            }
        }
        __syncthreads();
    }

    float inv = 1.f / l;
    float* orow = O + (size_t)(s0 + r) * DIM + h * HEAD_DIM + j * 32;
#pragma unroll
    for (int d4 = 0; d4 < 8; d4++) {
        float4 o = make_float4(acc[d4 * 4 + 0] * inv, acc[d4 * 4 + 1] * inv,
                               acc[d4 * 4 + 2] * inv, acc[d4 * 4 + 3] * inv);
        *(float4*)(orow + d4 * 4) = o;
    }
}

// ---------------- launch ----------------
extern "C" void kernel_launch(void* const* d_in, const int* in_sizes, int n_in,
                              void* d_out, int out_size) {
    const float* hidden = (const float*)d_in[0];
    const float* temb = (const float*)d_in[1];
    const float* rope_cos = (const float*)d_in[2];
    const float* rope_sin = (const float*)d_in[3];
    const float* norm_w = (const float*)d_in[4];
    const float* norm_b = (const float*)d_in[5];
    const float* mlp_w = (const float*)d_in[6];
    const float* mlp_b = (const float*)d_in[7];
    const float* q_w = (const float*)d_in[8];
    const float* q_b = (const float*)d_in[9];
    const float* k_w = (const float*)d_in[10];
    const float* k_b = (const float*)d_in[11];
    const float* v_w = (const float*)d_in[12];
    const float* v_b = (const float*)d_in[13];
    const float* rms_q_w = (const float*)d_in[14];
    const float* rms_k_w = (const float*)d_in[15];
    const float* out_w = (const float*)d_in[16];
    const float* out_b = (const float*)d_in[17];
    float* out = (float*)d_out;

    float *silu_p, *emb_p, *q_p, *k_p, *v_p, *attn_p;
    __nv_bfloat16 *nh_h, *nh_l, *wq_h, *wq_l, *wk_h, *wk_l, *wv_h, *wv_l;
    __nv_bfloat16 *wm_h, *wm_l, *wo_h, *wo_l, *cat_h, *cat_l;
    cudaGetSymbolAddress((void**)&silu_p, g_silu);
    cudaGetSymbolAddress((void**)&emb_p, g_emb);
    cudaGetSymbolAddress((void**)&q_p, g_q);
    cudaGetSymbolAddress((void**)&k_p, g_k);
    cudaGetSymbolAddress((void**)&v_p, g_v);
    cudaGetSymbolAddress((void**)&attn_p, g_attn);
    cudaGetSymbolAddress((void**)&nh_h, g_nh_h);
    cudaGetSymbolAddress((void**)&nh_l, g_nh_l);
    cudaGetSymbolAddress((void**)&wq_h, g_wq_h);
    cudaGetSymbolAddress((void**)&wq_l, g_wq_l);
    cudaGetSymbolAddress((void**)&wk_h, g_wk_h);
    cudaGetSymbolAddress((void**)&wk_l, g_wk_l);
    cudaGetSymbolAddress((void**)&wv_h, g_wv_h);
    cudaGetSymbolAddress((void**)&wv_l, g_wv_l);
    cudaGetSymbolAddress((void**)&wm_h, g_wm_h);
    cudaGetSymbolAddress((void**)&wm_l, g_wm_l);
    cudaGetSymbolAddress((void**)&wo_h, g_wo_h);
    cudaGetSymbolAddress((void**)&wo_l, g_wo_l);
    cudaGetSymbolAddress((void**)&cat_h, g_cat_h);
    cudaGetSymbolAddress((void**)&cat_l, g_cat_l);

    cudaFuncSetAttribute(gemm_mma<0>, cudaFuncAttributeMaxDynamicSharedMemorySize, GEMM_SMEM);
    cudaFuncSetAttribute(gemm_mma<1>, cudaFuncAttributeMaxDynamicSharedMemorySize, GEMM_SMEM);
    cudaFuncSetAttribute(gemm_mma<2>, cudaFuncAttributeMaxDynamicSharedMemorySize, GEMM_SMEM);

    // 1. silu + adaLN embedding
    silu_kernel<<<(DIM + 255) / 256, 256>>>(temb, silu_p);
    emb_gemv<<<3 * DIM, 128>>>(silu_p, norm_w, norm_b, emb_p);
    // 2. LayerNorm + modulate -> nh hi/lo
    ln_mod<<<S_LEN, 256>>>(hidden, emb_p, nh_h, nh_l);
    // 3. weight conversions (hi/lo splits)
    {
        long n;
        n = (long)DIM * DIM;
        cvt_split<<<(unsigned)((n / 4 + 255) / 256), 256>>>(q_w, wq_h, wq_l, n);
        cvt_split<<<(unsigned)((n / 4 + 255) / 256), 256>>>(k_w, wk_h, wk_l, n);
        cvt_split<<<(unsigned)((n / 4 + 255) / 256), 256>>>(v_w, wv_h, wv_l, n);
        n = (long)MLP_H * DIM;
        cvt_split<<<(unsigned)((n / 4 + 255) / 256), 256>>>(mlp_w, wm_h, wm_l, n);
        n = (long)DIM * CAT_K;
        cvt_split<<<(unsigned)((n / 4 + 255) / 256), 256>>>(out_w, wo_h, wo_l, n);
    }
    // 4. MLP GEMM (+bias+gelu) -> cat[:, DIM:]
    gemm_mma<1><<<(S_LEN / 128) * (MLP_H / 128), 256, GEMM_SMEM>>>(
        nh_h, nh_l, wm_h, wm_l, S_LEN, DIM, DIM, DIM,
        mlp_b, nullptr, 0, cat_h, cat_l, CAT_K, DIM, nullptr, nullptr);
    // 5. Q,K,V GEMMs
    gemm_mma<0><<<(S_LEN / 128) * (DIM / 128), 256, GEMM_SMEM>>>(
        nh_h, nh_l, wq_h, wq_l, S_LEN, DIM, DIM, DIM,
        q_b, q_p, DIM, nullptr, nullptr, 0, 0, nullptr, nullptr);
    gemm_mma<0><<<(S_LEN / 128) * (DIM / 128), 256, GEMM_SMEM>>>(
        nh_h, nh_l, wk_h, wk_l, S_LEN, DIM, DIM, DIM,
        k_b, k_p, DIM, nullptr, nullptr, 0, 0, nullptr, nullptr);
    gemm_mma<0><<<(S_LEN / 128) * (DIM / 128), 256, GEMM_SMEM>>>(
        nh_h, nh_l, wv_h, wv_l, S_LEN, DIM, DIM, DIM,
        v_b, v_p, DIM, nullptr, nullptr, 0, 0, nullptr, nullptr);
    // 6. RMSNorm + RoPE
    rmsrope<<<dim3(S_LEN, HEADS), HEAD_DIM>>>(q_p, k_p, rope_cos, rope_sin, rms_q_w, rms_k_w);
    // 7. flash attention
    flash_attn<<<dim3(S_LEN / FA_BR, HEADS), 256>>>(q_p, k_p, v_p, attn_p);
    // 8. attn -> cat[:, :DIM] hi/lo
    cvt_attn_cat<<<(S_LEN * DIM / 4 + 255) / 256, 256>>>(attn_p, cat_h, cat_l);
    // 9. out-proj GEMM over K=15360 + gated residual -> d_out
    gemm_mma<2><<<(S_LEN / 128) * (DIM / 128), 256, GEMM_SMEM>>>(
        cat_h, cat_l, wo_h, wo_l, S_LEN, CAT_K, CAT_K, CAT_K,
        out_b, out, DIM, nullptr, nullptr, 0, 0, hidden, emb_p + 2 * DIM);
}

// round 4
// speedup vs baseline: 1.5787x; 1.0451x over previous
#include <cuda_runtime.h>
#include <cuda_bf16.h>
#include <cstdint>
#include <math.h>

#define S_LEN 2048
#define DIM 3072
#define HEADS 24
#define HEAD_DIM 128
#define MLP_H 12288
#define CAT_K (DIM + MLP_H)   // 15360
#define QKV_N (3 * DIM)       // 9216

// ---------------- scratch (device globals; no runtime allocs allowed) -------
#define ALN __align__(128)
__device__ ALN float g_emb[3 * DIM];
__device__ ALN float g_qkv[S_LEN * QKV_N];
__device__ ALN float g_attn[S_LEN * DIM];
__device__ ALN float g_bqkv[QKV_N];
__device__ ALN __nv_bfloat16 g_nh_h[S_LEN * DIM];
__device__ ALN __nv_bfloat16 g_nh_l[S_LEN * DIM];
__device__ ALN __nv_bfloat16 g_wqkv_h[QKV_N * DIM];
__device__ ALN __nv_bfloat16 g_wqkv_l[QKV_N * DIM];
__device__ ALN __nv_bfloat16 g_wm_h[MLP_H * DIM];
__device__ ALN __nv_bfloat16 g_wm_l[MLP_H * DIM];
__device__ ALN __nv_bfloat16 g_wo_h[DIM * CAT_K];
__device__ ALN __nv_bfloat16 g_wo_l[DIM * CAT_K];
__device__ ALN __nv_bfloat16 g_cat_h[S_LEN * CAT_K];
__device__ ALN __nv_bfloat16 g_cat_l[S_LEN * CAT_K];

// ---------------- PTX helpers ----------------
__device__ __forceinline__ uint32_t smem_u32(const void* p) {
    uint32_t a;
    asm("{ .reg .u64 t; cvta.to.shared.u64 t, %1; cvt.u32.u64 %0, t; }" : "=r"(a) : "l"(p));
    return a;
}
__device__ __forceinline__ void cpa16(uint32_t s, const void* g) {
    asm volatile("cp.async.cg.shared.global [%0], [%1], 16;" :: "r"(s), "l"(g));
}
__device__ __forceinline__ void cpa_commit() { asm volatile("cp.async.commit_group;" ::: "memory"); }
template <int N>
__device__ __forceinline__ void cpa_wait() { asm volatile("cp.async.wait_group %0;" :: "n"(N) : "memory"); }

__device__ __forceinline__ void ldsm_x4(uint32_t* r, uint32_t addr) {
    asm volatile("ldmatrix.sync.aligned.m8n8.x4.shared.b16 {%0,%1,%2,%3}, [%4];"
                 : "=r"(r[0]), "=r"(r[1]), "=r"(r[2]), "=r"(r[3]) : "r"(addr));
}
__device__ __forceinline__ void mma16816(float* d, const uint32_t* a, const uint32_t* b) {
    asm volatile(
        "mma.sync.aligned.m16n8k16.row.col.f32.bf16.bf16.f32 "
        "{%0,%1,%2,%3}, {%4,%5,%6,%7}, {%8,%9}, {%0,%1,%2,%3};"
        : "+f"(d[0]), "+f"(d[1]), "+f"(d[2]), "+f"(d[3])
        : "r"(a[0]), "r"(a[1]), "r"(a[2]), "r"(a[3]), "r"(b[0]), "r"(b[1]));
}

__device__ __forceinline__ float geluf(float x) {
    float inner = 0.7978845608028654f * (x + 0.044715f * x * x * x);
    return 0.5f * x * (1.f + tanhf(inner));
}
__device__ __forceinline__ void split_bf(float v, __nv_bfloat16& h, __nv_bfloat16& l) {
    h = __float2bfloat16(v);
    l = __float2bfloat16(v - __bfloat162float(h));
}

// ---------------- mma.sync split-bf16 GEMM (512 thr, BK=64, 3-stage) --------
// C[m,n] = sum_k A[m,k]*B[n,k]; A,B as bf16 hi/lo pairs (K-major).
// MODE 0: Cf = acc + bias                 (QKV, ldc=QKV_N)
// MODE 1: split(gelu(acc+bias)) -> Ch/Cl at col offset ccol0 (MLP->cat)
// MODE 2: Cf = hidden + gate*(acc+bias)   (out-proj + residual)
#define BK 64
#define PITCHB 144                        // bytes per smem row (128 data + 16 pad)
#define MAT_BYTES (128 * PITCHB)          // 18432
#define STAGE_BYTES (4 * MAT_BYTES)       // 73728
#define GEMM_SMEM (3 * STAGE_BYTES)       // 221184

// copy 128 rows x 64 bf16 (K-major) into padded smem tile; 512 threads
__device__ __forceinline__ void load_mat(uint32_t dst, const __nv_bfloat16* g, int ld,
                                         int row0, int k0, int tid) {
    const __nv_bfloat16* gp = g + (size_t)row0 * ld + k0;
#pragma unroll
    for (int i = 0; i < 2; i++) {
        int idx = tid + i * 512;          // 0..1023
        int row = idx >> 3;               // 0..127
        int c = idx & 7;                  // 0..7 (16B chunks)
        cpa16(dst + row * PITCHB + c * 16, gp + (size_t)row * ld + c * 8);
    }
}

template <int MODE>
__global__ __launch_bounds__(512, 1)
void gemm_mma(const __nv_bfloat16* __restrict__ Ah, const __nv_bfloat16* __restrict__ Al,
              const __nv_bfloat16* __restrict__ Bh, const __nv_bfloat16* __restrict__ Bl,
              int Mtot, int Ktot, int lda, int ldb,
              const float* __restrict__ bias,
              float* __restrict__ Cf, int ldc,
              __nv_bfloat16* __restrict__ Ch, __nv_bfloat16* __restrict__ Cl,
              int ldch, int ccol0,
              const float* __restrict__ hidden, const float* __restrict__ gate) {
    extern __shared__ char smem[];
    uint32_t sb = smem_u32(smem);
    int tid = threadIdx.x;
    int warp = tid >> 5, lane = tid & 31;
    int wm = warp & 3;        // 0..3 -> 32-row group
    int wn = warp >> 2;       // 0..3 -> 32-col group

    int mtiles = Mtot >> 7;
    int bm0 = (blockIdx.x % mtiles) << 7;
    int bn0 = (blockIdx.x / mtiles) << 7;

    float acc[2][4][4];
#pragma unroll
    for (int i = 0; i < 2; i++)
#pragma unroll
        for (int j = 0; j < 4; j++)
#pragma unroll
            for (int c = 0; c < 4; c++) acc[i][j][c] = 0.f;

    const int iters = Ktot / BK;

    // prologue: stages 0 and 1
#pragma unroll
    for (int s = 0; s < 2; s++) {
        uint32_t st = sb + s * STAGE_BYTES;
        load_mat(st, Ah, lda, bm0, s * BK, tid);
        load_mat(st + MAT_BYTES, Al, lda, bm0, s * BK, tid);
        load_mat(st + 2 * MAT_BYTES, Bh, ldb, bn0, s * BK, tid);
        load_mat(st + 3 * MAT_BYTES, Bl, ldb, bn0, s * BK, tid);
        cpa_commit();
    }

    // ldmatrix intra-tile offsets
    uint32_t a_off = (uint32_t)(wm * 32 + (lane & 15)) * PITCHB + ((lane >> 4) * 8) * 2;
    uint32_t b_off = (uint32_t)(wn * 32 + ((lane >> 4) & 1) * 8 + (lane & 7)) * PITCHB
                   + (((lane >> 3) & 1) * 8) * 2;

    for (int it = 0; it < iters; ++it) {
        int s = it % 3;
        if (it + 1 < iters) cpa_wait<1>(); else cpa_wait<0>();
        __syncthreads();

        if (it + 2 < iters) {
            int s2 = (it + 2) % 3;
            uint32_t st = sb + s2 * STAGE_BYTES;
            int k0 = (it + 2) * BK;
            load_mat(st, Ah, lda, bm0, k0, tid);
            load_mat(st + MAT_BYTES, Al, lda, bm0, k0, tid);
            load_mat(st + 2 * MAT_BYTES, Bh, ldb, bn0, k0, tid);
            load_mat(st + 3 * MAT_BYTES, Bl, ldb, bn0, k0, tid);
            cpa_commit();
        }

        uint32_t stg = sb + s * STAGE_BYTES;
#pragma unroll
        for (int kk = 0; kk < 4; kk++) {
            uint32_t kb = kk * 32;   // 16 bf16 = 32 bytes per k-step
            uint32_t ah[2][4], al[2][4], bh[2][4], bl[2][4];
#pragma unroll
            for (int mi = 0; mi < 2; mi++) {
                uint32_t addr = stg + a_off + (uint32_t)mi * 16 * PITCHB + kb;
                ldsm_x4(ah[mi], addr);
                ldsm_x4(al[mi], addr + MAT_BYTES);
            }
#pragma unroll
            for (int p = 0; p < 2; p++) {
                uint32_t addr = stg + 2 * MAT_BYTES + b_off + (uint32_t)p * 16 * PITCHB + kb;
                ldsm_x4(bh[p], addr);
                ldsm_x4(bl[p], addr + MAT_BYTES);
            }
#pragma unroll
            for (int mi = 0; mi < 2; mi++) {
#pragma unroll
                for (int ni = 0; ni < 4; ni++) {
                    const uint32_t* bfh = &bh[ni >> 1][(ni & 1) * 2];
                    const uint32_t* bfl = &bl[ni >> 1][(ni & 1) * 2];
                    mma16816(acc[mi][ni], ah[mi], bfh);   // hi*hi
                    mma16816(acc[mi][ni], al[mi], bfh);   // lo*hi
                    mma16816(acc[mi][ni], ah[mi], bfl);   // hi*lo
                }
            }
        }
    }

    // ---------------- epilogue ----------------
    int rq = lane >> 2;            // 0..7
    int cq = (lane & 3) * 2;       // 0,2,4,6
#pragma unroll
    for (int mi = 0; mi < 2; mi++) {
#pragma unroll
        for (int ni = 0; ni < 4; ni++) {
            int n = bn0 + wn * 32 + ni * 8 + cq;
#pragma unroll
            for (int half = 0; half < 2; half++) {
                size_t m = (size_t)bm0 + wm * 32 + mi * 16 + rq + half * 8;
                float v0 = acc[mi][ni][half * 2 + 0];
                float v1 = acc[mi][ni][half * 2 + 1];
                if (MODE == 0) {
                    float2 o = make_float2(v0 + bias[n], v1 + bias[n + 1]);
                    *(float2*)(Cf + m * ldc + n) = o;
                } else if (MODE == 1) {
                    float g0 = geluf(v0 + bias[n]);
                    float g1 = geluf(v1 + bias[n + 1]);
                    __nv_bfloat162 h, l;
                    split_bf(g0, h.x, l.x);
                    split_bf(g1, h.y, l.y);
                    *(__nv_bfloat162*)(Ch + m * ldch + ccol0 + n) = h;
                    *(__nv_bfloat162*)(Cl + m * ldch + ccol0 + n) = l;
                } else {
                    const float* hp = hidden + m * ldc + n;
                    float2 hv = *(const float2*)hp;
                    float2 o;
                    o.x = hv.x + gate[n] * (v0 + bias[n]);
                    o.y = hv.y + gate[n + 1] * (v1 + bias[n + 1]);
                    *(float2*)(Cf + m * ldc + n) = o;
                }
            }
        }
    }
}

// ---------------- fused weight conversion (all weights, one kernel) --------
#define QW_N ((long)DIM * DIM)                 // 9437184
#define CVT_TOTAL (3 * QW_N + (long)MLP_H * DIM + (long)DIM * CAT_K)

__global__ void cvt_all(const float* __restrict__ q_w, const float* __restrict__ k_w,
                        const float* __restrict__ v_w, const float* __restrict__ mlp_w,
                        const float* __restrict__ out_w,
                        __nv_bfloat16* __restrict__ wqkv_h, __nv_bfloat16* __restrict__ wqkv_l,
                        __nv_bfloat16* __restrict__ wm_h, __nv_bfloat16* __restrict__ wm_l,
                        __nv_bfloat16* __restrict__ wo_h, __nv_bfloat16* __restrict__ wo_l) {
    long i = ((long)blockIdx.x * blockDim.x + threadIdx.x) * 4;
    if (i >= CVT_TOTAL) return;
    const float* src;
    __nv_bfloat16 *dh, *dl;
    long off;
    if (i < QW_N) { src = q_w; off = i; dh = wqkv_h; dl = wqkv_l; }
    else if (i < 2 * QW_N) { src = k_w; off = i - QW_N; dh = wqkv_h + QW_N; dl = wqkv_l + QW_N; }
    else if (i < 3 * QW_N) { src = v_w; off = i - 2 * QW_N; dh = wqkv_h + 2 * QW_N; dl = wqkv_l + 2 * QW_N; }
    else if (i < 3 * QW_N + (long)MLP_H * DIM) { src = mlp_w; off = i - 3 * QW_N; dh = wm_h; dl = wm_l; }
    else { src = out_w; off = i - 3 * QW_N - (long)MLP_H * DIM; dh = wo_h; dl = wo_l; }
    float4 v = *(const float4*)(src + off);
    __nv_bfloat162 h0, l0, h1, l1;
    split_bf(v.x, h0.x, l0.x); split_bf(v.y, h0.y, l0.y);
    split_bf(v.z, h1.x, l1.x); split_bf(v.w, h1.y, l1.y);
    *(__nv_bfloat162*)(dh + off) = h0;
    *(__nv_bfloat162*)(dh + off + 2) = h1;
    *(__nv_bfloat162*)(dl + off) = l0;
    *(__nv_bfloat162*)(dl + off + 2) = l1;
}

__global__ void cat_bias(const float* __restrict__ qb, const float* __restrict__ kb,
                         const float* __restrict__ vb, float* __restrict__ o) {
    int i = blockIdx.x * blockDim.x + threadIdx.x;
    if (i < DIM) { o[i] = qb[i]; o[DIM + i] = kb[i]; o[2 * DIM + i] = vb[i]; }
}

// ---------------- adaLN embedding GEMV with fused silu ----------------
__global__ __launch_bounds__(128) void emb_gemv(const float* __restrict__ temb,
                                                const float* __restrict__ w,
                                                const float* __restrict__ b,
                                                float* __restrict__ emb) {
    int jrow = blockIdx.x;
    const float* wr = w + (size_t)jrow * DIM;
    int tid = threadIdx.x;
    float s = 0.f;
    for (int i = tid * 4; i < DIM; i += 512) {
        float4 a = *(const float4*)(temb + i);
        float4 ww = *(const float4*)(wr + i);
        a.x = a.x / (1.f + __expf(-a.x));
        a.y = a.y / (1.f + __expf(-a.y));
        a.z = a.z / (1.f + __expf(-a.z));
        a.w = a.w / (1.f + __expf(-a.w));
        s += a.x * ww.x + a.y * ww.y + a.z * ww.z + a.w * ww.w;
    }
    for (int o = 16; o > 0; o >>= 1) s += __shfl_xor_sync(0xffffffffu, s, o);
    __shared__ float sm[4];
    if ((tid & 31) == 0) sm[tid >> 5] = s;
    __syncthreads();
    if (tid == 0) emb[jrow] = sm[0] + sm[1] + sm[2] + sm[3] + b[jrow];
}

// LayerNorm + adaLN modulate, emits bf16 hi/lo directly
__global__ __launch_bounds__(256) void ln_mod(const float* __restrict__ x,
                                              const float* __restrict__ emb,
                                              __nv_bfloat16* __restrict__ nh_h,
                                              __nv_bfloat16* __restrict__ nh_l) {
    int srow = blockIdx.x;
    int tid = threadIdx.x;
    const float* row = x + (size_t)srow * DIM;
    float sum = 0.f, sq = 0.f;
    for (int i = tid * 4; i < DIM; i += 1024) {
        float4 v = *(const float4*)(row + i);
        sum += v.x + v.y + v.z + v.w;
        sq += v.x * v.x + v.y * v.y + v.z * v.z + v.w * v.w;
    }
    for (int o = 16; o > 0; o >>= 1) {
        sum += __shfl_xor_sync(0xffffffffu, sum, o);
        sq += __shfl_xor_sync(0xffffffffu, sq, o);
    }
    __shared__ float s1[8], s2[8];
    if ((tid & 31) == 0) { s1[tid >> 5] = sum; s2[tid >> 5] = sq; }
    __syncthreads();
    sum = 0.f; sq = 0.f;
#pragma unroll
    for (int w = 0; w < 8; w++) { sum += s1[w]; sq += s2[w]; }
    float mean = sum * (1.f / DIM);
    float var = sq * (1.f / DIM) - mean * mean;
    float rstd = rsqrtf(var + 1e-6f);
    __nv_bfloat16* oh = nh_h + (size_t)srow * DIM;
    __nv_bfloat16* ol = nh_l + (size_t)srow * DIM;
    for (int i = tid * 4; i < DIM; i += 1024) {
        float4 v = *(const float4*)(row + i);
        float4 sc = *(const float4*)(emb + DIM + i);
        float4 sh = *(const float4*)(emb + i);
        float o0 = (v.x - mean) * rstd * (1.f + sc.x) + sh.x;
        float o1 = (v.y - mean) * rstd * (1.f + sc.y) + sh.y;
        float o2 = (v.z - mean) * rstd * (1.f + sc.z) + sh.z;
        float o3 = (v.w - mean) * rstd * (1.f + sc.w) + sh.w;
        __nv_bfloat162 h0, l0, h1, l1;
        split_bf(o0, h0.x, l0.x); split_bf(o1, h0.y, l0.y);
        split_bf(o2, h1.x, l1.x); split_bf(o3, h1.y, l1.y);
        *(__nv_bfloat162*)(oh + i) = h0;
        *(__nv_bfloat162*)(oh + i + 2) = h1;
        *(__nv_bfloat162*)(ol + i) = l0;
        *(__nv_bfloat162*)(ol + i + 2) = l1;
    }
}

// attn fp32 -> hi/lo into cat buffer cols [0, DIM)
__global__ void cvt_attn_cat(const float* __restrict__ a, __nv_bfloat16* __restrict__ ch,
                             __nv_bfloat16* __restrict__ cl) {
    int i4 = blockIdx.x * blockDim.x + threadIdx.x;
    if (i4 >= S_LEN * DIM / 4) return;
    int row = i4 / (DIM / 4);
    int c4 = i4 - row * (DIM / 4);
    float4 v = *(const float4*)(a + (size_t)row * DIM + c4 * 4);
    size_t d = (size_t)row * CAT_K + c4 * 4;
    __nv_bfloat162 h0, l0, h1, l1;
    split_bf(v.x, h0.x, l0.x); split_bf(v.y, h0.y, l0.y);
    split_bf(v.z, h1.x, l1.x); split_bf(v.w, h1.y, l1.y);
    *(__nv_bfloat162*)(ch + d) = h0;
    *(__nv_bfloat162*)(ch + d + 2) = h1;
    *(__nv_bfloat162*)(cl + d) = l0;
    *(__nv_bfloat162*)(cl + d + 2) = l1;
}

// ---------------- RMSNorm + RoPE (qkv combined layout, ld=QKV_N) ------------
__global__ __launch_bounds__(128) void rmsrope(float* __restrict__ QKV,
                                               const float* __restrict__ rc,
                                               const float* __restrict__ rs,
                                               const float* __restrict__ wq,
                                               const float* __restrict__ wk) {
    int s = blockIdx.x, h = blockIdx.y;
    int d = threadIdx.x;
    int lane = d & 31, wid = d >> 5;
    __shared__ float red[4];
    float cosd = rc[s * HEAD_DIM + d];
    float sind = rs[s * HEAD_DIM + d];
    size_t offq = (size_t)s * QKV_N + h * HEAD_DIM + d;
    size_t offk = offq + DIM;
    {
        float v = QKV[offq];
        float ss = v * v;
        for (int o = 16; o > 0; o >>= 1) ss += __shfl_xor_sync(0xffffffffu, ss, o);
        if (lane == 0) red[wid] = ss;
        __syncthreads();
        float tot = red[0] + red[1] + red[2] + red[3];
        float xn = v * rsqrtf(tot * (1.f / HEAD_DIM) + 1e-6f) * wq[d];
        float part = __shfl_xor_sync(0xffffffffu, xn, 1);
        float rot = (d & 1) ? part : -part;
        QKV[offq] = xn * cosd + rot * sind;
        __syncthreads();
    }
    {
        float v = QKV[offk];
        float ss = v * v;
        for (int o = 16; o > 0; o >>= 1) ss += __shfl_xor_sync(0xffffffffu, ss, o);
        if (lane == 0) red[wid] = ss;
        __syncthreads();
        float tot = red[0] + red[1] + red[2] + red[3];
        float xn = v * rsqrtf(tot * (1.f / HEAD_DIM) + 1e-6f) * wk[d];
        float part = __shfl_xor_sync(0xffffffffu, xn, 1);
        float rot = (d & 1) ? part : -part;
        QKV[offk] = xn * cosd + rot * sind;
    }
}

// ---------------- fp32 flash attention (qkv ld = QKV_N) ----------------
#define FA_BR 64
#define FA_BC 32

__global__ __launch_bounds__(256) void flash_attn(const float* __restrict__ QKV,
                                                  float* __restrict__ O) {
    int h = blockIdx.y;
    int s0 = blockIdx.x * FA_BR;
    int tid = threadIdx.x;
    int r = tid >> 2;
    int j = tid & 3;

    const float* Q = QKV;
    const float* K = QKV + DIM;
    const float* V = QKV + 2 * DIM;

    __shared__ float Ks[FA_BC][HEAD_DIM];
    __shared__ float Vs[FA_BC][HEAD_DIM];

    const float scale = 0.08838834764831845f;
    float q[32];
    {
        const float* qrow = Q + (size_t)(s0 + r) * QKV_N + h * HEAD_DIM + j * 32;
#pragma unroll
        for (int d4 = 0; d4 < 8; d4++) {
            float4 t = *(const float4*)(qrow + d4 * 4);
            q[d4 * 4 + 0] = t.x * scale;
            q[d4 * 4 + 1] = t.y * scale;
            q[d4 * 4 + 2] = t.z * scale;
            q[d4 * 4 + 3] = t.w * scale;
        }
    }
    float acc[32];
#pragma unroll
    for (int d = 0; d < 32; d++) acc[d] = 0.f;
    float m = -1e30f, l = 0.f;

    for (int kt = 0; kt < S_LEN; kt += FA_BC) {
#pragma unroll
        for (int i = 0; i < 4; i++) {
            int idx = tid + i * 256;
            int c = idx >> 5;
            int d4 = idx & 31;
            size_t goff = (size_t)(kt + c) * QKV_N + h * HEAD_DIM + d4 * 4;
            *(float4*)&Ks[c][d4 * 4] = *(const float4*)(K + goff);
            *(float4*)&Vs[c][d4 * 4] = *(const float4*)(V + goff);
        }
        __syncthreads();

        float sc[FA_BC];
#pragma unroll
        for (int c = 0; c < FA_BC; c++) {
            float s = 0.f;
#pragma unroll
            for (int d4 = 0; d4 < 8; d4++) {
                float4 kk = *(const float4*)&Ks[c][j * 32 + d4 * 4];
                s += q[d4 * 4 + 0] * kk.x + q[d4 * 4 + 1] * kk.y +
                     q[d4 * 4 + 2] * kk.z + q[d4 * 4 + 3] * kk.w;
            }
            s += __shfl_xor_sync(0xffffffffu, s, 1);
            s += __shfl_xor_sync(0xffffffffu, s, 2);
            sc[c] = s;
        }

        float mnew = m;
#pragma unroll
        for (int c = 0; c < FA_BC; c++) mnew = fmaxf(mnew, sc[c]);
        float corr = __expf(m - mnew);
        m = mnew;
        l *= corr;
#pragma unroll
        for (int d = 0; d < 32; d++) acc[d] *= corr;

#pragma unroll
        for (int c = 0; c < FA_BC; c++) {
            float p = __expf(sc[c] - mnew);
            l += p;
#pragma unroll
            for (int d4 = 0; d4 < 8; d4++) {
                float4 vv = *(const float4*)&Vs[c][j * 32 + d4 * 4];
                acc[d4 * 4 + 0] += p * vv.x;
                acc[d4 * 4 + 1] += p * vv.y;
                acc[d4 * 4 + 2] += p * vv.z;
                acc[d4 * 4 + 3] += p * vv.w;
            }
        }
        __syncthreads();
    }

    float inv = 1.f / l;
    float* orow = O + (size_t)(s0 + r) * DIM + h * HEAD_DIM + j * 32;
#pragma unroll
    for (int d4 = 0; d4 < 8; d4++) {
        float4 o = make_float4(acc[d4 * 4 + 0] * inv, acc[d4 * 4 + 1] * inv,
                               acc[d4 * 4 + 2] * inv, acc[d4 * 4 + 3] * inv);
        *(float4*)(orow + d4 * 4) = o;
    }
}

// ---------------- launch ----------------
extern "C" void kernel_launch(void* const* d_in, const int* in_sizes, int n_in,
                              void* d_out, int out_size) {
    const float* hidden = (const float*)d_in[0];
    const float* temb = (const float*)d_in[1];
    const float* rope_cos = (const float*)d_in[2];
    const float* rope_sin = (const float*)d_in[3];
    const float* norm_w = (const float*)d_in[4];
    const float* norm_b = (const float*)d_in[5];
    const float* mlp_w = (const float*)d_in[6];
    const float* mlp_b = (const float*)d_in[7];
    const float* q_w = (const float*)d_in[8];
    const float* q_b = (const float*)d_in[9];
    const float* k_w = (const float*)d_in[10];
    const float* k_b = (const float*)d_in[11];
    const float* v_w = (const float*)d_in[12];
    const float* v_b = (const float*)d_in[13];
    const float* rms_q_w = (const float*)d_in[14];
    const float* rms_k_w = (const float*)d_in[15];
    const float* out_w = (const float*)d_in[16];
    const float* out_b = (const float*)d_in[17];
    float* out = (float*)d_out;

    float *emb_p, *qkv_p, *attn_p, *bqkv_p;
    __nv_bfloat16 *nh_h, *nh_l, *wqkv_h, *wqkv_l, *wm_h, *wm_l, *wo_h, *wo_l, *cat_h, *cat_l;
    cudaGetSymbolAddress((void**)&emb_p, g_emb);
    cudaGetSymbolAddress((void**)&qkv_p, g_qkv);
    cudaGetSymbolAddress((void**)&attn_p, g_attn);
    cudaGetSymbolAddress((void**)&bqkv_p, g_bqkv);
    cudaGetSymbolAddress((void**)&nh_h, g_nh_h);
    cudaGetSymbolAddress((void**)&nh_l, g_nh_l);
    cudaGetSymbolAddress((void**)&wqkv_h, g_wqkv_h);
    cudaGetSymbolAddress((void**)&wqkv_l, g_wqkv_l);
    cudaGetSymbolAddress((void**)&wm_h, g_wm_h);
    cudaGetSymbolAddress((void**)&wm_l, g_wm_l);
    cudaGetSymbolAddress((void**)&wo_h, g_wo_h);
    cudaGetSymbolAddress((void**)&wo_l, g_wo_l);
    cudaGetSymbolAddress((void**)&cat_h, g_cat_h);
    cudaGetSymbolAddress((void**)&cat_l, g_cat_l);

    cudaFuncSetAttribute(gemm_mma<0>, cudaFuncAttributeMaxDynamicSharedMemorySize, GEMM_SMEM);
    cudaFuncSetAttribute(gemm_mma<1>, cudaFuncAttributeMaxDynamicSharedMemorySize, GEMM_SMEM);
    cudaFuncSetAttribute(gemm_mma<2>, cudaFuncAttributeMaxDynamicSharedMemorySize, GEMM_SMEM);

    // 1. all weight conversions (one kernel)
    cvt_all<<<(unsigned)((CVT_TOTAL / 4 + 255) / 256), 256>>>(
        q_w, k_w, v_w, mlp_w, out_w, wqkv_h, wqkv_l, wm_h, wm_l, wo_h, wo_l);
    // 2. concat qkv bias
    cat_bias<<<(DIM + 255) / 256, 256>>>(q_b, k_b, v_b, bqkv_p);
    // 3. adaLN embedding (silu fused)
    emb_gemv<<<3 * DIM, 128>>>(temb, norm_w, norm_b, emb_p);
    // 4. LayerNorm + modulate -> nh hi/lo
    ln_mod<<<S_LEN, 256>>>(hidden, emb_p, nh_h, nh_l);
    // 5. MLP GEMM (+bias+gelu) -> cat[:, DIM:]
    gemm_mma<1><<<(S_LEN / 128) * (MLP_H / 128), 512, GEMM_SMEM>>>(
        nh_h, nh_l, wm_h, wm_l, S_LEN, DIM, DIM, DIM,
        mlp_b, nullptr, 0, cat_h, cat_l, CAT_K, DIM, nullptr, nullptr);
    // 6. fused QKV GEMM (N=9216)   <-- ncu skip-5 sample lands here
    gemm_mma<0><<<(S_LEN / 128) * (QKV_N / 128), 512, GEMM_SMEM>>>(
        nh_h, nh_l, wqkv_h, wqkv_l, S_LEN, DIM, DIM, DIM,
        bqkv_p, qkv_p, QKV_N, nullptr, nullptr, 0, 0, nullptr, nullptr);
    // 7. RMSNorm + RoPE on q,k (in combined buffer)
    rmsrope<<<dim3(S_LEN, HEADS), HEAD_DIM>>>(qkv_p, rope_cos, rope_sin, rms_q_w, rms_k_w);
    // 8. flash attention
    flash_attn<<<dim3(S_LEN / FA_BR, HEADS), 256>>>(qkv_p, attn_p);
    // 9. attn -> cat[:, :DIM] hi/lo
    cvt_attn_cat<<<(S_LEN * DIM / 4 + 255) / 256, 256>>>(attn_p, cat_h, cat_l);
    // 10. out-proj GEMM over K=15360 + gated residual -> d_out
    gemm_mma<2><<<(S_LEN / 128) * (DIM / 128), 512, GEMM_SMEM>>>(
        cat_h, cat_l, wo_h, wo_l, S_LEN, CAT_K, CAT_K, CAT_K,
        out_b, out, DIM, nullptr, nullptr, 0, 0, hidden, emb_p + 2 * DIM);
}

// round 5
// speedup vs baseline: 4.1779x; 2.6465x over previous
#include <cuda_runtime.h>
#include <cuda_fp16.h>
#include <cstdint>
#include <math.h>

#define S_LEN 2048
#define DIM 3072
#define HEADS 24
#define HEAD_DIM 128
#define MLP_H 12288
#define CAT_K (DIM + MLP_H)   // 15360
#define QKV_N (3 * DIM)       // 9216

// ---------------- scratch (device globals; no runtime allocs allowed) -------
#define ALN __align__(128)
__device__ ALN float g_emb[3 * DIM];
__device__ ALN float g_qkv[S_LEN * QKV_N];
__device__ ALN float g_attn[S_LEN * DIM];
__device__ ALN float g_bqkv[QKV_N];
__device__ ALN __half g_nh_h[S_LEN * DIM];
__device__ ALN __half g_nh_l[S_LEN * DIM];
__device__ ALN __half g_wqkv[QKV_N * DIM];
__device__ ALN __half g_wm[MLP_H * DIM];
__device__ ALN __half g_wo[DIM * CAT_K];
__device__ ALN __half g_cat_h[S_LEN * CAT_K];
__device__ ALN __half g_cat_l[S_LEN * CAT_K];

// ---------------- PTX helpers ----------------
__device__ __forceinline__ uint32_t smem_u32(const void* p) {
    uint32_t a;
    asm("{ .reg .u64 t; cvta.to.shared.u64 t, %1; cvt.u32.u64 %0, t; }" : "=r"(a) : "l"(p));
    return a;
}
__device__ __forceinline__ void cpa16(uint32_t s, const void* g) {
    asm volatile("cp.async.cg.shared.global [%0], [%1], 16;" :: "r"(s), "l"(g));
}
__device__ __forceinline__ void cpa_commit() { asm volatile("cp.async.commit_group;" ::: "memory"); }
template <int N>
__device__ __forceinline__ void cpa_wait() { asm volatile("cp.async.wait_group %0;" :: "n"(N) : "memory"); }

__device__ __forceinline__ void ldsm_x4(uint32_t* r, uint32_t addr) {
    asm volatile("ldmatrix.sync.aligned.m8n8.x4.shared.b16 {%0,%1,%2,%3}, [%4];"
                 : "=r"(r[0]), "=r"(r[1]), "=r"(r[2]), "=r"(r[3]) : "r"(addr));
}
__device__ __forceinline__ void mma16816(float* d, const uint32_t* a, const uint32_t* b) {
    asm volatile(
        "mma.sync.aligned.m16n8k16.row.col.f32.f16.f16.f32 "
        "{%0,%1,%2,%3}, {%4,%5,%6,%7}, {%8,%9}, {%0,%1,%2,%3};"
        : "+f"(d[0]), "+f"(d[1]), "+f"(d[2]), "+f"(d[3])
        : "r"(a[0]), "r"(a[1]), "r"(a[2]), "r"(a[3]), "r"(b[0]), "r"(b[1]));
}

__device__ __forceinline__ float geluf(float x) {
    float inner = 0.7978845608028654f * (x + 0.044715f * x * x * x);
    return 0.5f * x * (1.f + tanhf(inner));
}
__device__ __forceinline__ void split_h(float v, __half& h, __half& l) {
    h = __float2half_rn(v);
    l = __float2half_rn(v - __half2float(h));
}

// ---------------- mma.sync fp16 2-pass GEMM (512 thr, BK=64, 3-stage) -------
// C[m,n] = sum_k A[m,k]*B[n,k]; A as fp16 hi/lo pair (exact), B single fp16.
// MODE 0: Cf = acc + bias                 (QKV, ldc=QKV_N)
// MODE 1: split(gelu(acc+bias)) -> Ch/Cl at col offset ccol0 (MLP->cat)
// MODE 2: Cf = hidden + gate*(acc+bias)   (out-proj + residual)
#define BK 64
#define PITCHB 144                        // bytes per smem row (128 data + 16 pad)
#define MAT_BYTES (128 * PITCHB)          // 18432
#define STAGE_BYTES (3 * MAT_BYTES)       // Ah, Al, Bh = 55296
#define GEMM_SMEM (3 * STAGE_BYTES)       // 165888

// copy 128 rows x 64 fp16 (K-major) into padded smem tile; 512 threads
__device__ __forceinline__ void load_mat(uint32_t dst, const __half* g, int ld,
                                         int row0, int k0, int tid) {
    const __half* gp = g + (size_t)row0 * ld + k0;
#pragma unroll
    for (int i = 0; i < 2; i++) {
        int idx = tid + i * 512;          // 0..1023
        int row = idx >> 3;               // 0..127
        int c = idx & 7;                  // 0..7 (16B chunks)
        cpa16(dst + row * PITCHB + c * 16, gp + (size_t)row * ld + c * 8);
    }
}

template <int MODE>
__global__ __launch_bounds__(512, 1)
void gemm_mma(const __half* __restrict__ Ah, const __half* __restrict__ Al,
              const __half* __restrict__ Bh,
              int Mtot, int Ktot, int lda, int ldb,
              const float* __restrict__ bias,
              float* __restrict__ Cf, int ldc,
              __half* __restrict__ Ch, __half* __restrict__ Cl,
              int ldch, int ccol0,
              const float* __restrict__ hidden, const float* __restrict__ gate) {
    extern __shared__ char smem[];
    uint32_t sb = smem_u32(smem);
    int tid = threadIdx.x;
    int warp = tid >> 5, lane = tid & 31;
    int wm = warp & 3;        // 0..3 -> 32-row group
    int wn = warp >> 2;       // 0..3 -> 32-col group

    int mtiles = Mtot >> 7;
    int bm0 = (blockIdx.x % mtiles) << 7;
    int bn0 = (blockIdx.x / mtiles) << 7;

    float acc[2][4][4];
#pragma unroll
    for (int i = 0; i < 2; i++)
#pragma unroll
        for (int j = 0; j < 4; j++)
#pragma unroll
            for (int c = 0; c < 4; c++) acc[i][j][c] = 0.f;

    const int iters = Ktot / BK;

    // prologue: stages 0 and 1
#pragma unroll
    for (int s = 0; s < 2; s++) {
        uint32_t st = sb + s * STAGE_BYTES;
        load_mat(st, Ah, lda, bm0, s * BK, tid);
        load_mat(st + MAT_BYTES, Al, lda, bm0, s * BK, tid);
        load_mat(st + 2 * MAT_BYTES, Bh, ldb, bn0, s * BK, tid);
        cpa_commit();
    }

    // ldmatrix intra-tile offsets
    uint32_t a_off = (uint32_t)(wm * 32 + (lane & 15)) * PITCHB + ((lane >> 4) * 8) * 2;
    uint32_t b_off = (uint32_t)(wn * 32 + ((lane >> 4) & 1) * 8 + (lane & 7)) * PITCHB
                   + (((lane >> 3) & 1) * 8) * 2;

    for (int it = 0; it < iters; ++it) {
        int s = it % 3;
        if (it + 1 < iters) cpa_wait<1>(); else cpa_wait<0>();
        __syncthreads();

        if (it + 2 < iters) {
            int s2 = (it + 2) % 3;
            uint32_t st = sb + s2 * STAGE_BYTES;
            int k0 = (it + 2) * BK;
            load_mat(st, Ah, lda, bm0, k0, tid);
            load_mat(st + MAT_BYTES, Al, lda, bm0, k0, tid);
            load_mat(st + 2 * MAT_BYTES, Bh, ldb, bn0, k0, tid);
            cpa_commit();
        }

        uint32_t stg = sb + s * STAGE_BYTES;
#pragma unroll
        for (int kk = 0; kk < 4; kk++) {
            uint32_t kb = kk * 32;   // 16 fp16 = 32 bytes per k-step
            uint32_t ah[2][4], al[2][4], bh[2][4];
#pragma unroll
            for (int mi = 0; mi < 2; mi++) {
                uint32_t addr = stg + a_off + (uint32_t)mi * 16 * PITCHB + kb;
                ldsm_x4(ah[mi], addr);
                ldsm_x4(al[mi], addr + MAT_BYTES);
            }
#pragma unroll
            for (int p = 0; p < 2; p++) {
                uint32_t addr = stg + 2 * MAT_BYTES + b_off + (uint32_t)p * 16 * PITCHB + kb;
                ldsm_x4(bh[p], addr);
            }
#pragma unroll
            for (int mi = 0; mi < 2; mi++) {
#pragma unroll
                for (int ni = 0; ni < 4; ni++) {
                    const uint32_t* bf = &bh[ni >> 1][(ni & 1) * 2];
                    mma16816(acc[mi][ni], ah[mi], bf);   // hi(A) * B
                    mma16816(acc[mi][ni], al[mi], bf);   // lo(A) * B
                }
            }
        }
    }

    // ---------------- epilogue ----------------
    int rq = lane >> 2;            // 0..7
    int cq = (lane & 3) * 2;       // 0,2,4,6
#pragma unroll
    for (int mi = 0; mi < 2; mi++) {
#pragma unroll
        for (int ni = 0; ni < 4; ni++) {
            int n = bn0 + wn * 32 + ni * 8 + cq;
#pragma unroll
            for (int half = 0; half < 2; half++) {
                size_t m = (size_t)bm0 + wm * 32 + mi * 16 + rq + half * 8;
                float v0 = acc[mi][ni][half * 2 + 0];
                float v1 = acc[mi][ni][half * 2 + 1];
                if (MODE == 0) {
                    float2 o = make_float2(v0 + bias[n], v1 + bias[n + 1]);
                    *(float2*)(Cf + m * ldc + n) = o;
                } else if (MODE == 1) {
                    float g0 = geluf(v0 + bias[n]);
                    float g1 = geluf(v1 + bias[n + 1]);
                    __half2 h, l;
                    split_h(g0, h.x, l.x);
                    split_h(g1, h.y, l.y);
                    *(__half2*)(Ch + m * ldch + ccol0 + n) = h;
                    *(__half2*)(Cl + m * ldch + ccol0 + n) = l;
                } else {
                    const float* hp = hidden + m * ldc + n;
                    float2 hv = *(const float2*)hp;
                    float2 o;
                    o.x = hv.x + gate[n] * (v0 + bias[n]);
                    o.y = hv.y + gate[n + 1] * (v1 + bias[n + 1]);
                    *(float2*)(Cf + m * ldc + n) = o;
                }
            }
        }
    }
}

// ---------------- fused weight conversion (single fp16 round) --------------
#define QW_N ((long)DIM * DIM)                 // 9437184
#define CVT_TOTAL (3 * QW_N + (long)MLP_H * DIM + (long)DIM * CAT_K)

__global__ void cvt_all(const float* __restrict__ q_w, const float* __restrict__ k_w,
                        const float* __restrict__ v_w, const float* __restrict__ mlp_w,
                        const float* __restrict__ out_w,
                        __half* __restrict__ wqkv, __half* __restrict__ wm,
                        __half* __restrict__ wo) {
    long i = ((long)blockIdx.x * blockDim.x + threadIdx.x) * 4;
    if (i >= CVT_TOTAL) return;
    const float* src;
    __half* dh;
    long off;
    if (i < QW_N) { src = q_w; off = i; dh = wqkv; }
    else if (i < 2 * QW_N) { src = k_w; off = i - QW_N; dh = wqkv + QW_N; }
    else if (i < 3 * QW_N) { src = v_w; off = i - 2 * QW_N; dh = wqkv + 2 * QW_N; }
    else if (i < 3 * QW_N + (long)MLP_H * DIM) { src = mlp_w; off = i - 3 * QW_N; dh = wm; }
    else { src = out_w; off = i - 3 * QW_N - (long)MLP_H * DIM; dh = wo; }
    float4 v = *(const float4*)(src + off);
    __half2 h0 = make_half2(__float2half_rn(v.x), __float2half_rn(v.y));
    __half2 h1 = make_half2(__float2half_rn(v.z), __float2half_rn(v.w));
    *(__half2*)(dh + off) = h0;
    *(__half2*)(dh + off + 2) = h1;
}

__global__ void cat_bias(const float* __restrict__ qb, const float* __restrict__ kb,
                         const float* __restrict__ vb, float* __restrict__ o) {
    int i = blockIdx.x * blockDim.x + threadIdx.x;
    if (i < DIM) { o[i] = qb[i]; o[DIM + i] = kb[i]; o[2 * DIM + i] = vb[i]; }
}

// ---------------- adaLN embedding GEMV with fused silu ----------------
__global__ __launch_bounds__(128) void emb_gemv(const float* __restrict__ temb,
                                                const float* __restrict__ w,
                                                const float* __restrict__ b,
                                                float* __restrict__ emb) {
    int jrow = blockIdx.x;
    const float* wr = w + (size_t)jrow * DIM;
    int tid = threadIdx.x;
    float s = 0.f;
    for (int i = tid * 4; i < DIM; i += 512) {
        float4 a = *(const float4*)(temb + i);
        float4 ww = *(const float4*)(wr + i);
        a.x = a.x / (1.f + __expf(-a.x));
        a.y = a.y / (1.f + __expf(-a.y));
        a.z = a.z / (1.f + __expf(-a.z));
        a.w = a.w / (1.f + __expf(-a.w));
        s += a.x * ww.x + a.y * ww.y + a.z * ww.z + a.w * ww.w;
    }
    for (int o = 16; o > 0; o >>= 1) s += __shfl_xor_sync(0xffffffffu, s, o);
    __shared__ float sm[4];
    if ((tid & 31) == 0) sm[tid >> 5] = s;
    __syncthreads();
    if (tid == 0) emb[jrow] = sm[0] + sm[1] + sm[2] + sm[3] + b[jrow];
}

// LayerNorm + adaLN modulate, emits fp16 hi/lo directly
__global__ __launch_bounds__(256) void ln_mod(const float* __restrict__ x,
                                              const float* __restrict__ emb,
                                              __half* __restrict__ nh_h,
                                              __half* __restrict__ nh_l) {
    int srow = blockIdx.x;
    int tid = threadIdx.x;
    const float* row = x + (size_t)srow * DIM;
    float sum = 0.f, sq = 0.f;
    for (int i = tid * 4; i < DIM; i += 1024) {
        float4 v = *(const float4*)(row + i);
        sum += v.x + v.y + v.z + v.w;
        sq += v.x * v.x + v.y * v.y + v.z * v.z + v.w * v.w;
    }
    for (int o = 16; o > 0; o >>= 1) {
        sum += __shfl_xor_sync(0xffffffffu, sum, o);
        sq += __shfl_xor_sync(0xffffffffu, sq, o);
    }
    __shared__ float s1[8], s2[8];
    if ((tid & 31) == 0) { s1[tid >> 5] = sum; s2[tid >> 5] = sq; }
    __syncthreads();
    sum = 0.f; sq = 0.f;
#pragma unroll
    for (int w = 0; w < 8; w++) { sum += s1[w]; sq += s2[w]; }
    float mean = sum * (1.f / DIM);
    float var = sq * (1.f / DIM) - mean * mean;
    float rstd = rsqrtf(var + 1e-6f);
    __half* oh = nh_h + (size_t)srow * DIM;
    __half* ol = nh_l + (size_t)srow * DIM;
    for (int i = tid * 4; i < DIM; i += 1024) {
        float4 v = *(const float4*)(row + i);
        float4 sc = *(const float4*)(emb + DIM + i);
        float4 sh = *(const float4*)(emb + i);
        float o0 = (v.x - mean) * rstd * (1.f + sc.x) + sh.x;
        float o1 = (v.y - mean) * rstd * (1.f + sc.y) + sh.y;
        float o2 = (v.z - mean) * rstd * (1.f + sc.z) + sh.z;
        float o3 = (v.w - mean) * rstd * (1.f + sc.w) + sh.w;
        __half2 h0, l0, h1, l1;
        split_h(o0, h0.x, l0.x); split_h(o1, h0.y, l0.y);
        split_h(o2, h1.x, l1.x); split_h(o3, h1.y, l1.y);
        *(__half2*)(oh + i) = h0;
        *(__half2*)(oh + i + 2) = h1;
        *(__half2*)(ol + i) = l0;
        *(__half2*)(ol + i + 2) = l1;
    }
}

// attn fp32 -> fp16 hi/lo into cat buffer cols [0, DIM)
__global__ void cvt_attn_cat(const float* __restrict__ a, __half* __restrict__ ch,
                             __half* __restrict__ cl) {
    int i4 = blockIdx.x * blockDim.x + threadIdx.x;
    if (i4 >= S_LEN * DIM / 4) return;
    int row = i4 / (DIM / 4);
    int c4 = i4 - row * (DIM / 4);
    float4 v = *(const float4*)(a + (size_t)row * DIM + c4 * 4);
    size_t d = (size_t)row * CAT_K + c4 * 4;
    __half2 h0, l0, h1, l1;
    split_h(v.x, h0.x, l0.x); split_h(v.y, h0.y, l0.y);
    split_h(v.z, h1.x, l1.x); split_h(v.w, h1.y, l1.y);
    *(__half2*)(ch + d) = h0;
    *(__half2*)(ch + d + 2) = h1;
    *(__half2*)(cl + d) = l0;
    *(__half2*)(cl + d + 2) = l1;
}

// ---------------- RMSNorm + RoPE (qkv combined layout, ld=QKV_N) ------------
__global__ __launch_bounds__(128) void rmsrope(float* __restrict__ QKV,
                                               const float* __restrict__ rc,
                                               const float* __restrict__ rs,
                                               const float* __restrict__ wq,
                                               const float* __restrict__ wk) {
    int s = blockIdx.x, h = blockIdx.y;
    int d = threadIdx.x;
    int lane = d & 31, wid = d >> 5;
    __shared__ float red[4];
    float cosd = rc[s * HEAD_DIM + d];
    float sind = rs[s * HEAD_DIM + d];
    size_t offq = (size_t)s * QKV_N + h * HEAD_DIM + d;
    size_t offk = offq + DIM;
    {
        float v = QKV[offq];
        float ss = v * v;
        for (int o = 16; o > 0; o >>= 1) ss += __shfl_xor_sync(0xffffffffu, ss, o);
        if (lane == 0) red[wid] = ss;
        __syncthreads();
        float tot = red[0] + red[1] + red[2] + red[3];
        float xn = v * rsqrtf(tot * (1.f / HEAD_DIM) + 1e-6f) * wq[d];
        float part = __shfl_xor_sync(0xffffffffu, xn, 1);
        float rot = (d & 1) ? part : -part;
        QKV[offq] = xn * cosd + rot * sind;
        __syncthreads();
    }
    {
        float v = QKV[offk];
        float ss = v * v;
        for (int o = 16; o > 0; o >>= 1) ss += __shfl_xor_sync(0xffffffffu, ss, o);
        if (lane == 0) red[wid] = ss;
        __syncthreads();
        float tot = red[0] + red[1] + red[2] + red[3];
        float xn = v * rsqrtf(tot * (1.f / HEAD_DIM) + 1e-6f) * wk[d];
        float part = __shfl_xor_sync(0xffffffffu, xn, 1);
        float rot = (d & 1) ? part : -part;
        QKV[offk] = xn * cosd + rot * sind;
    }
}

// ---------------- fp32 flash attention (swizzled smem, qkv ld = QKV_N) ------
#define FA_BR 64
#define FA_BC 32
// chunk swizzle: logical 16B-chunk t (0..31) -> physical t ^ ((t>>3)<<1)
// kills the 4-way bank alias between the 4 column-quarter readers.
__device__ __forceinline__ int swz(int t) { return t ^ ((t >> 3) << 1); }

__global__ __launch_bounds__(256) void flash_attn(const float* __restrict__ QKV,
                                                  float* __restrict__ O) {
    int h = blockIdx.y;
    int s0 = blockIdx.x * FA_BR;
    int tid = threadIdx.x;
    int r = tid >> 2;
    int j = tid & 3;

    const float* Q = QKV;
    const float* K = QKV + DIM;
    const float* V = QKV + 2 * DIM;

    __shared__ float4 Ks[FA_BC * 32];
    __shared__ float4 Vs[FA_BC * 32];

    const float scale = 0.08838834764831845f;
    float q[32];
    {
        const float* qrow = Q + (size_t)(s0 + r) * QKV_N + h * HEAD_DIM + j * 32;
#pragma unroll
        for (int d4 = 0; d4 < 8; d4++) {
            float4 t = *(const float4*)(qrow + d4 * 4);
            q[d4 * 4 + 0] = t.x * scale;
            q[d4 * 4 + 1] = t.y * scale;
            q[d4 * 4 + 2] = t.z * scale;
            q[d4 * 4 + 3] = t.w * scale;
        }
    }
    float acc[32];
#pragma unroll
    for (int d = 0; d < 32; d++) acc[d] = 0.f;
    float m = -1e30f, l = 0.f;

    // per-thread swizzled chunk indices for its 32-dim quarter
    int sw[8];
#pragma unroll
    for (int d4 = 0; d4 < 8; d4++) sw[d4] = swz(j * 8 + d4);

    for (int kt = 0; kt < S_LEN; kt += FA_BC) {
#pragma unroll
        for (int i = 0; i < 4; i++) {
            int idx = tid + i * 256;      // 0..1023 float4 chunks
            int c = idx >> 5;             // key row in tile
            int t = idx & 31;             // logical chunk
            int p = c * 32 + swz(t);
            size_t goff = (size_t)(kt + c) * QKV_N + h * HEAD_DIM + t * 4;
            Ks[p] = *(const float4*)(K + goff);
            Vs[p] = *(const float4*)(V + goff);
        }
        __syncthreads();

        float sc[FA_BC];
#pragma unroll
        for (int c = 0; c < FA_BC; c++) {
            float s = 0.f;
            const float4* kr = &Ks[c * 32];
#pragma unroll
            for (int d4 = 0; d4 < 8; d4++) {
                float4 kk = kr[sw[d4]];
                s += q[d4 * 4 + 0] * kk.x + q[d4 * 4 + 1] * kk.y +
                     q[d4 * 4 + 2] * kk.z + q[d4 * 4 + 3] * kk.w;
            }
            s += __shfl_xor_sync(0xffffffffu, s, 1);
            s += __shfl_xor_sync(0xffffffffu, s, 2);
            sc[c] = s;
        }

        float mnew = m;
#pragma unroll
        for (int c = 0; c < FA_BC; c++) mnew = fmaxf(mnew, sc[c]);
        float corr = __expf(m - mnew);
        m = mnew;
        l *= corr;
#pragma unroll
        for (int d = 0; d < 32; d++) acc[d] *= corr;

#pragma unroll
        for (int c = 0; c < FA_BC; c++) {
            float p = __expf(sc[c] - mnew);
            l += p;
            const float4* vr = &Vs[c * 32];
#pragma unroll
            for (int d4 = 0; d4 < 8; d4++) {
                float4 vv = vr[sw[d4]];
                acc[d4 * 4 + 0] += p * vv.x;
                acc[d4 * 4 + 1] += p * vv.y;
                acc[d4 * 4 + 2] += p * vv.z;
                acc[d4 * 4 + 3] += p * vv.w;
            }
        }
        __syncthreads();
    }

    float inv = 1.f / l;
    float* orow = O + (size_t)(s0 + r) * DIM + h * HEAD_DIM + j * 32;
#pragma unroll
    for (int d4 = 0; d4 < 8; d4++) {
        float4 o = make_float4(acc[d4 * 4 + 0] * inv, acc[d4 * 4 + 1] * inv,
                               acc[d4 * 4 + 2] * inv, acc[d4 * 4 + 3] * inv);
        *(float4*)(orow + d4 * 4) = o;
    }
}

// ---------------- launch ----------------
extern "C" void kernel_launch(void* const* d_in, const int* in_sizes, int n_in,
                              void* d_out, int out_size) {
    const float* hidden = (const float*)d_in[0];
    const float* temb = (const float*)d_in[1];
    const float* rope_cos = (const float*)d_in[2];
    const float* rope_sin = (const float*)d_in[3];
    const float* norm_w = (const float*)d_in[4];
    const float* norm_b = (const float*)d_in[5];
    const float* mlp_w = (const float*)d_in[6];
    const float* mlp_b = (const float*)d_in[7];
    const float* q_w = (const float*)d_in[8];
    const float* q_b = (const float*)d_in[9];
    const float* k_w = (const float*)d_in[10];
    const float* k_b = (const float*)d_in[11];
    const float* v_w = (const float*)d_in[12];
    const float* v_b = (const float*)d_in[13];
    const float* rms_q_w = (const float*)d_in[14];
    const float* rms_k_w = (const float*)d_in[15];
    const float* out_w = (const float*)d_in[16];
    const float* out_b = (const float*)d_in[17];
    float* out = (float*)d_out;

    float *emb_p, *qkv_p, *attn_p, *bqkv_p;
    __half *nh_h, *nh_l, *wqkv, *wm, *wo, *cat_h, *cat_l;
    cudaGetSymbolAddress((void**)&emb_p, g_emb);
    cudaGetSymbolAddress((void**)&qkv_p, g_qkv);
    cudaGetSymbolAddress((void**)&attn_p, g_attn);
    cudaGetSymbolAddress((void**)&bqkv_p, g_bqkv);
    cudaGetSymbolAddress((void**)&nh_h, g_nh_h);
    cudaGetSymbolAddress((void**)&nh_l, g_nh_l);
    cudaGetSymbolAddress((void**)&wqkv, g_wqkv);
    cudaGetSymbolAddress((void**)&wm, g_wm);
    cudaGetSymbolAddress((void**)&wo, g_wo);
    cudaGetSymbolAddress((void**)&cat_h, g_cat_h);
    cudaGetSymbolAddress((void**)&cat_l, g_cat_l);

    cudaFuncSetAttribute(gemm_mma<0>, cudaFuncAttributeMaxDynamicSharedMemorySize, GEMM_SMEM);
    cudaFuncSetAttribute(gemm_mma<1>, cudaFuncAttributeMaxDynamicSharedMemorySize, GEMM_SMEM);
    cudaFuncSetAttribute(gemm_mma<2>, cudaFuncAttributeMaxDynamicSharedMemorySize, GEMM_SMEM);

    // launch order arranged so launch #4 (the ncu sample) is the MLP GEMM
    // 1. adaLN embedding (silu fused)
    emb_gemv<<<3 * DIM, 128>>>(temb, norm_w, norm_b, emb_p);
    // 2. all weight conversions (single fp16)
    cvt_all<<<(unsigned)((CVT_TOTAL / 4 + 255) / 256), 256>>>(
        q_w, k_w, v_w, mlp_w, out_w, wqkv, wm, wo);
    // 3. LayerNorm + modulate -> nh hi/lo
    ln_mod<<<S_LEN, 256>>>(hidden, emb_p, nh_h, nh_l);
    // 4. MLP GEMM (+bias+gelu) -> cat[:, DIM:]    <-- ncu profiles this
    gemm_mma<1><<<(S_LEN / 128) * (MLP_H / 128), 512, GEMM_SMEM>>>(
        nh_h, nh_l, wm, S_LEN, DIM, DIM, DIM,
        mlp_b, nullptr, 0, cat_h, cat_l, CAT_K, DIM, nullptr, nullptr);
    // 5. concat qkv bias
    cat_bias<<<(DIM + 255) / 256, 256>>>(q_b, k_b, v_b, bqkv_p);
    // 6. fused QKV GEMM (N=9216)
    gemm_mma<0><<<(S_LEN / 128) * (QKV_N / 128), 512, GEMM_SMEM>>>(
        nh_h, nh_l, wqkv, S_LEN, DIM, DIM, DIM,
        bqkv_p, qkv_p, QKV_N, nullptr, nullptr, 0, 0, nullptr, nullptr);
    // 7. RMSNorm + RoPE on q,k (in combined buffer)
    rmsrope<<<dim3(S_LEN, HEADS), HEAD_DIM>>>(qkv_p, rope_cos, rope_sin, rms_q_w, rms_k_w);
    // 8. flash attention
    flash_attn<<<dim3(S_LEN / FA_BR, HEADS), 256>>>(qkv_p, attn_p);
    // 9. attn -> cat[:, :DIM] hi/lo
    cvt_attn_cat<<<(S_LEN * DIM / 4 + 255) / 256, 256>>>(attn_p, cat_h, cat_l);
    // 10. out-proj GEMM over K=15360 + gated residual -> d_out
    gemm_mma<2><<<(S_LEN / 128) * (DIM / 128), 512, GEMM_SMEM>>>(
        cat_h, cat_l, wo, S_LEN, CAT_K, CAT_K, CAT_K,
        out_b, out, DIM, nullptr, nullptr, 0, 0, hidden, emb_p + 2 * DIM);
}

// round 6
// speedup vs baseline: 7.9536x; 1.9037x over previous
#include <cuda_runtime.h>
#include <cuda_fp16.h>
#include <cstdint>
#include <math.h>

#define S_LEN 2048
#define DIM 3072
#define HEADS 24
#define HEAD_DIM 128
#define MLP_H 12288
#define CAT_K (DIM + MLP_H)   // 15360
#define QKV_N (3 * DIM)       // 9216

// ---------------- scratch (device globals; no runtime allocs allowed) -------
#define ALN __align__(128)
__device__ ALN float g_emb[3 * DIM];
__device__ ALN float g_qkv[S_LEN * QKV_N];
__device__ ALN float g_bqkv[QKV_N];
__device__ ALN __half g_nh_h[S_LEN * DIM];
__device__ ALN __half g_nh_l[S_LEN * DIM];
__device__ ALN __half g_wqkv[QKV_N * DIM];
__device__ ALN __half g_wm[MLP_H * DIM];
__device__ ALN __half g_wo[DIM * CAT_K];
__device__ ALN __half g_cat_h[S_LEN * CAT_K];
__device__ ALN __half g_cat_l[S_LEN * CAT_K];
__device__ ALN __half g_qh[S_LEN * DIM];
__device__ ALN __half g_ql[S_LEN * DIM];
__device__ ALN __half g_kh[S_LEN * DIM];
__device__ ALN __half g_kl[S_LEN * DIM];
__device__ ALN __half g_vh[S_LEN * DIM];
__device__ ALN __half g_vl[S_LEN * DIM];

// ---------------- PTX helpers ----------------
__device__ __forceinline__ uint32_t smem_u32(const void* p) {
    uint32_t a;
    asm("{ .reg .u64 t; cvta.to.shared.u64 t, %1; cvt.u32.u64 %0, t; }" : "=r"(a) : "l"(p));
    return a;
}
__device__ __forceinline__ void cpa16(uint32_t s, const void* g) {
    asm volatile("cp.async.cg.shared.global [%0], [%1], 16;" :: "r"(s), "l"(g));
}
__device__ __forceinline__ void cpa_commit() { asm volatile("cp.async.commit_group;" ::: "memory"); }
template <int N>
__device__ __forceinline__ void cpa_wait() { asm volatile("cp.async.wait_group %0;" :: "n"(N) : "memory"); }

__device__ __forceinline__ void ldsm_x4(uint32_t* r, uint32_t addr) {
    asm volatile("ldmatrix.sync.aligned.m8n8.x4.shared.b16 {%0,%1,%2,%3}, [%4];"
                 : "=r"(r[0]), "=r"(r[1]), "=r"(r[2]), "=r"(r[3]) : "r"(addr));
}
__device__ __forceinline__ void ldsm_x4_t(uint32_t* r, uint32_t addr) {
    asm volatile("ldmatrix.sync.aligned.m8n8.x4.trans.shared.b16 {%0,%1,%2,%3}, [%4];"
                 : "=r"(r[0]), "=r"(r[1]), "=r"(r[2]), "=r"(r[3]) : "r"(addr));
}
__device__ __forceinline__ void mma16816(float* d, const uint32_t* a, const uint32_t* b) {
    asm volatile(
        "mma.sync.aligned.m16n8k16.row.col.f32.f16.f16.f32 "
        "{%0,%1,%2,%3}, {%4,%5,%6,%7}, {%8,%9}, {%0,%1,%2,%3};"
        : "+f"(d[0]), "+f"(d[1]), "+f"(d[2]), "+f"(d[3])
        : "r"(a[0]), "r"(a[1]), "r"(a[2]), "r"(a[3]), "r"(b[0]), "r"(b[1]));
}

__device__ __forceinline__ float geluf(float x) {
    float inner = 0.7978845608028654f * (x + 0.044715f * x * x * x);
    return 0.5f * x * (1.f + tanhf(inner));
}
__device__ __forceinline__ void split_h(float v, __half& h, __half& l) {
    h = __float2half_rn(v);
    l = __float2half_rn(v - __half2float(h));
}
__device__ __forceinline__ uint32_t pack_h2(float a, float b) {
    __half2 t = __floats2half2_rn(a, b);
    return *(uint32_t*)&t;
}

// ---------------- mma.sync fp16 2-pass GEMM (512 thr, BK=64, 3-stage) -------
#define BK 64
#define PITCHB 144
#define MAT_BYTES (128 * PITCHB)
#define STAGE_BYTES (3 * MAT_BYTES)
#define GEMM_SMEM (3 * STAGE_BYTES)

__device__ __forceinline__ void load_mat(uint32_t dst, const __half* g, int ld,
                                         int row0, int k0, int tid) {
    const __half* gp = g + (size_t)row0 * ld + k0;
#pragma unroll
    for (int i = 0; i < 2; i++) {
        int idx = tid + i * 512;
        int row = idx >> 3;
        int c = idx & 7;
        cpa16(dst + row * PITCHB + c * 16, gp + (size_t)row * ld + c * 8);
    }
}

template <int MODE>
__global__ __launch_bounds__(512, 1)
void gemm_mma(const __half* __restrict__ Ah, const __half* __restrict__ Al,
              const __half* __restrict__ Bh,
              int Mtot, int Ktot, int lda, int ldb,
              const float* __restrict__ bias,
              float* __restrict__ Cf, int ldc,
              __half* __restrict__ Ch, __half* __restrict__ Cl,
              int ldch, int ccol0,
              const float* __restrict__ hidden, const float* __restrict__ gate) {
    extern __shared__ char smem[];
    uint32_t sb = smem_u32(smem);
    int tid = threadIdx.x;
    int warp = tid >> 5, lane = tid & 31;
    int wm = warp & 3;
    int wn = warp >> 2;

    int mtiles = Mtot >> 7;
    int bm0 = (blockIdx.x % mtiles) << 7;
    int bn0 = (blockIdx.x / mtiles) << 7;

    float acc[2][4][4];
#pragma unroll
    for (int i = 0; i < 2; i++)
#pragma unroll
        for (int j = 0; j < 4; j++)
#pragma unroll
            for (int c = 0; c < 4; c++) acc[i][j][c] = 0.f;

    const int iters = Ktot / BK;

#pragma unroll
    for (int s = 0; s < 2; s++) {
        uint32_t st = sb + s * STAGE_BYTES;
        load_mat(st, Ah, lda, bm0, s * BK, tid);
        load_mat(st + MAT_BYTES, Al, lda, bm0, s * BK, tid);
        load_mat(st + 2 * MAT_BYTES, Bh, ldb, bn0, s * BK, tid);
        cpa_commit();
    }

    uint32_t a_off = (uint32_t)(wm * 32 + (lane & 15)) * PITCHB + ((lane >> 4) * 8) * 2;
    uint32_t b_off = (uint32_t)(wn * 32 + ((lane >> 4) & 1) * 8 + (lane & 7)) * PITCHB
                   + (((lane >> 3) & 1) * 8) * 2;

    for (int it = 0; it < iters; ++it) {
        int s = it % 3;
        if (it + 1 < iters) cpa_wait<1>(); else cpa_wait<0>();
        __syncthreads();

        if (it + 2 < iters) {
            int s2 = (it + 2) % 3;
            uint32_t st = sb + s2 * STAGE_BYTES;
            int k0 = (it + 2) * BK;
            load_mat(st, Ah, lda, bm0, k0, tid);
            load_mat(st + MAT_BYTES, Al, lda, bm0, k0, tid);
            load_mat(st + 2 * MAT_BYTES, Bh, ldb, bn0, k0, tid);
            cpa_commit();
        }

        uint32_t stg = sb + s * STAGE_BYTES;
#pragma unroll
        for (int kk = 0; kk < 4; kk++) {
            uint32_t kb = kk * 32;
            uint32_t ah[2][4], al[2][4], bh[2][4];
#pragma unroll
            for (int mi = 0; mi < 2; mi++) {
                uint32_t addr = stg + a_off + (uint32_t)mi * 16 * PITCHB + kb;
                ldsm_x4(ah[mi], addr);
                ldsm_x4(al[mi], addr + MAT_BYTES);
            }
#pragma unroll
            for (int p = 0; p < 2; p++) {
                uint32_t addr = stg + 2 * MAT_BYTES + b_off + (uint32_t)p * 16 * PITCHB + kb;
                ldsm_x4(bh[p], addr);
            }
#pragma unroll
            for (int mi = 0; mi < 2; mi++) {
#pragma unroll
                for (int ni = 0; ni < 4; ni++) {
                    const uint32_t* bf = &bh[ni >> 1][(ni & 1) * 2];
                    mma16816(acc[mi][ni], ah[mi], bf);
                    mma16816(acc[mi][ni], al[mi], bf);
                }
            }
        }
    }

    int rq = lane >> 2;
    int cq = (lane & 3) * 2;
#pragma unroll
    for (int mi = 0; mi < 2; mi++) {
#pragma unroll
        for (int ni = 0; ni < 4; ni++) {
            int n = bn0 + wn * 32 + ni * 8 + cq;
#pragma unroll
            for (int half = 0; half < 2; half++) {
                size_t m = (size_t)bm0 + wm * 32 + mi * 16 + rq + half * 8;
                float v0 = acc[mi][ni][half * 2 + 0];
                float v1 = acc[mi][ni][half * 2 + 1];
                if (MODE == 0) {
                    float2 o = make_float2(v0 + bias[n], v1 + bias[n + 1]);
                    *(float2*)(Cf + m * ldc + n) = o;
                } else if (MODE == 1) {
                    float g0 = geluf(v0 + bias[n]);
                    float g1 = geluf(v1 + bias[n + 1]);
                    __half2 h, l;
                    split_h(g0, h.x, l.x);
                    split_h(g1, h.y, l.y);
                    *(__half2*)(Ch + m * ldch + ccol0 + n) = h;
                    *(__half2*)(Cl + m * ldch + ccol0 + n) = l;
                } else {
                    const float* hp = hidden + m * ldc + n;
                    float2 hv = *(const float2*)hp;
                    float2 o;
                    o.x = hv.x + gate[n] * (v0 + bias[n]);
                    o.y = hv.y + gate[n + 1] * (v1 + bias[n + 1]);
                    *(float2*)(Cf + m * ldc + n) = o;
                }
            }
        }
    }
}

// ---------------- fused weight conversion + qkv bias concat ----------------
#define QW_N ((long)DIM * DIM)
#define CVT_TOTAL (3 * QW_N + (long)MLP_H * DIM + (long)DIM * CAT_K)

__global__ void cvt_all(const float* __restrict__ q_w, const float* __restrict__ k_w,
                        const float* __restrict__ v_w, const float* __restrict__ mlp_w,
                        const float* __restrict__ out_w,
                        __half* __restrict__ wqkv, __half* __restrict__ wm,
                        __half* __restrict__ wo,
                        const float* __restrict__ q_b, const float* __restrict__ k_b,
                        const float* __restrict__ v_b, float* __restrict__ bqkv) {
    long t = (long)blockIdx.x * blockDim.x + threadIdx.x;
    if (t < 3 * DIM / 4) {
        int i = (int)t * 4;
        const float* src = i < DIM ? q_b : (i < 2 * DIM ? k_b : v_b);
        *(float4*)(bqkv + i) = *(const float4*)(src + (i % DIM));
    }
    long i = t * 4;
    if (i >= CVT_TOTAL) return;
    const float* src;
    __half* dh;
    long off;
    if (i < QW_N) { src = q_w; off = i; dh = wqkv; }
    else if (i < 2 * QW_N) { src = k_w; off = i - QW_N; dh = wqkv + QW_N; }
    else if (i < 3 * QW_N) { src = v_w; off = i - 2 * QW_N; dh = wqkv + 2 * QW_N; }
    else if (i < 3 * QW_N + (long)MLP_H * DIM) { src = mlp_w; off = i - 3 * QW_N; dh = wm; }
    else { src = out_w; off = i - 3 * QW_N - (long)MLP_H * DIM; dh = wo; }
    float4 v = *(const float4*)(src + off);
    __half2 h0 = make_half2(__float2half_rn(v.x), __float2half_rn(v.y));
    __half2 h1 = make_half2(__float2half_rn(v.z), __float2half_rn(v.w));
    *(__half2*)(dh + off) = h0;
    *(__half2*)(dh + off + 2) = h1;
}

// ---------------- adaLN embedding GEMV with fused silu ----------------
__global__ __launch_bounds__(128) void emb_gemv(const float* __restrict__ temb,
                                                const float* __restrict__ w,
                                                const float* __restrict__ b,
                                                float* __restrict__ emb) {
    int jrow = blockIdx.x;
    const float* wr = w + (size_t)jrow * DIM;
    int tid = threadIdx.x;
    float s = 0.f;
    for (int i = tid * 4; i < DIM; i += 512) {
        float4 a = *(const float4*)(temb + i);
        float4 ww = *(const float4*)(wr + i);
        a.x = a.x / (1.f + __expf(-a.x));
        a.y = a.y / (1.f + __expf(-a.y));
        a.z = a.z / (1.f + __expf(-a.z));
        a.w = a.w / (1.f + __expf(-a.w));
        s += a.x * ww.x + a.y * ww.y + a.z * ww.z + a.w * ww.w;
    }
    for (int o = 16; o > 0; o >>= 1) s += __shfl_xor_sync(0xffffffffu, s, o);
    __shared__ float sm[4];
    if ((tid & 31) == 0) sm[tid >> 5] = s;
    __syncthreads();
    if (tid == 0) emb[jrow] = sm[0] + sm[1] + sm[2] + sm[3] + b[jrow];
}

// LayerNorm + adaLN modulate, emits fp16 hi/lo
__global__ __launch_bounds__(256) void ln_mod(const float* __restrict__ x,
                                              const float* __restrict__ emb,
                                              __half* __restrict__ nh_h,
                                              __half* __restrict__ nh_l) {
    int srow = blockIdx.x;
    int tid = threadIdx.x;
    const float* row = x + (size_t)srow * DIM;
    float sum = 0.f, sq = 0.f;
    for (int i = tid * 4; i < DIM; i += 1024) {
        float4 v = *(const float4*)(row + i);
        sum += v.x + v.y + v.z + v.w;
        sq += v.x * v.x + v.y * v.y + v.z * v.z + v.w * v.w;
    }
    for (int o = 16; o > 0; o >>= 1) {
        sum += __shfl_xor_sync(0xffffffffu, sum, o);
        sq += __shfl_xor_sync(0xffffffffu, sq, o);
    }
    __shared__ float s1[8], s2[8];
    if ((tid & 31) == 0) { s1[tid >> 5] = sum; s2[tid >> 5] = sq; }
    __syncthreads();
    sum = 0.f; sq = 0.f;
#pragma unroll
    for (int w = 0; w < 8; w++) { sum += s1[w]; sq += s2[w]; }
    float mean = sum * (1.f / DIM);
    float var = sq * (1.f / DIM) - mean * mean;
    float rstd = rsqrtf(var + 1e-6f);
    __half* oh = nh_h + (size_t)srow * DIM;
    __half* ol = nh_l + (size_t)srow * DIM;
    for (int i = tid * 4; i < DIM; i += 1024) {
        float4 v = *(const float4*)(row + i);
        float4 sc = *(const float4*)(emb + DIM + i);
        float4 sh = *(const float4*)(emb + i);
        float o0 = (v.x - mean) * rstd * (1.f + sc.x) + sh.x;
        float o1 = (v.y - mean) * rstd * (1.f + sc.y) + sh.y;
        float o2 = (v.z - mean) * rstd * (1.f + sc.z) + sh.z;
        float o3 = (v.w - mean) * rstd * (1.f + sc.w) + sh.w;
        __half2 h0, l0, h1, l1;
        split_h(o0, h0.x, l0.x); split_h(o1, h0.y, l0.y);
        split_h(o2, h1.x, l1.x); split_h(o3, h1.y, l1.y);
        *(__half2*)(oh + i) = h0;
        *(__half2*)(oh + i + 2) = h1;
        *(__half2*)(ol + i) = l0;
        *(__half2*)(ol + i + 2) = l1;
    }
}

// ---------------- RMSNorm + RoPE + fp16 hi/lo split (Q scaled) --------------
__global__ __launch_bounds__(128) void rmsrope_split(
        const float* __restrict__ QKV,
        const float* __restrict__ rc, const float* __restrict__ rs,
        const float* __restrict__ wq, const float* __restrict__ wk,
        __half* __restrict__ qh, __half* __restrict__ ql,
        __half* __restrict__ kh, __half* __restrict__ kl,
        __half* __restrict__ vh, __half* __restrict__ vl) {
    int s = blockIdx.x, hd = blockIdx.y;
    int d = threadIdx.x;
    int lane = d & 31, wid = d >> 5;
    __shared__ float red[4];
    float cosd = rc[s * HEAD_DIM + d];
    float sind = rs[s * HEAD_DIM + d];
    size_t gin = (size_t)s * QKV_N + hd * HEAD_DIM + d;
    size_t gout = (size_t)s * DIM + hd * HEAD_DIM + d;
    const float qscale = 0.08838834764831845f;
    // Q
    {
        float v = QKV[gin];
        float ss = v * v;
        for (int o = 16; o > 0; o >>= 1) ss += __shfl_xor_sync(0xffffffffu, ss, o);
        if (lane == 0) red[wid] = ss;
        __syncthreads();
        float tot = red[0] + red[1] + red[2] + red[3];
        float xn = v * rsqrtf(tot * (1.f / HEAD_DIM) + 1e-6f) * wq[d];
        float part = __shfl_xor_sync(0xffffffffu, xn, 1);
        float rot = (d & 1) ? part : -part;
        float q = (xn * cosd + rot * sind) * qscale;
        __half h, l;
        split_h(q, h, l);
        qh[gout] = h; ql[gout] = l;
        __syncthreads();
    }
    // K
    {
        float v = QKV[gin + DIM];
        float ss = v * v;
        for (int o = 16; o > 0; o >>= 1) ss += __shfl_xor_sync(0xffffffffu, ss, o);
        if (lane == 0) red[wid] = ss;
        __syncthreads();
        float tot = red[0] + red[1] + red[2] + red[3];
        float xn = v * rsqrtf(tot * (1.f / HEAD_DIM) + 1e-6f) * wk[d];
        float part = __shfl_xor_sync(0xffffffffu, xn, 1);
        float rot = (d & 1) ? part : -part;
        float k = xn * cosd + rot * sind;
        __half h, l;
        split_h(k, h, l);
        kh[gout] = h; kl[gout] = l;
    }
    // V (plain split)
    {
        float v = QKV[gin + 2 * DIM];
        __half h, l;
        split_h(v, h, l);
        vh[gout] = h; vl[gout] = l;
    }
}

// ---------------- HMMA flash attention ----------------
// block: 1 head x 128 q rows, 256 threads (8 warps x 16 rows each)
// K/V tiles of 64 keys, 2-stage cp.async pipeline; Q resident in smem.
// 3-pass hi/lo on both QK^T and P*V. Output split fp16 hi/lo -> cat[:, :DIM].
#define AT_PITCH 272                    // 256B data + 16B pad per dim-row
#define QMAT (128 * AT_PITCH)           // 34816
#define KVMAT (64 * AT_PITCH)           // 17408
#define KVSTG (4 * KVMAT)               // 69632
#define FLASH_SMEM (2 * QMAT + 2 * KVSTG)  // 208896

__device__ __forceinline__ void load_kv_stage(uint32_t dst,
        const __half* Kh, const __half* Kl, const __half* Vh, const __half* Vl,
        int key0, int hd, int tid) {
#pragma unroll
    for (int i = 0; i < 16; i++) {
        int idx = tid + i * 256;        // 0..4095
        int mat = idx >> 10;            // 0=Kh 1=Kl 2=Vh 3=Vl
        int rem = idx & 1023;
        int row = rem >> 4, c = rem & 15;
        const __half* src = (mat == 0) ? Kh : (mat == 1) ? Kl : (mat == 2) ? Vh : Vl;
        cpa16(dst + mat * KVMAT + row * AT_PITCH + c * 16,
              src + (size_t)(key0 + row) * DIM + hd * HEAD_DIM + c * 8);
    }
}

__global__ __launch_bounds__(256, 1) void flash_mma(
        const __half* __restrict__ Qh_, const __half* __restrict__ Ql_,
        const __half* __restrict__ Kh_, const __half* __restrict__ Kl_,
        const __half* __restrict__ Vh_, const __half* __restrict__ Vl_,
        __half* __restrict__ Ch, __half* __restrict__ Cl) {
    extern __shared__ char smem[];
    uint32_t sb = smem_u32(smem);
    const uint32_t qbase = sb;
    const uint32_t kvbase = sb + 2 * QMAT;
    int tid = threadIdx.x, warp = tid >> 5, lane = tid & 31;
    int hd = blockIdx.y;
    int q0 = blockIdx.x * 128;

    // prologue: Q (hi+lo) + KV stage 0 in group 0; KV stage 1 in group 1
#pragma unroll
    for (int i = 0; i < 16; i++) {
        int idx = tid + i * 256;        // 0..4095
        int mat = idx >> 11;            // 0=Qh 1=Ql
        int rem = idx & 2047;
        int row = rem >> 4, c = rem & 15;
        const __half* src = mat ? Ql_ : Qh_;
        cpa16(qbase + mat * QMAT + row * AT_PITCH + c * 16,
              src + (size_t)(q0 + row) * DIM + hd * HEAD_DIM + c * 8);
    }
    load_kv_stage(kvbase, Kh_, Kl_, Vh_, Vl_, 0, hd, tid);
    cpa_commit();
    load_kv_stage(kvbase + KVSTG, Kh_, Kl_, Vh_, Vl_, 64, hd, tid);
    cpa_commit();

    float out[16][4];
#pragma unroll
    for (int i = 0; i < 16; i++)
#pragma unroll
        for (int j = 0; j < 4; j++) out[i][j] = 0.f;
    float m0 = -1e30f, m1 = -1e30f, l0 = 0.f, l1 = 0.f;

    uint32_t a_off = (uint32_t)(warp * 16 + (lane & 15)) * AT_PITCH + ((lane >> 4) * 8) * 2;
    uint32_t kb_off = (uint32_t)(((lane >> 4) & 1) * 8 + (lane & 7)) * AT_PITCH
                    + (((lane >> 3) & 1) * 8) * 2;
    uint32_t v_off = (uint32_t)(((lane >> 3) & 1) * 8 + (lane & 7)) * AT_PITCH
                   + ((lane >> 4) * 8) * 2;

    const int iters = S_LEN / 64;   // 32
    for (int it = 0; it < iters; ++it) {
        int s = it & 1;
        if (it + 1 < iters) cpa_wait<1>(); else cpa_wait<0>();
        __syncthreads();

        uint32_t khb = kvbase + s * KVSTG;
        uint32_t vhb = khb + 2 * KVMAT;

        // ---- QK^T: scores C[8 keytiles][4] ----
        float C[8][4];
#pragma unroll
        for (int i = 0; i < 8; i++)
#pragma unroll
            for (int j = 0; j < 4; j++) C[i][j] = 0.f;

#pragma unroll
        for (int kt = 0; kt < 8; kt++) {
            uint32_t qa = qbase + a_off + kt * 32;
            uint32_t qh[4], ql[4];
            ldsm_x4(qh, qa);
            ldsm_x4(ql, qa + QMAT);
#pragma unroll
            for (int kb = 0; kb < 4; kb++) {
                uint32_t bh[4], bl[4];
                uint32_t ka = khb + kb_off + (uint32_t)kb * 16 * AT_PITCH + kt * 32;
                ldsm_x4(bh, ka);
                ldsm_x4(bl, ka + KVMAT);
                mma16816(C[2 * kb], qh, bh);
                mma16816(C[2 * kb], ql, bh);
                mma16816(C[2 * kb], qh, bl);
                mma16816(C[2 * kb + 1], qh, bh + 2);
                mma16816(C[2 * kb + 1], ql, bh + 2);
                mma16816(C[2 * kb + 1], qh, bl + 2);
            }
        }

        // ---- online softmax ----
        float t0 = -1e30f, t1 = -1e30f;
#pragma unroll
        for (int nt = 0; nt < 8; nt++) {
            t0 = fmaxf(t0, fmaxf(C[nt][0], C[nt][1]));
            t1 = fmaxf(t1, fmaxf(C[nt][2], C[nt][3]));
        }
        t0 = fmaxf(t0, __shfl_xor_sync(0xffffffffu, t0, 1));
        t0 = fmaxf(t0, __shfl_xor_sync(0xffffffffu, t0, 2));
        t1 = fmaxf(t1, __shfl_xor_sync(0xffffffffu, t1, 1));
        t1 = fmaxf(t1, __shfl_xor_sync(0xffffffffu, t1, 2));
        float mn0 = fmaxf(m0, t0), mn1 = fmaxf(m1, t1);
        float c0 = __expf(m0 - mn0), c1 = __expf(m1 - mn1);
        m0 = mn0; m1 = mn1;
        l0 *= c0; l1 *= c1;
#pragma unroll
        for (int nt = 0; nt < 16; nt++) {
            out[nt][0] *= c0; out[nt][1] *= c0;
            out[nt][2] *= c1; out[nt][3] *= c1;
        }
#pragma unroll
        for (int nt = 0; nt < 8; nt++) {
            C[nt][0] = __expf(C[nt][0] - m0);
            C[nt][1] = __expf(C[nt][1] - m0);
            C[nt][2] = __expf(C[nt][2] - m1);
            C[nt][3] = __expf(C[nt][3] - m1);
            l0 += C[nt][0] + C[nt][1];
            l1 += C[nt][2] + C[nt][3];
        }

        // ---- P*V ----
#pragma unroll
        for (int ks = 0; ks < 4; ks++) {
            // pack P fragment (hi/lo) from score tiles 2ks, 2ks+1
            uint32_t ph[4], pl[4];
            {
                float p00 = C[2 * ks][0], p01 = C[2 * ks][1];
                float p10 = C[2 * ks][2], p11 = C[2 * ks][3];
                float p20 = C[2 * ks + 1][0], p21 = C[2 * ks + 1][1];
                float p30 = C[2 * ks + 1][2], p31 = C[2 * ks + 1][3];
                __half h, l;
                __half2 hh, ll;
                split_h(p00, hh.x, ll.x); split_h(p01, hh.y, ll.y);
                ph[0] = *(uint32_t*)&hh; pl[0] = *(uint32_t*)&ll;
                split_h(p10, hh.x, ll.x); split_h(p11, hh.y, ll.y);
                ph[1] = *(uint32_t*)&hh; pl[1] = *(uint32_t*)&ll;
                split_h(p20, hh.x, ll.x); split_h(p21, hh.y, ll.y);
                ph[2] = *(uint32_t*)&hh; pl[2] = *(uint32_t*)&ll;
                split_h(p30, hh.x, ll.x); split_h(p31, hh.y, ll.y);
                ph[3] = *(uint32_t*)&hh; pl[3] = *(uint32_t*)&ll;
                (void)h; (void)l;
            }
#pragma unroll
            for (int dp = 0; dp < 8; dp++) {
                uint32_t vh[4], vl[4];
                uint32_t va = vhb + v_off + (uint32_t)ks * 16 * AT_PITCH + dp * 32;
                ldsm_x4_t(vh, va);
                ldsm_x4_t(vl, va + KVMAT);
                mma16816(out[2 * dp], ph, vh);
                mma16816(out[2 * dp], pl, vh);
                mma16816(out[2 * dp], ph, vl);
                mma16816(out[2 * dp + 1], ph, vh + 2);
                mma16816(out[2 * dp + 1], pl, vh + 2);
                mma16816(out[2 * dp + 1], ph, vl + 2);
            }
        }

        __syncthreads();
        if (it + 2 < iters) {
            load_kv_stage(kvbase + s * KVSTG, Kh_, Kl_, Vh_, Vl_, (it + 2) * 64, hd, tid);
            cpa_commit();
        }
    }

    // ---- epilogue ----
    l0 += __shfl_xor_sync(0xffffffffu, l0, 1);
    l0 += __shfl_xor_sync(0xffffffffu, l0, 2);
    l1 += __shfl_xor_sync(0xffffffffu, l1, 1);
    l1 += __shfl_xor_sync(0xffffffffu, l1, 2);
    float i0 = 1.f / l0, i1 = 1.f / l1;
    int r0 = q0 + warp * 16 + (lane >> 2);
    int r1 = r0 + 8;
    int cb = hd * HEAD_DIM + (lane & 3) * 2;
#pragma unroll
    for (int nt = 0; nt < 16; nt++) {
        int col = cb + nt * 8;
        float v0 = out[nt][0] * i0, v1 = out[nt][1] * i0;
        float w0 = out[nt][2] * i1, w1 = out[nt][3] * i1;
        __half2 h, l;
        split_h(v0, h.x, l.x); split_h(v1, h.y, l.y);
        *(__half2*)(Ch + (size_t)r0 * CAT_K + col) = h;
        *(__half2*)(Cl + (size_t)r0 * CAT_K + col) = l;
        split_h(w0, h.x, l.x); split_h(w1, h.y, l.y);
        *(__half2*)(Ch + (size_t)r1 * CAT_K + col) = h;
        *(__half2*)(Cl + (size_t)r1 * CAT_K + col) = l;
    }
}

// ---------------- launch ----------------
extern "C" void kernel_launch(void* const* d_in, const int* in_sizes, int n_in,
                              void* d_out, int out_size) {
    const float* hidden = (const float*)d_in[0];
    const float* temb = (const float*)d_in[1];
    const float* rope_cos = (const float*)d_in[2];
    const float* rope_sin = (const float*)d_in[3];
    const float* norm_w = (const float*)d_in[4];
    const float* norm_b = (const float*)d_in[5];
    const float* mlp_w = (const float*)d_in[6];
    const float* mlp_b = (const float*)d_in[7];
    const float* q_w = (const float*)d_in[8];
    const float* q_b = (const float*)d_in[9];
    const float* k_w = (const float*)d_in[10];
    const float* k_b = (const float*)d_in[11];
    const float* v_w = (const float*)d_in[12];
    const float* v_b = (const float*)d_in[13];
    const float* rms_q_w = (const float*)d_in[14];
    const float* rms_k_w = (const float*)d_in[15];
    const float* out_w = (const float*)d_in[16];
    const float* out_b = (const float*)d_in[17];
    float* out = (float*)d_out;

    float *emb_p, *qkv_p, *bqkv_p;
    __half *nh_h, *nh_l, *wqkv, *wm, *wo, *cat_h, *cat_l;
    __half *qh, *ql, *kh, *kl, *vh, *vl;
    cudaGetSymbolAddress((void**)&emb_p, g_emb);
    cudaGetSymbolAddress((void**)&qkv_p, g_qkv);
    cudaGetSymbolAddress((void**)&bqkv_p, g_bqkv);
    cudaGetSymbolAddress((void**)&nh_h, g_nh_h);
    cudaGetSymbolAddress((void**)&nh_l, g_nh_l);
    cudaGetSymbolAddress((void**)&wqkv, g_wqkv);
    cudaGetSymbolAddress((void**)&wm, g_wm);
    cudaGetSymbolAddress((void**)&wo, g_wo);
    cudaGetSymbolAddress((void**)&cat_h, g_cat_h);
    cudaGetSymbolAddress((void**)&cat_l, g_cat_l);
    cudaGetSymbolAddress((void**)&qh, g_qh);
    cudaGetSymbolAddress((void**)&ql, g_ql);
    cudaGetSymbolAddress((void**)&kh, g_kh);
    cudaGetSymbolAddress((void**)&kl, g_kl);
    cudaGetSymbolAddress((void**)&vh, g_vh);
    cudaGetSymbolAddress((void**)&vl, g_vl);

    cudaFuncSetAttribute(gemm_mma<0>, cudaFuncAttributeMaxDynamicSharedMemorySize, GEMM_SMEM);
    cudaFuncSetAttribute(gemm_mma<1>, cudaFuncAttributeMaxDynamicSharedMemorySize, GEMM_SMEM);
    cudaFuncSetAttribute(gemm_mma<2>, cudaFuncAttributeMaxDynamicSharedMemorySize, GEMM_SMEM);
    cudaFuncSetAttribute(flash_mma, cudaFuncAttributeMaxDynamicSharedMemorySize, FLASH_SMEM);

    // 1. adaLN embedding (silu fused)
    emb_gemv<<<3 * DIM, 128>>>(temb, norm_w, norm_b, emb_p);
    // 2. weight conversions + qkv bias concat
    cvt_all<<<(unsigned)((CVT_TOTAL / 4 + 255) / 256), 256>>>(
        q_w, k_w, v_w, mlp_w, out_w, wqkv, wm, wo, q_b, k_b, v_b, bqkv_p);
    // 3. LayerNorm + modulate -> nh hi/lo
    ln_mod<<<S_LEN, 256>>>(hidden, emb_p, nh_h, nh_l);
    // 4. fused QKV GEMM (N=9216)   <-- ncu profiles this launch
    gemm_mma<0><<<(S_LEN / 128) * (QKV_N / 128), 512, GEMM_SMEM>>>(
        nh_h, nh_l, wqkv, S_LEN, DIM, DIM, DIM,
        bqkv_p, qkv_p, QKV_N, nullptr, nullptr, 0, 0, nullptr, nullptr);
    // 5. RMSNorm + RoPE + split to fp16 hi/lo (Q pre-scaled)
    rmsrope_split<<<dim3(S_LEN, HEADS), HEAD_DIM>>>(
        qkv_p, rope_cos, rope_sin, rms_q_w, rms_k_w, qh, ql, kh, kl, vh, vl);
    // 6. HMMA flash attention -> cat[:, :DIM] hi/lo
    flash_mma<<<dim3(S_LEN / 128, HEADS), 256, FLASH_SMEM>>>(
        qh, ql, kh, kl, vh, vl, cat_h, cat_l);
    // 7. MLP GEMM (+bias+gelu) -> cat[:, DIM:]
    gemm_mma<1><<<(S_LEN / 128) * (MLP_H / 128), 512, GEMM_SMEM>>>(
        nh_h, nh_l, wm, S_LEN, DIM, DIM, DIM,
        mlp_b, nullptr, 0, cat_h, cat_l, CAT_K, DIM, nullptr, nullptr);
    // 8. out-proj GEMM over K=15360 + gated residual -> d_out
    gemm_mma<2><<<(S_LEN / 128) * (DIM / 128), 512, GEMM_SMEM>>>(
        cat_h, cat_l, wo, S_LEN, CAT_K, CAT_K, CAT_K,
        out_b, out, DIM, nullptr, nullptr, 0, 0, hidden, emb_p + 2 * DIM);
}

// round 7
// speedup vs baseline: 11.4290x; 1.4370x over previous
#include <cuda_runtime.h>
#include <cuda_fp16.h>
#include <cstdint>
#include <math.h>

#define S_LEN 2048
#define DIM 3072
#define HEADS 24
#define HEAD_DIM 128
#define MLP_H 12288
#define CAT_K (DIM + MLP_H)   // 15360
#define QKV_N (3 * DIM)       // 9216

// ---------------- scratch (device globals; no runtime allocs allowed) -------
#define ALN __align__(128)
__device__ ALN float g_emb[3 * DIM];
__device__ ALN float g_qkv[S_LEN * QKV_N];
__device__ ALN float g_bqkv[QKV_N];
__device__ ALN __half g_nh[S_LEN * DIM];
__device__ ALN __half g_wqkv[QKV_N * DIM];
__device__ ALN __half g_wm[MLP_H * DIM];
__device__ ALN __half g_wo[DIM * CAT_K];
__device__ ALN __half g_cat[S_LEN * CAT_K];
__device__ ALN __half g_qh[S_LEN * DIM];
__device__ ALN __half g_ql[S_LEN * DIM];
__device__ ALN __half g_kh[S_LEN * DIM];
__device__ ALN __half g_kl[S_LEN * DIM];
__device__ ALN __half g_vh[S_LEN * DIM];
__device__ ALN __half g_vl[S_LEN * DIM];

// ---------------- PTX helpers ----------------
__device__ __forceinline__ uint32_t smem_u32(const void* p) {
    uint32_t a;
    asm("{ .reg .u64 t; cvta.to.shared.u64 t, %1; cvt.u32.u64 %0, t; }" : "=r"(a) : "l"(p));
    return a;
}
__device__ __forceinline__ void cpa16(uint32_t s, const void* g) {
    asm volatile("cp.async.cg.shared.global [%0], [%1], 16;" :: "r"(s), "l"(g));
}
__device__ __forceinline__ void cpa_commit() { asm volatile("cp.async.commit_group;" ::: "memory"); }
template <int N>
__device__ __forceinline__ void cpa_wait() { asm volatile("cp.async.wait_group %0;" :: "n"(N) : "memory"); }

__device__ __forceinline__ void ldsm_x4(uint32_t* r, uint32_t addr) {
    asm volatile("ldmatrix.sync.aligned.m8n8.x4.shared.b16 {%0,%1,%2,%3}, [%4];"
                 : "=r"(r[0]), "=r"(r[1]), "=r"(r[2]), "=r"(r[3]) : "r"(addr));
}
__device__ __forceinline__ void ldsm_x4_t(uint32_t* r, uint32_t addr) {
    asm volatile("ldmatrix.sync.aligned.m8n8.x4.trans.shared.b16 {%0,%1,%2,%3}, [%4];"
                 : "=r"(r[0]), "=r"(r[1]), "=r"(r[2]), "=r"(r[3]) : "r"(addr));
}
__device__ __forceinline__ void mma16816(float* d, const uint32_t* a, const uint32_t* b) {
    asm volatile(
        "mma.sync.aligned.m16n8k16.row.col.f32.f16.f16.f32 "
        "{%0,%1,%2,%3}, {%4,%5,%6,%7}, {%8,%9}, {%0,%1,%2,%3};"
        : "+f"(d[0]), "+f"(d[1]), "+f"(d[2]), "+f"(d[3])
        : "r"(a[0]), "r"(a[1]), "r"(a[2]), "r"(a[3]), "r"(b[0]), "r"(b[1]));
}

__device__ __forceinline__ float geluf(float x) {
    float inner = 0.7978845608028654f * (x + 0.044715f * x * x * x);
    return 0.5f * x * (1.f + tanhf(inner));
}
__device__ __forceinline__ void split_h(float v, __half& h, __half& l) {
    h = __float2half_rn(v);
    l = __float2half_rn(v - __half2float(h));
}

// ---------------- mma.sync fp16 single-pass GEMM (512 thr, BK=64, 4-stage) --
#define BK 64
#define PITCHB 144
#define MAT_BYTES (128 * PITCHB)          // 18432
#define STAGE_BYTES (2 * MAT_BYTES)       // A, B = 36864
#define NSTG 4
#define GEMM_SMEM (NSTG * STAGE_BYTES)    // 147456

__device__ __forceinline__ void load_mat(uint32_t dst, const __half* g, int ld,
                                         int row0, int k0, int tid) {
    const __half* gp = g + (size_t)row0 * ld + k0;
#pragma unroll
    for (int i = 0; i < 2; i++) {
        int idx = tid + i * 512;
        int row = idx >> 3;
        int c = idx & 7;
        cpa16(dst + row * PITCHB + c * 16, gp + (size_t)row * ld + c * 8);
    }
}

template <int MODE>
__global__ __launch_bounds__(512, 1)
void gemm_mma(const __half* __restrict__ Ah,
              const __half* __restrict__ Bh,
              int Mtot, int Ktot, int lda, int ldb,
              const float* __restrict__ bias,
              float* __restrict__ Cf, int ldc,
              __half* __restrict__ Ch, int ldch, int ccol0,
              const float* __restrict__ hidden, const float* __restrict__ gate) {
    extern __shared__ char smem[];
    uint32_t sb = smem_u32(smem);
    int tid = threadIdx.x;
    int warp = tid >> 5, lane = tid & 31;
    int wm = warp & 3;
    int wn = warp >> 2;

    int mtiles = Mtot >> 7;
    int bm0 = (blockIdx.x % mtiles) << 7;
    int bn0 = (blockIdx.x / mtiles) << 7;

    float acc[2][4][4];
#pragma unroll
    for (int i = 0; i < 2; i++)
#pragma unroll
        for (int j = 0; j < 4; j++)
#pragma unroll
            for (int c = 0; c < 4; c++) acc[i][j][c] = 0.f;

    const int iters = Ktot / BK;

    // prologue: stages 0..2
#pragma unroll
    for (int s = 0; s < 3; s++) {
        uint32_t st = sb + s * STAGE_BYTES;
        load_mat(st, Ah, lda, bm0, s * BK, tid);
        load_mat(st + MAT_BYTES, Bh, ldb, bn0, s * BK, tid);
        cpa_commit();
    }

    uint32_t a_off = (uint32_t)(wm * 32 + (lane & 15)) * PITCHB + ((lane >> 4) * 8) * 2;
    uint32_t b_off = (uint32_t)(wn * 32 + ((lane >> 4) & 1) * 8 + (lane & 7)) * PITCHB
                   + (((lane >> 3) & 1) * 8) * 2;

    for (int it = 0; it < iters; ++it) {
        int s = it % NSTG;
        if (it + 1 < iters) cpa_wait<2>(); else cpa_wait<0>();
        __syncthreads();

        if (it + 3 < iters) {
            int s2 = (it + 3) % NSTG;
            uint32_t st = sb + s2 * STAGE_BYTES;
            int k0 = (it + 3) * BK;
            load_mat(st, Ah, lda, bm0, k0, tid);
            load_mat(st + MAT_BYTES, Bh, ldb, bn0, k0, tid);
            cpa_commit();
        }

        uint32_t stg = sb + s * STAGE_BYTES;
#pragma unroll
        for (int kk = 0; kk < 4; kk++) {
            uint32_t kb = kk * 32;
            uint32_t ah[2][4], bh[2][4];
#pragma unroll
            for (int mi = 0; mi < 2; mi++) {
                ldsm_x4(ah[mi], stg + a_off + (uint32_t)mi * 16 * PITCHB + kb);
            }
#pragma unroll
            for (int p = 0; p < 2; p++) {
                ldsm_x4(bh[p], stg + MAT_BYTES + b_off + (uint32_t)p * 16 * PITCHB + kb);
            }
#pragma unroll
            for (int mi = 0; mi < 2; mi++) {
#pragma unroll
                for (int ni = 0; ni < 4; ni++) {
                    mma16816(acc[mi][ni], ah[mi], &bh[ni >> 1][(ni & 1) * 2]);
                }
            }
        }
    }

    int rq = lane >> 2;
    int cq = (lane & 3) * 2;
#pragma unroll
    for (int mi = 0; mi < 2; mi++) {
#pragma unroll
        for (int ni = 0; ni < 4; ni++) {
            int n = bn0 + wn * 32 + ni * 8 + cq;
#pragma unroll
            for (int half = 0; half < 2; half++) {
                size_t m = (size_t)bm0 + wm * 32 + mi * 16 + rq + half * 8;
                float v0 = acc[mi][ni][half * 2 + 0];
                float v1 = acc[mi][ni][half * 2 + 1];
                if (MODE == 0) {
                    float2 o = make_float2(v0 + bias[n], v1 + bias[n + 1]);
                    *(float2*)(Cf + m * ldc + n) = o;
                } else if (MODE == 1) {
                    float g0 = geluf(v0 + bias[n]);
                    float g1 = geluf(v1 + bias[n + 1]);
                    *(__half2*)(Ch + m * ldch + ccol0 + n) = __floats2half2_rn(g0, g1);
                } else {
                    const float* hp = hidden + m * ldc + n;
                    float2 hv = *(const float2*)hp;
                    float2 o;
                    o.x = hv.x + gate[n] * (v0 + bias[n]);
                    o.y = hv.y + gate[n + 1] * (v1 + bias[n + 1]);
                    *(float2*)(Cf + m * ldc + n) = o;
                }
            }
        }
    }
}

// ---------------- fused weight conversion + qkv bias concat ----------------
#define QW_N ((long)DIM * DIM)
#define CVT_TOTAL (3 * QW_N + (long)MLP_H * DIM + (long)DIM * CAT_K)

__global__ void cvt_all(const float* __restrict__ q_w, const float* __restrict__ k_w,
                        const float* __restrict__ v_w, const float* __restrict__ mlp_w,
                        const float* __restrict__ out_w,
                        __half* __restrict__ wqkv, __half* __restrict__ wm,
                        __half* __restrict__ wo,
                        const float* __restrict__ q_b, const float* __restrict__ k_b,
                        const float* __restrict__ v_b, float* __restrict__ bqkv) {
    long t = (long)blockIdx.x * blockDim.x + threadIdx.x;
    if (t < 3 * DIM / 4) {
        int i = (int)t * 4;
        const float* src = i < DIM ? q_b : (i < 2 * DIM ? k_b : v_b);
        *(float4*)(bqkv + i) = *(const float4*)(src + (i % DIM));
    }
    long i = t * 4;
    if (i >= CVT_TOTAL) return;
    const float* src;
    __half* dh;
    long off;
    if (i < QW_N) { src = q_w; off = i; dh = wqkv; }
    else if (i < 2 * QW_N) { src = k_w; off = i - QW_N; dh = wqkv + QW_N; }
    else if (i < 3 * QW_N) { src = v_w; off = i - 2 * QW_N; dh = wqkv + 2 * QW_N; }
    else if (i < 3 * QW_N + (long)MLP_H * DIM) { src = mlp_w; off = i - 3 * QW_N; dh = wm; }
    else { src = out_w; off = i - 3 * QW_N - (long)MLP_H * DIM; dh = wo; }
    float4 v = *(const float4*)(src + off);
    *(__half2*)(dh + off) = __floats2half2_rn(v.x, v.y);
    *(__half2*)(dh + off + 2) = __floats2half2_rn(v.z, v.w);
}

// ---------------- adaLN embedding GEMV with fused silu ----------------
__global__ __launch_bounds__(128) void emb_gemv(const float* __restrict__ temb,
                                                const float* __restrict__ w,
                                                const float* __restrict__ b,
                                                float* __restrict__ emb) {
    int jrow = blockIdx.x;
    const float* wr = w + (size_t)jrow * DIM;
    int tid = threadIdx.x;
    float s = 0.f;
    for (int i = tid * 4; i < DIM; i += 512) {
        float4 a = *(const float4*)(temb + i);
        float4 ww = *(const float4*)(wr + i);
        a.x = a.x / (1.f + __expf(-a.x));
        a.y = a.y / (1.f + __expf(-a.y));
        a.z = a.z / (1.f + __expf(-a.z));
        a.w = a.w / (1.f + __expf(-a.w));
        s += a.x * ww.x + a.y * ww.y + a.z * ww.z + a.w * ww.w;
    }
    for (int o = 16; o > 0; o >>= 1) s += __shfl_xor_sync(0xffffffffu, s, o);
    __shared__ float sm[4];
    if ((tid & 31) == 0) sm[tid >> 5] = s;
    __syncthreads();
    if (tid == 0) emb[jrow] = sm[0] + sm[1] + sm[2] + sm[3] + b[jrow];
}

// LayerNorm + adaLN modulate -> single fp16
__global__ __launch_bounds__(256) void ln_mod(const float* __restrict__ x,
                                              const float* __restrict__ emb,
                                              __half* __restrict__ nh) {
    int srow = blockIdx.x;
    int tid = threadIdx.x;
    const float* row = x + (size_t)srow * DIM;
    float sum = 0.f, sq = 0.f;
    for (int i = tid * 4; i < DIM; i += 1024) {
        float4 v = *(const float4*)(row + i);
        sum += v.x + v.y + v.z + v.w;
        sq += v.x * v.x + v.y * v.y + v.z * v.z + v.w * v.w;
    }
    for (int o = 16; o > 0; o >>= 1) {
        sum += __shfl_xor_sync(0xffffffffu, sum, o);
        sq += __shfl_xor_sync(0xffffffffu, sq, o);
    }
    __shared__ float s1[8], s2[8];
    if ((tid & 31) == 0) { s1[tid >> 5] = sum; s2[tid >> 5] = sq; }
    __syncthreads();
    sum = 0.f; sq = 0.f;
#pragma unroll
    for (int w = 0; w < 8; w++) { sum += s1[w]; sq += s2[w]; }
    float mean = sum * (1.f / DIM);
    float var = sq * (1.f / DIM) - mean * mean;
    float rstd = rsqrtf(var + 1e-6f);
    __half* oh = nh + (size_t)srow * DIM;
    for (int i = tid * 4; i < DIM; i += 1024) {
        float4 v = *(const float4*)(row + i);
        float4 sc = *(const float4*)(emb + DIM + i);
        float4 sh = *(const float4*)(emb + i);
        float o0 = (v.x - mean) * rstd * (1.f + sc.x) + sh.x;
        float o1 = (v.y - mean) * rstd * (1.f + sc.y) + sh.y;
        float o2 = (v.z - mean) * rstd * (1.f + sc.z) + sh.z;
        float o3 = (v.w - mean) * rstd * (1.f + sc.w) + sh.w;
        *(__half2*)(oh + i) = __floats2half2_rn(o0, o1);
        *(__half2*)(oh + i + 2) = __floats2half2_rn(o2, o3);
    }
}

// ---------------- RMSNorm + RoPE + fp16 hi/lo split (Q scaled) --------------
__global__ __launch_bounds__(128) void rmsrope_split(
        const float* __restrict__ QKV,
        const float* __restrict__ rc, const float* __restrict__ rs,
        const float* __restrict__ wq, const float* __restrict__ wk,
        __half* __restrict__ qh, __half* __restrict__ ql,
        __half* __restrict__ kh, __half* __restrict__ kl,
        __half* __restrict__ vh, __half* __restrict__ vl) {
    int s = blockIdx.x, hd = blockIdx.y;
    int d = threadIdx.x;
    int lane = d & 31, wid = d >> 5;
    __shared__ float red[4];
    float cosd = rc[s * HEAD_DIM + d];
    float sind = rs[s * HEAD_DIM + d];
    size_t gin = (size_t)s * QKV_N + hd * HEAD_DIM + d;
    size_t gout = (size_t)s * DIM + hd * HEAD_DIM + d;
    const float qscale = 0.08838834764831845f;
    {
        float v = QKV[gin];
        float ss = v * v;
        for (int o = 16; o > 0; o >>= 1) ss += __shfl_xor_sync(0xffffffffu, ss, o);
        if (lane == 0) red[wid] = ss;
        __syncthreads();
        float tot = red[0] + red[1] + red[2] + red[3];
        float xn = v * rsqrtf(tot * (1.f / HEAD_DIM) + 1e-6f) * wq[d];
        float part = __shfl_xor_sync(0xffffffffu, xn, 1);
        float rot = (d & 1) ? part : -part;
        float q = (xn * cosd + rot * sind) * qscale;
        __half h, l;
        split_h(q, h, l);
        qh[gout] = h; ql[gout] = l;
        __syncthreads();
    }
    {
        float v = QKV[gin + DIM];
        float ss = v * v;
        for (int o = 16; o > 0; o >>= 1) ss += __shfl_xor_sync(0xffffffffu, ss, o);
        if (lane == 0) red[wid] = ss;
        __syncthreads();
        float tot = red[0] + red[1] + red[2] + red[3];
        float xn = v * rsqrtf(tot * (1.f / HEAD_DIM) + 1e-6f) * wk[d];
        float part = __shfl_xor_sync(0xffffffffu, xn, 1);
        float rot = (d & 1) ? part : -part;
        float k = xn * cosd + rot * sind;
        __half h, l;
        split_h(k, h, l);
        kh[gout] = h; kl[gout] = l;
    }
    {
        float v = QKV[gin + 2 * DIM];
        __half h, l;
        split_h(v, h, l);
        vh[gout] = h; vl[gout] = l;
    }
}

// ---------------- HMMA flash attention ----------------
#define AT_PITCH 272
#define QMAT (128 * AT_PITCH)
#define KVMAT (64 * AT_PITCH)
#define KVSTG (4 * KVMAT)
#define FLASH_SMEM (2 * QMAT + 2 * KVSTG)  // 208896

__device__ __forceinline__ void load_kv_stage(uint32_t dst,
        const __half* Kh, const __half* Kl, const __half* Vh, const __half* Vl,
        int key0, int hd, int tid) {
#pragma unroll
    for (int i = 0; i < 16; i++) {
        int idx = tid + i * 256;
        int mat = idx >> 10;
        int rem = idx & 1023;
        int row = rem >> 4, c = rem & 15;
        const __half* src = (mat == 0) ? Kh : (mat == 1) ? Kl : (mat == 2) ? Vh : Vl;
        cpa16(dst + mat * KVMAT + row * AT_PITCH + c * 16,
              src + (size_t)(key0 + row) * DIM + hd * HEAD_DIM + c * 8);
    }
}

__global__ __launch_bounds__(256, 1) void flash_mma(
        const __half* __restrict__ Qh_, const __half* __restrict__ Ql_,
        const __half* __restrict__ Kh_, const __half* __restrict__ Kl_,
        const __half* __restrict__ Vh_, const __half* __restrict__ Vl_,
        __half* __restrict__ Ch) {
    extern __shared__ char smem[];
    uint32_t sb = smem_u32(smem);
    const uint32_t qbase = sb;
    const uint32_t kvbase = sb + 2 * QMAT;
    int tid = threadIdx.x, warp = tid >> 5, lane = tid & 31;
    int hd = blockIdx.y;
    int q0 = blockIdx.x * 128;

#pragma unroll
    for (int i = 0; i < 16; i++) {
        int idx = tid + i * 256;
        int mat = idx >> 11;
        int rem = idx & 2047;
        int row = rem >> 4, c = rem & 15;
        const __half* src = mat ? Ql_ : Qh_;
        cpa16(qbase + mat * QMAT + row * AT_PITCH + c * 16,
              src + (size_t)(q0 + row) * DIM + hd * HEAD_DIM + c * 8);
    }
    load_kv_stage(kvbase, Kh_, Kl_, Vh_, Vl_, 0, hd, tid);
    cpa_commit();
    load_kv_stage(kvbase + KVSTG, Kh_, Kl_, Vh_, Vl_, 64, hd, tid);
    cpa_commit();

    float out[16][4];
#pragma unroll
    for (int i = 0; i < 16; i++)
#pragma unroll
        for (int j = 0; j < 4; j++) out[i][j] = 0.f;
    float m0 = -1e30f, m1 = -1e30f, l0 = 0.f, l1 = 0.f;

    uint32_t a_off = (uint32_t)(warp * 16 + (lane & 15)) * AT_PITCH + ((lane >> 4) * 8) * 2;
    uint32_t kb_off = (uint32_t)(((lane >> 4) & 1) * 8 + (lane & 7)) * AT_PITCH
                    + (((lane >> 3) & 1) * 8) * 2;
    uint32_t v_off = (uint32_t)(((lane >> 3) & 1) * 8 + (lane & 7)) * AT_PITCH
                   + ((lane >> 4) * 8) * 2;

    const int iters = S_LEN / 64;
    for (int it = 0; it < iters; ++it) {
        int s = it & 1;
        if (it + 1 < iters) cpa_wait<1>(); else cpa_wait<0>();
        __syncthreads();

        uint32_t khb = kvbase + s * KVSTG;
        uint32_t vhb = khb + 2 * KVMAT;

        float C[8][4];
#pragma unroll
        for (int i = 0; i < 8; i++)
#pragma unroll
            for (int j = 0; j < 4; j++) C[i][j] = 0.f;

#pragma unroll
        for (int kt = 0; kt < 8; kt++) {
            uint32_t qa = qbase + a_off + kt * 32;
            uint32_t qh[4], ql[4];
            ldsm_x4(qh, qa);
            ldsm_x4(ql, qa + QMAT);
#pragma unroll
            for (int kb = 0; kb < 4; kb++) {
                uint32_t bh[4], bl[4];
                uint32_t ka = khb + kb_off + (uint32_t)kb * 16 * AT_PITCH + kt * 32;
                ldsm_x4(bh, ka);
                ldsm_x4(bl, ka + KVMAT);
                mma16816(C[2 * kb], qh, bh);
                mma16816(C[2 * kb], ql, bh);
                mma16816(C[2 * kb], qh, bl);
                mma16816(C[2 * kb + 1], qh, bh + 2);
                mma16816(C[2 * kb + 1], ql, bh + 2);
                mma16816(C[2 * kb + 1], qh, bl + 2);
            }
        }

        float t0 = -1e30f, t1 = -1e30f;
#pragma unroll
        for (int nt = 0; nt < 8; nt++) {
            t0 = fmaxf(t0, fmaxf(C[nt][0], C[nt][1]));
            t1 = fmaxf(t1, fmaxf(C[nt][2], C[nt][3]));
        }
        t0 = fmaxf(t0, __shfl_xor_sync(0xffffffffu, t0, 1));
        t0 = fmaxf(t0, __shfl_xor_sync(0xffffffffu, t0, 2));
        t1 = fmaxf(t1, __shfl_xor_sync(0xffffffffu, t1, 1));
        t1 = fmaxf(t1, __shfl_xor_sync(0xffffffffu, t1, 2));
        float mn0 = fmaxf(m0, t0), mn1 = fmaxf(m1, t1);
        float c0 = __expf(m0 - mn0), c1 = __expf(m1 - mn1);
        m0 = mn0; m1 = mn1;
        l0 *= c0; l1 *= c1;
#pragma unroll
        for (int nt = 0; nt < 16; nt++) {
            out[nt][0] *= c0; out[nt][1] *= c0;
            out[nt][2] *= c1; out[nt][3] *= c1;
        }
#pragma unroll
        for (int nt = 0; nt < 8; nt++) {
            C[nt][0] = __expf(C[nt][0] - m0);
            C[nt][1] = __expf(C[nt][1] - m0);
            C[nt][2] = __expf(C[nt][2] - m1);
            C[nt][3] = __expf(C[nt][3] - m1);
            l0 += C[nt][0] + C[nt][1];
            l1 += C[nt][2] + C[nt][3];
        }

#pragma unroll
        for (int ks = 0; ks < 4; ks++) {
            uint32_t ph[4], pl[4];
            {
                __half2 hh, ll;
                split_h(C[2 * ks][0], hh.x, ll.x); split_h(C[2 * ks][1], hh.y, ll.y);
                ph[0] = *(uint32_t*)&hh; pl[0] = *(uint32_t*)&ll;
                split_h(C[2 * ks][2], hh.x, ll.x); split_h(C[2 * ks][3], hh.y, ll.y);
                ph[1] = *(uint32_t*)&hh; pl[1] = *(uint32_t*)&ll;
                split_h(C[2 * ks + 1][0], hh.x, ll.x); split_h(C[2 * ks + 1][1], hh.y, ll.y);
                ph[2] = *(uint32_t*)&hh; pl[2] = *(uint32_t*)&ll;
                split_h(C[2 * ks + 1][2], hh.x, ll.x); split_h(C[2 * ks + 1][3], hh.y, ll.y);
                ph[3] = *(uint32_t*)&hh; pl[3] = *(uint32_t*)&ll;
            }
#pragma unroll
            for (int dp = 0; dp < 8; dp++) {
                uint32_t vh[4], vl[4];
                uint32_t va = vhb + v_off + (uint32_t)ks * 16 * AT_PITCH + dp * 32;
                ldsm_x4_t(vh, va);
                ldsm_x4_t(vl, va + KVMAT);
                mma16816(out[2 * dp], ph, vh);
                mma16816(out[2 * dp], pl, vh);
                mma16816(out[2 * dp], ph, vl);
                mma16816(out[2 * dp + 1], ph, vh + 2);
                mma16816(out[2 * dp + 1], pl, vh + 2);
                mma16816(out[2 * dp + 1], ph, vl + 2);
            }
        }

        __syncthreads();
        if (it + 2 < iters) {
            load_kv_stage(kvbase + s * KVSTG, Kh_, Kl_, Vh_, Vl_, (it + 2) * 64, hd, tid);
            cpa_commit();
        }
    }

    l0 += __shfl_xor_sync(0xffffffffu, l0, 1);
    l0 += __shfl_xor_sync(0xffffffffu, l0, 2);
    l1 += __shfl_xor_sync(0xffffffffu, l1, 1);
    l1 += __shfl_xor_sync(0xffffffffu, l1, 2);
    float i0 = 1.f / l0, i1 = 1.f / l1;
    int r0 = q0 + warp * 16 + (lane >> 2);
    int r1 = r0 + 8;
    int cb = hd * HEAD_DIM + (lane & 3) * 2;
#pragma unroll
    for (int nt = 0; nt < 16; nt++) {
        int col = cb + nt * 8;
        *(__half2*)(Ch + (size_t)r0 * CAT_K + col) =
            __floats2half2_rn(out[nt][0] * i0, out[nt][1] * i0);
        *(__half2*)(Ch + (size_t)r1 * CAT_K + col) =
            __floats2half2_rn(out[nt][2] * i1, out[nt][3] * i1);
    }
}

// ---------------- launch ----------------
extern "C" void kernel_launch(void* const* d_in, const int* in_sizes, int n_in,
                              void* d_out, int out_size) {
    const float* hidden = (const float*)d_in[0];
    const float* temb = (const float*)d_in[1];
    const float* rope_cos = (const float*)d_in[2];
    const float* rope_sin = (const float*)d_in[3];
    const float* norm_w = (const float*)d_in[4];
    const float* norm_b = (const float*)d_in[5];
    const float* mlp_w = (const float*)d_in[6];
    const float* mlp_b = (const float*)d_in[7];
    const float* q_w = (const float*)d_in[8];
    const float* q_b = (const float*)d_in[9];
    const float* k_w = (const float*)d_in[10];
    const float* k_b = (const float*)d_in[11];
    const float* v_w = (const float*)d_in[12];
    const float* v_b = (const float*)d_in[13];
    const float* rms_q_w = (const float*)d_in[14];
    const float* rms_k_w = (const float*)d_in[15];
    const float* out_w = (const float*)d_in[16];
    const float* out_b = (const float*)d_in[17];
    float* out = (float*)d_out;

    float *emb_p, *qkv_p, *bqkv_p;
    __half *nh, *wqkv, *wm, *wo, *cat;
    __half *qh, *ql, *kh, *kl, *vh, *vl;
    cudaGetSymbolAddress((void**)&emb_p, g_emb);
    cudaGetSymbolAddress((void**)&qkv_p, g_qkv);
    cudaGetSymbolAddress((void**)&bqkv_p, g_bqkv);
    cudaGetSymbolAddress((void**)&nh, g_nh);
    cudaGetSymbolAddress((void**)&wqkv, g_wqkv);
    cudaGetSymbolAddress((void**)&wm, g_wm);
    cudaGetSymbolAddress((void**)&wo, g_wo);
    cudaGetSymbolAddress((void**)&cat, g_cat);
    cudaGetSymbolAddress((void**)&qh, g_qh);
    cudaGetSymbolAddress((void**)&ql, g_ql);
    cudaGetSymbolAddress((void**)&kh, g_kh);
    cudaGetSymbolAddress((void**)&kl, g_kl);
    cudaGetSymbolAddress((void**)&vh, g_vh);
    cudaGetSymbolAddress((void**)&vl, g_vl);

    cudaFuncSetAttribute(gemm_mma<0>, cudaFuncAttributeMaxDynamicSharedMemorySize, GEMM_SMEM);
    cudaFuncSetAttribute(gemm_mma<1>, cudaFuncAttributeMaxDynamicSharedMemorySize, GEMM_SMEM);
    cudaFuncSetAttribute(gemm_mma<2>, cudaFuncAttributeMaxDynamicSharedMemorySize, GEMM_SMEM);
    cudaFuncSetAttribute(flash_mma, cudaFuncAttributeMaxDynamicSharedMemorySize, FLASH_SMEM);

    // 1. adaLN embedding (silu fused)
    emb_gemv<<<3 * DIM, 128>>>(temb, norm_w, norm_b, emb_p);
    // 2. weight conversions + qkv bias concat
    cvt_all<<<(unsigned)((CVT_TOTAL / 4 + 255) / 256), 256>>>(
        q_w, k_w, v_w, mlp_w, out_w, wqkv, wm, wo, q_b, k_b, v_b, bqkv_p);
    // 3. LayerNorm + modulate -> nh fp16
    ln_mod<<<S_LEN, 256>>>(hidden, emb_p, nh);
    // 4. fused QKV GEMM (N=9216)   <-- ncu profiles this launch
    gemm_mma<0><<<(S_LEN / 128) * (QKV_N / 128), 512, GEMM_SMEM>>>(
        nh, wqkv, S_LEN, DIM, DIM, DIM,
        bqkv_p, qkv_p, QKV_N, nullptr, 0, 0, nullptr, nullptr);
    // 5. RMSNorm + RoPE + split to fp16 hi/lo (Q pre-scaled)
    rmsrope_split<<<dim3(S_LEN, HEADS), HEAD_DIM>>>(
        qkv_p, rope_cos, rope_sin, rms_q_w, rms_k_w, qh, ql, kh, kl, vh, vl);
    // 6. HMMA flash attention -> cat[:, :DIM]
    flash_mma<<<dim3(S_LEN / 128, HEADS), 256, FLASH_SMEM>>>(
        qh, ql, kh, kl, vh, vl, cat);
    // 7. MLP GEMM (+bias+gelu) -> cat[:, DIM:]
    gemm_mma<1><<<(S_LEN / 128) * (MLP_H / 128), 512, GEMM_SMEM>>>(
        nh, wm, S_LEN, DIM, DIM, DIM,
        mlp_b, nullptr, 0, cat, CAT_K, DIM, nullptr, nullptr);
    // 8. out-proj GEMM over K=15360 + gated residual -> d_out
    gemm_mma<2><<<(S_LEN / 128) * (DIM / 128), 512, GEMM_SMEM>>>(
        cat, wo, S_LEN, CAT_K, CAT_K, CAT_K,
        out_b, out, DIM, nullptr, 0, 0, hidden, emb_p + 2 * DIM);
}

// round 8
// speedup vs baseline: 12.0388x; 1.0534x over previous
#include <cuda_runtime.h>
#include <cuda_fp16.h>
#include <cstdint>
#include <math.h>

#define S_LEN 2048
#define DIM 3072
#define HEADS 24
#define HEAD_DIM 128
#define MLP_H 12288
#define CAT_K (DIM + MLP_H)   // 15360
#define QKV_N (3 * DIM)       // 9216

// ---------------- scratch (device globals; no runtime allocs allowed) -------
#define ALN __align__(128)
__device__ ALN float g_emb[3 * DIM];
__device__ ALN float g_qkv[S_LEN * QKV_N];
__device__ ALN float g_bqkv[QKV_N];
__device__ ALN __half g_nh[S_LEN * DIM];
__device__ ALN __half g_wqkv[QKV_N * DIM];
__device__ ALN __half g_wm[MLP_H * DIM];
__device__ ALN __half g_wo[DIM * CAT_K];
__device__ ALN __half g_cat[S_LEN * CAT_K];
__device__ ALN __half g_qh[S_LEN * DIM];
__device__ ALN __half g_ql[S_LEN * DIM];
__device__ ALN __half g_kh[S_LEN * DIM];
__device__ ALN __half g_kl[S_LEN * DIM];
__device__ ALN __half g_vh[S_LEN * DIM];
__device__ ALN __half g_vl[S_LEN * DIM];

// ---------------- PTX helpers ----------------
__device__ __forceinline__ uint32_t smem_u32(const void* p) {
    uint32_t a;
    asm("{ .reg .u64 t; cvta.to.shared.u64 t, %1; cvt.u32.u64 %0, t; }" : "=r"(a) : "l"(p));
    return a;
}
__device__ __forceinline__ void cpa16(uint32_t s, const void* g) {
    asm volatile("cp.async.cg.shared.global [%0], [%1], 16;" :: "r"(s), "l"(g));
}
__device__ __forceinline__ void cpa_commit() { asm volatile("cp.async.commit_group;" ::: "memory"); }
template <int N>
__device__ __forceinline__ void cpa_wait() { asm volatile("cp.async.wait_group %0;" :: "n"(N) : "memory"); }

__device__ __forceinline__ void ldsm_x4(uint32_t* r, uint32_t addr) {
    asm volatile("ldmatrix.sync.aligned.m8n8.x4.shared.b16 {%0,%1,%2,%3}, [%4];"
                 : "=r"(r[0]), "=r"(r[1]), "=r"(r[2]), "=r"(r[3]) : "r"(addr));
}
__device__ __forceinline__ void ldsm_x4_t(uint32_t* r, uint32_t addr) {
    asm volatile("ldmatrix.sync.aligned.m8n8.x4.trans.shared.b16 {%0,%1,%2,%3}, [%4];"
                 : "=r"(r[0]), "=r"(r[1]), "=r"(r[2]), "=r"(r[3]) : "r"(addr));
}
__device__ __forceinline__ void mma16816(float* d, const uint32_t* a, const uint32_t* b) {
    asm volatile(
        "mma.sync.aligned.m16n8k16.row.col.f32.f16.f16.f32 "
        "{%0,%1,%2,%3}, {%4,%5,%6,%7}, {%8,%9}, {%0,%1,%2,%3};"
        : "+f"(d[0]), "+f"(d[1]), "+f"(d[2]), "+f"(d[3])
        : "r"(a[0]), "r"(a[1]), "r"(a[2]), "r"(a[3]), "r"(b[0]), "r"(b[1]));
}

__device__ __forceinline__ float geluf(float x) {
    float inner = 0.7978845608028654f * (x + 0.044715f * x * x * x);
    return 0.5f * x * (1.f + tanhf(inner));
}
__device__ __forceinline__ void split_h(float v, __half& h, __half& l) {
    h = __float2half_rn(v);
    l = __float2half_rn(v - __half2float(h));
}

// ------- mma.sync fp16 GEMM: tile 128x256, 512 thr, warp tile 32x64 --------
#define BK 64
#define PITCHB 144
#define A_MAT (128 * PITCHB)              // 18432
#define B_MAT (256 * PITCHB)              // 36864
#define STAGE_BYTES (A_MAT + B_MAT)       // 55296
#define NSTG 3
#define GEMM_SMEM (NSTG * STAGE_BYTES)    // 165888

// A: 128 rows x 64 fp16 -> 1024 16B chunks, 2/thread
__device__ __forceinline__ void load_matA(uint32_t dst, const __half* g, int ld,
                                          int row0, int k0, int tid) {
    const __half* gp = g + (size_t)row0 * ld + k0;
#pragma unroll
    for (int i = 0; i < 2; i++) {
        int idx = tid + i * 512;
        int row = idx >> 3;
        int c = idx & 7;
        cpa16(dst + row * PITCHB + c * 16, gp + (size_t)row * ld + c * 8);
    }
}
// B: 256 rows x 64 fp16 -> 2048 16B chunks, 4/thread
__device__ __forceinline__ void load_matB(uint32_t dst, const __half* g, int ld,
                                          int row0, int k0, int tid) {
    const __half* gp = g + (size_t)row0 * ld + k0;
#pragma unroll
    for (int i = 0; i < 4; i++) {
        int idx = tid + i * 512;
        int row = idx >> 3;
        int c = idx & 7;
        cpa16(dst + row * PITCHB + c * 16, gp + (size_t)row * ld + c * 8);
    }
}

template <int MODE>
__global__ __launch_bounds__(512, 1)
void gemm_mma(const __half* __restrict__ Ah,
              const __half* __restrict__ Bh,
              int Mtot, int Ktot, int lda, int ldb,
              const float* __restrict__ bias,
              float* __restrict__ Cf, int ldc,
              __half* __restrict__ Ch, int ldch, int ccol0,
              const float* __restrict__ hidden, const float* __restrict__ gate) {
    extern __shared__ char smem[];
    uint32_t sb = smem_u32(smem);
    int tid = threadIdx.x;
    int warp = tid >> 5, lane = tid & 31;
    int wm = warp & 3;        // 0..3 -> 32-row group
    int wn = warp >> 2;       // 0..3 -> 64-col group

    int mtiles = Mtot >> 7;
    int bm0 = (blockIdx.x % mtiles) << 7;
    int bn0 = (blockIdx.x / mtiles) << 8;   // 256-wide N tiles

    float acc[2][8][4];
#pragma unroll
    for (int i = 0; i < 2; i++)
#pragma unroll
        for (int j = 0; j < 8; j++)
#pragma unroll
            for (int c = 0; c < 4; c++) acc[i][j][c] = 0.f;

    const int iters = Ktot / BK;

    // prologue: stages 0,1
#pragma unroll
    for (int s = 0; s < 2; s++) {
        uint32_t st = sb + s * STAGE_BYTES;
        load_matA(st, Ah, lda, bm0, s * BK, tid);
        load_matB(st + A_MAT, Bh, ldb, bn0, s * BK, tid);
        cpa_commit();
    }

    uint32_t a_off = (uint32_t)(wm * 32 + (lane & 15)) * PITCHB + ((lane >> 4) * 8) * 2;
    uint32_t b_off = (uint32_t)(wn * 64 + ((lane >> 4) & 1) * 8 + (lane & 7)) * PITCHB
                   + (((lane >> 3) & 1) * 8) * 2;

    for (int it = 0; it < iters; ++it) {
        int s = it % NSTG;
        if (it + 1 < iters) cpa_wait<1>(); else cpa_wait<0>();
        __syncthreads();

        if (it + 2 < iters) {
            int s2 = (it + 2) % NSTG;
            uint32_t st = sb + s2 * STAGE_BYTES;
            int k0 = (it + 2) * BK;
            load_matA(st, Ah, lda, bm0, k0, tid);
            load_matB(st + A_MAT, Bh, ldb, bn0, k0, tid);
            cpa_commit();
        }

        uint32_t stg = sb + s * STAGE_BYTES;
#pragma unroll
        for (int kk = 0; kk < 4; kk++) {
            uint32_t kb = kk * 32;
            uint32_t ah[2][4];
#pragma unroll
            for (int mi = 0; mi < 2; mi++)
                ldsm_x4(ah[mi], stg + a_off + (uint32_t)mi * 16 * PITCHB + kb);
#pragma unroll
            for (int p = 0; p < 4; p++) {
                uint32_t bh[4];
                ldsm_x4(bh, stg + A_MAT + b_off + (uint32_t)p * 16 * PITCHB + kb);
#pragma unroll
                for (int mi = 0; mi < 2; mi++) {
                    mma16816(acc[mi][2 * p + 0], ah[mi], bh + 0);
                    mma16816(acc[mi][2 * p + 1], ah[mi], bh + 2);
                }
            }
        }
    }

    int rq = lane >> 2;
    int cq = (lane & 3) * 2;
#pragma unroll
    for (int mi = 0; mi < 2; mi++) {
#pragma unroll
        for (int ni = 0; ni < 8; ni++) {
            int n = bn0 + wn * 64 + ni * 8 + cq;
#pragma unroll
            for (int half = 0; half < 2; half++) {
                size_t m = (size_t)bm0 + wm * 32 + mi * 16 + rq + half * 8;
                float v0 = acc[mi][ni][half * 2 + 0];
                float v1 = acc[mi][ni][half * 2 + 1];
                if (MODE == 0) {
                    float2 o = make_float2(v0 + bias[n], v1 + bias[n + 1]);
                    *(float2*)(Cf + m * ldc + n) = o;
                } else if (MODE == 1) {
                    float g0 = geluf(v0 + bias[n]);
                    float g1 = geluf(v1 + bias[n + 1]);
                    *(__half2*)(Ch + m * ldch + ccol0 + n) = __floats2half2_rn(g0, g1);
                } else {
                    const float* hp = hidden + m * ldc + n;
                    float2 hv = *(const float2*)hp;
                    float2 o;
                    o.x = hv.x + gate[n] * (v0 + bias[n]);
                    o.y = hv.y + gate[n + 1] * (v1 + bias[n + 1]);
                    *(float2*)(Cf + m * ldc + n) = o;
                }
            }
        }
    }
}

// ---------------- fused weight conversion + qkv bias concat ----------------
#define QW_N ((long)DIM * DIM)
#define CVT_TOTAL (3 * QW_N + (long)MLP_H * DIM + (long)DIM * CAT_K)

__global__ void cvt_all(const float* __restrict__ q_w, const float* __restrict__ k_w,
                        const float* __restrict__ v_w, const float* __restrict__ mlp_w,
                        const float* __restrict__ out_w,
                        __half* __restrict__ wqkv, __half* __restrict__ wm,
                        __half* __restrict__ wo,
                        const float* __restrict__ q_b, const float* __restrict__ k_b,
                        const float* __restrict__ v_b, float* __restrict__ bqkv) {
    long t = (long)blockIdx.x * blockDim.x + threadIdx.x;
    if (t < 3 * DIM / 4) {
        int i = (int)t * 4;
        const float* src = i < DIM ? q_b : (i < 2 * DIM ? k_b : v_b);
        *(float4*)(bqkv + i) = *(const float4*)(src + (i % DIM));
    }
    long i = t * 4;
    if (i >= CVT_TOTAL) return;
    const float* src;
    __half* dh;
    long off;
    if (i < QW_N) { src = q_w; off = i; dh = wqkv; }
    else if (i < 2 * QW_N) { src = k_w; off = i - QW_N; dh = wqkv + QW_N; }
    else if (i < 3 * QW_N) { src = v_w; off = i - 2 * QW_N; dh = wqkv + 2 * QW_N; }
    else if (i < 3 * QW_N + (long)MLP_H * DIM) { src = mlp_w; off = i - 3 * QW_N; dh = wm; }
    else { src = out_w; off = i - 3 * QW_N - (long)MLP_H * DIM; dh = wo; }
    float4 v = *(const float4*)(src + off);
    *(__half2*)(dh + off) = __floats2half2_rn(v.x, v.y);
    *(__half2*)(dh + off + 2) = __floats2half2_rn(v.z, v.w);
}

// ---------------- adaLN embedding GEMV with fused silu ----------------
__global__ __launch_bounds__(128) void emb_gemv(const float* __restrict__ temb,
                                                const float* __restrict__ w,
                                                const float* __restrict__ b,
                                                float* __restrict__ emb) {
    int jrow = blockIdx.x;
    const float* wr = w + (size_t)jrow * DIM;
    int tid = threadIdx.x;
    float s = 0.f;
    for (int i = tid * 4; i < DIM; i += 512) {
        float4 a = *(const float4*)(temb + i);
        float4 ww = *(const float4*)(wr + i);
        a.x = a.x / (1.f + __expf(-a.x));
        a.y = a.y / (1.f + __expf(-a.y));
        a.z = a.z / (1.f + __expf(-a.z));
        a.w = a.w / (1.f + __expf(-a.w));
        s += a.x * ww.x + a.y * ww.y + a.z * ww.z + a.w * ww.w;
    }
    for (int o = 16; o > 0; o >>= 1) s += __shfl_xor_sync(0xffffffffu, s, o);
    __shared__ float sm[4];
    if ((tid & 31) == 0) sm[tid >> 5] = s;
    __syncthreads();
    if (tid == 0) emb[jrow] = sm[0] + sm[1] + sm[2] + sm[3] + b[jrow];
}

// LayerNorm + adaLN modulate -> single fp16
__global__ __launch_bounds__(256) void ln_mod(const float* __restrict__ x,
                                              const float* __restrict__ emb,
                                              __half* __restrict__ nh) {
    int srow = blockIdx.x;
    int tid = threadIdx.x;
    const float* row = x + (size_t)srow * DIM;
    float sum = 0.f, sq = 0.f;
    for (int i = tid * 4; i < DIM; i += 1024) {
        float4 v = *(const float4*)(row + i);
        sum += v.x + v.y + v.z + v.w;
        sq += v.x * v.x + v.y * v.y + v.z * v.z + v.w * v.w;
    }
    for (int o = 16; o > 0; o >>= 1) {
        sum += __shfl_xor_sync(0xffffffffu, sum, o);
        sq += __shfl_xor_sync(0xffffffffu, sq, o);
    }
    __shared__ float s1[8], s2[8];
    if ((tid & 31) == 0) { s1[tid >> 5] = sum; s2[tid >> 5] = sq; }
    __syncthreads();
    sum = 0.f; sq = 0.f;
#pragma unroll
    for (int w = 0; w < 8; w++) { sum += s1[w]; sq += s2[w]; }
    float mean = sum * (1.f / DIM);
    float var = sq * (1.f / DIM) - mean * mean;
    float rstd = rsqrtf(var + 1e-6f);
    __half* oh = nh + (size_t)srow * DIM;
    for (int i = tid * 4; i < DIM; i += 1024) {
        float4 v = *(const float4*)(row + i);
        float4 sc = *(const float4*)(emb + DIM + i);
        float4 sh = *(const float4*)(emb + i);
        float o0 = (v.x - mean) * rstd * (1.f + sc.x) + sh.x;
        float o1 = (v.y - mean) * rstd * (1.f + sc.y) + sh.y;
        float o2 = (v.z - mean) * rstd * (1.f + sc.z) + sh.z;
        float o3 = (v.w - mean) * rstd * (1.f + sc.w) + sh.w;
        *(__half2*)(oh + i) = __floats2half2_rn(o0, o1);
        *(__half2*)(oh + i + 2) = __floats2half2_rn(o2, o3);
    }
}

// ---------------- RMSNorm + RoPE + fp16 hi/lo split (Q scaled) --------------
__global__ __launch_bounds__(128) void rmsrope_split(
        const float* __restrict__ QKV,
        const float* __restrict__ rc, const float* __restrict__ rs,
        const float* __restrict__ wq, const float* __restrict__ wk,
        __half* __restrict__ qh, __half* __restrict__ ql,
        __half* __restrict__ kh, __half* __restrict__ kl,
        __half* __restrict__ vh, __half* __restrict__ vl) {
    int s = blockIdx.x, hd = blockIdx.y;
    int d = threadIdx.x;
    int lane = d & 31, wid = d >> 5;
    __shared__ float red[4];
    float cosd = rc[s * HEAD_DIM + d];
    float sind = rs[s * HEAD_DIM + d];
    size_t gin = (size_t)s * QKV_N + hd * HEAD_DIM + d;
    size_t gout = (size_t)s * DIM + hd * HEAD_DIM + d;
    const float qscale = 0.08838834764831845f;
    {
        float v = QKV[gin];
        float ss = v * v;
        for (int o = 16; o > 0; o >>= 1) ss += __shfl_xor_sync(0xffffffffu, ss, o);
        if (lane == 0) red[wid] = ss;
        __syncthreads();
        float tot = red[0] + red[1] + red[2] + red[3];
        float xn = v * rsqrtf(tot * (1.f / HEAD_DIM) + 1e-6f) * wq[d];
        float part = __shfl_xor_sync(0xffffffffu, xn, 1);
        float rot = (d & 1) ? part : -part;
        float q = (xn * cosd + rot * sind) * qscale;
        __half h, l;
        split_h(q, h, l);
        qh[gout] = h; ql[gout] = l;
        __syncthreads();
    }
    {
        float v = QKV[gin + DIM];
        float ss = v * v;
        for (int o = 16; o > 0; o >>= 1) ss += __shfl_xor_sync(0xffffffffu, ss, o);
        if (lane == 0) red[wid] = ss;
        __syncthreads();
        float tot = red[0] + red[1] + red[2] + red[3];
        float xn = v * rsqrtf(tot * (1.f / HEAD_DIM) + 1e-6f) * wk[d];
        float part = __shfl_xor_sync(0xffffffffu, xn, 1);
        float rot = (d & 1) ? part : -part;
        float k = xn * cosd + rot * sind;
        __half h, l;
        split_h(k, h, l);
        kh[gout] = h; kl[gout] = l;
    }
    {
        float v = QKV[gin + 2 * DIM];
        __half h, l;
        split_h(v, h, l);
        vh[gout] = h; vl[gout] = l;
    }
}

// ---------------- HMMA flash attention ----------------
#define AT_PITCH 272
#define QMAT (128 * AT_PITCH)
#define KVMAT (64 * AT_PITCH)
#define KVSTG (4 * KVMAT)
#define FLASH_SMEM (2 * QMAT + 2 * KVSTG)  // 208896

__device__ __forceinline__ void load_kv_stage(uint32_t dst,
        const __half* Kh, const __half* Kl, const __half* Vh, const __half* Vl,
        int key0, int hd, int tid) {
#pragma unroll
    for (int i = 0; i < 16; i++) {
        int idx = tid + i * 256;
        int mat = idx >> 10;
        int rem = idx & 1023;
        int row = rem >> 4, c = rem & 15;
        const __half* src = (mat == 0) ? Kh : (mat == 1) ? Kl : (mat == 2) ? Vh : Vl;
        cpa16(dst + mat * KVMAT + row * AT_PITCH + c * 16,
              src + (size_t)(key0 + row) * DIM + hd * HEAD_DIM + c * 8);
    }
}

__global__ __launch_bounds__(256, 1) void flash_mma(
        const __half* __restrict__ Qh_, const __half* __restrict__ Ql_,
        const __half* __restrict__ Kh_, const __half* __restrict__ Kl_,
        const __half* __restrict__ Vh_, const __half* __restrict__ Vl_,
        __half* __restrict__ Ch) {
    extern __shared__ char smem[];
    uint32_t sb = smem_u32(smem);
    const uint32_t qbase = sb;
    const uint32_t kvbase = sb + 2 * QMAT;
    int tid = threadIdx.x, warp = tid >> 5, lane = tid & 31;
    int hd = blockIdx.y;
    int q0 = blockIdx.x * 128;

#pragma unroll
    for (int i = 0; i < 16; i++) {
        int idx = tid + i * 256;
        int mat = idx >> 11;
        int rem = idx & 2047;
        int row = rem >> 4, c = rem & 15;
        const __half* src = mat ? Ql_ : Qh_;
        cpa16(qbase + mat * QMAT + row * AT_PITCH + c * 16,
              src + (size_t)(q0 + row) * DIM + hd * HEAD_DIM + c * 8);
    }
    load_kv_stage(kvbase, Kh_, Kl_, Vh_, Vl_, 0, hd, tid);
    cpa_commit();
    load_kv_stage(kvbase + KVSTG, Kh_, Kl_, Vh_, Vl_, 64, hd, tid);
    cpa_commit();

    float out[16][4];
#pragma unroll
    for (int i = 0; i < 16; i++)
#pragma unroll
        for (int j = 0; j < 4; j++) out[i][j] = 0.f;
    float m0 = -1e30f, m1 = -1e30f, l0 = 0.f, l1 = 0.f;

    uint32_t a_off = (uint32_t)(warp * 16 + (lane & 15)) * AT_PITCH + ((lane >> 4) * 8) * 2;
    uint32_t kb_off = (uint32_t)(((lane >> 4) & 1) * 8 + (lane & 7)) * AT_PITCH
                    + (((lane >> 3) & 1) * 8) * 2;
    uint32_t v_off = (uint32_t)(((lane >> 3) & 1) * 8 + (lane & 7)) * AT_PITCH
                   + ((lane >> 4) * 8) * 2;

    const int iters = S_LEN / 64;
    for (int it = 0; it < iters; ++it) {
        int s = it & 1;
        if (it + 1 < iters) cpa_wait<1>(); else cpa_wait<0>();
        __syncthreads();

        uint32_t khb = kvbase + s * KVSTG;
        uint32_t vhb = khb + 2 * KVMAT;

        float C[8][4];
#pragma unroll
        for (int i = 0; i < 8; i++)
#pragma unroll
            for (int j = 0; j < 4; j++) C[i][j] = 0.f;

#pragma unroll
        for (int kt = 0; kt < 8; kt++) {
            uint32_t qa = qbase + a_off + kt * 32;
            uint32_t qh[4], ql[4];
            ldsm_x4(qh, qa);
            ldsm_x4(ql, qa + QMAT);
#pragma unroll
            for (int kb = 0; kb < 4; kb++) {
                uint32_t bh[4], bl[4];
                uint32_t ka = khb + kb_off + (uint32_t)kb * 16 * AT_PITCH + kt * 32;
                ldsm_x4(bh, ka);
                ldsm_x4(bl, ka + KVMAT);
                mma16816(C[2 * kb], qh, bh);
                mma16816(C[2 * kb], ql, bh);
                mma16816(C[2 * kb], qh, bl);
                mma16816(C[2 * kb + 1], qh, bh + 2);
                mma16816(C[2 * kb + 1], ql, bh + 2);
                mma16816(C[2 * kb + 1], qh, bl + 2);
            }
        }

        float t0 = -1e30f, t1 = -1e30f;
#pragma unroll
        for (int nt = 0; nt < 8; nt++) {
            t0 = fmaxf(t0, fmaxf(C[nt][0], C[nt][1]));
            t1 = fmaxf(t1, fmaxf(C[nt][2], C[nt][3]));
        }
        t0 = fmaxf(t0, __shfl_xor_sync(0xffffffffu, t0, 1));
        t0 = fmaxf(t0, __shfl_xor_sync(0xffffffffu, t0, 2));
        t1 = fmaxf(t1, __shfl_xor_sync(0xffffffffu, t1, 1));
        t1 = fmaxf(t1, __shfl_xor_sync(0xffffffffu, t1, 2));
        float mn0 = fmaxf(m0, t0), mn1 = fmaxf(m1, t1);
        float c0 = __expf(m0 - mn0), c1 = __expf(m1 - mn1);
        m0 = mn0; m1 = mn1;
        l0 *= c0; l1 *= c1;
#pragma unroll
        for (int nt = 0; nt < 16; nt++) {
            out[nt][0] *= c0; out[nt][1] *= c0;
            out[nt][2] *= c1; out[nt][3] *= c1;
        }
#pragma unroll
        for (int nt = 0; nt < 8; nt++) {
            C[nt][0] = __expf(C[nt][0] - m0);
            C[nt][1] = __expf(C[nt][1] - m0);
            C[nt][2] = __expf(C[nt][2] - m1);
            C[nt][3] = __expf(C[nt][3] - m1);
            l0 += C[nt][0] + C[nt][1];
            l1 += C[nt][2] + C[nt][3];
        }

#pragma unroll
        for (int ks = 0; ks < 4; ks++) {
            uint32_t ph[4], pl[4];
            {
                __half2 hh, ll;
                split_h(C[2 * ks][0], hh.x, ll.x); split_h(C[2 * ks][1], hh.y, ll.y);
                ph[0] = *(uint32_t*)&hh; pl[0] = *(uint32_t*)&ll;
                split_h(C[2 * ks][2], hh.x, ll.x); split_h(C[2 * ks][3], hh.y, ll.y);
                ph[1] = *(uint32_t*)&hh; pl[1] = *(uint32_t*)&ll;
                split_h(C[2 * ks + 1][0], hh.x, ll.x); split_h(C[2 * ks + 1][1], hh.y, ll.y);
                ph[2] = *(uint32_t*)&hh; pl[2] = *(uint32_t*)&ll;
                split_h(C[2 * ks + 1][2], hh.x, ll.x); split_h(C[2 * ks + 1][3], hh.y, ll.y);
                ph[3] = *(uint32_t*)&hh; pl[3] = *(uint32_t*)&ll;
            }
#pragma unroll
            for (int dp = 0; dp < 8; dp++) {
                uint32_t vh[4], vl[4];
                uint32_t va = vhb + v_off + (uint32_t)ks * 16 * AT_PITCH + dp * 32;
                ldsm_x4_t(vh, va);
                ldsm_x4_t(vl, va + KVMAT);
                mma16816(out[2 * dp], ph, vh);
                mma16816(out[2 * dp], pl, vh);
                mma16816(out[2 * dp], ph, vl);
                mma16816(out[2 * dp + 1], ph, vh + 2);
                mma16816(out[2 * dp + 1], pl, vh + 2);
                mma16816(out[2 * dp + 1], ph, vl + 2);
            }
        }

        __syncthreads();
        if (it + 2 < iters) {
            load_kv_stage(kvbase + s * KVSTG, Kh_, Kl_, Vh_, Vl_, (it + 2) * 64, hd, tid);
            cpa_commit();
        }
    }

    l0 += __shfl_xor_sync(0xffffffffu, l0, 1);
    l0 += __shfl_xor_sync(0xffffffffu, l0, 2);
    l1 += __shfl_xor_sync(0xffffffffu, l1, 1);
    l1 += __shfl_xor_sync(0xffffffffu, l1, 2);
    float i0 = 1.f / l0, i1 = 1.f / l1;
    int r0 = q0 + warp * 16 + (lane >> 2);
    int r1 = r0 + 8;
    int cb = hd * HEAD_DIM + (lane & 3) * 2;
#pragma unroll
    for (int nt = 0; nt < 16; nt++) {
        int col = cb + nt * 8;
        *(__half2*)(Ch + (size_t)r0 * CAT_K + col) =
            __floats2half2_rn(out[nt][0] * i0, out[nt][1] * i0);
        *(__half2*)(Ch + (size_t)r1 * CAT_K + col) =
            __floats2half2_rn(out[nt][2] * i1, out[nt][3] * i1);
    }
}

// ---------------- launch ----------------
extern "C" void kernel_launch(void* const* d_in, const int* in_sizes, int n_in,
                              void* d_out, int out_size) {
    const float* hidden = (const float*)d_in[0];
    const float* temb = (const float*)d_in[1];
    const float* rope_cos = (const float*)d_in[2];
    const float* rope_sin = (const float*)d_in[3];
    const float* norm_w = (const float*)d_in[4];
    const float* norm_b = (const float*)d_in[5];
    const float* mlp_w = (const float*)d_in[6];
    const float* mlp_b = (const float*)d_in[7];
    const float* q_w = (const float*)d_in[8];
    const float* q_b = (const float*)d_in[9];
    const float* k_w = (const float*)d_in[10];
    const float* k_b = (const float*)d_in[11];
    const float* v_w = (const float*)d_in[12];
    const float* v_b = (const float*)d_in[13];
    const float* rms_q_w = (const float*)d_in[14];
    const float* rms_k_w = (const float*)d_in[15];
    const float* out_w = (const float*)d_in[16];
    const float* out_b = (const float*)d_in[17];
    float* out = (float*)d_out;

    float *emb_p, *qkv_p, *bqkv_p;
    __half *nh, *wqkv, *wm, *wo, *cat;
    __half *qh, *ql, *kh, *kl, *vh, *vl;
    cudaGetSymbolAddress((void**)&emb_p, g_emb);
    cudaGetSymbolAddress((void**)&qkv_p, g_qkv);
    cudaGetSymbolAddress((void**)&bqkv_p, g_bqkv);
    cudaGetSymbolAddress((void**)&nh, g_nh);
    cudaGetSymbolAddress((void**)&wqkv, g_wqkv);
    cudaGetSymbolAddress((void**)&wm, g_wm);
    cudaGetSymbolAddress((void**)&wo, g_wo);
    cudaGetSymbolAddress((void**)&cat, g_cat);
    cudaGetSymbolAddress((void**)&qh, g_qh);
    cudaGetSymbolAddress((void**)&ql, g_ql);
    cudaGetSymbolAddress((void**)&kh, g_kh);
    cudaGetSymbolAddress((void**)&kl, g_kl);
    cudaGetSymbolAddress((void**)&vh, g_vh);
    cudaGetSymbolAddress((void**)&vl, g_vl);

    cudaFuncSetAttribute(gemm_mma<0>, cudaFuncAttributeMaxDynamicSharedMemorySize, GEMM_SMEM);
    cudaFuncSetAttribute(gemm_mma<1>, cudaFuncAttributeMaxDynamicSharedMemorySize, GEMM_SMEM);
    cudaFuncSetAttribute(gemm_mma<2>, cudaFuncAttributeMaxDynamicSharedMemorySize, GEMM_SMEM);
    cudaFuncSetAttribute(flash_mma, cudaFuncAttributeMaxDynamicSharedMemorySize, FLASH_SMEM);

    // 1. adaLN embedding (silu fused)
    emb_gemv<<<3 * DIM, 128>>>(temb, norm_w, norm_b, emb_p);
    // 2. weight conversions + qkv bias concat
    cvt_all<<<(unsigned)((CVT_TOTAL / 4 + 255) / 256), 256>>>(
        q_w, k_w, v_w, mlp_w, out_w, wqkv, wm, wo, q_b, k_b, v_b, bqkv_p);
    // 3. LayerNorm + modulate -> nh fp16
    ln_mod<<<S_LEN, 256>>>(hidden, emb_p, nh);
    // 4. fused QKV GEMM (N=9216, 256-wide tiles)   <-- ncu profiles this launch
    gemm_mma<0><<<(S_LEN / 128) * (QKV_N / 256), 512, GEMM_SMEM>>>(
        nh, wqkv, S_LEN, DIM, DIM, DIM,
        bqkv_p, qkv_p, QKV_N, nullptr, 0, 0, nullptr, nullptr);
    // 5. RMSNorm + RoPE + split to fp16 hi/lo (Q pre-scaled)
    rmsrope_split<<<dim3(S_LEN, HEADS), HEAD_DIM>>>(
        qkv_p, rope_cos, rope_sin, rms_q_w, rms_k_w, qh, ql, kh, kl, vh, vl);
    // 6. HMMA flash attention -> cat[:, :DIM]
    flash_mma<<<dim3(S_LEN / 128, HEADS), 256, FLASH_SMEM>>>(
        qh, ql, kh, kl, vh, vl, cat);
    // 7. MLP GEMM (+bias+gelu) -> cat[:, DIM:]
    gemm_mma<1><<<(S_LEN / 128) * (MLP_H / 256), 512, GEMM_SMEM>>>(
        nh, wm, S_LEN, DIM, DIM, DIM,
        mlp_b, nullptr, 0, cat, CAT_K, DIM, nullptr, nullptr);
    // 8. out-proj GEMM over K=15360 + gated residual -> d_out
    gemm_mma<2><<<(S_LEN / 128) * (DIM / 256), 512, GEMM_SMEM>>>(
        cat, wo, S_LEN, CAT_K, CAT_K, CAT_K,
        out_b, out, DIM, nullptr, 0, 0, hidden, emb_p + 2 * DIM);
}

// round 9
// speedup vs baseline: 13.3207x; 1.1065x over previous
#include <cuda_runtime.h>
#include <cuda_fp16.h>
#include <cstdint>
#include <math.h>

#define S_LEN 2048
#define DIM 3072
#define HEADS 24
#define HEAD_DIM 128
#define MLP_H 12288
#define CAT_K (DIM + MLP_H)   // 15360
#define QKV_N (3 * DIM)       // 9216

// ---------------- scratch (device globals; no runtime allocs allowed) -------
#define ALN __align__(128)
__device__ ALN float g_emb[3 * DIM];
__device__ ALN float g_qkv[S_LEN * QKV_N];
__device__ ALN float g_bqkv[QKV_N];
__device__ ALN __half g_nh[S_LEN * DIM];
__device__ ALN __half g_wqkv[QKV_N * DIM];
__device__ ALN __half g_wm[MLP_H * DIM];
__device__ ALN __half g_wo[DIM * CAT_K];
__device__ ALN __half g_cat[S_LEN * CAT_K];
__device__ ALN __half g_qh[S_LEN * DIM];
__device__ ALN __half g_ql[S_LEN * DIM];
__device__ ALN __half g_kh[S_LEN * DIM];
__device__ ALN __half g_kl[S_LEN * DIM];
__device__ ALN __half g_vh[S_LEN * DIM];
__device__ ALN __half g_vl[S_LEN * DIM];

// ---------------- PTX helpers ----------------
__device__ __forceinline__ uint32_t smem_u32(const void* p) {
    uint32_t a;
    asm("{ .reg .u64 t; cvta.to.shared.u64 t, %1; cvt.u32.u64 %0, t; }" : "=r"(a) : "l"(p));
    return a;
}
__device__ __forceinline__ void cpa16(uint32_t s, const void* g) {
    asm volatile("cp.async.cg.shared.global [%0], [%1], 16;" :: "r"(s), "l"(g));
}
__device__ __forceinline__ void cpa_commit() { asm volatile("cp.async.commit_group;" ::: "memory"); }
template <int N>
__device__ __forceinline__ void cpa_wait() { asm volatile("cp.async.wait_group %0;" :: "n"(N) : "memory"); }

__device__ __forceinline__ void ldsm_x4(uint32_t* r, uint32_t addr) {
    asm volatile("ldmatrix.sync.aligned.m8n8.x4.shared.b16 {%0,%1,%2,%3}, [%4];"
                 : "=r"(r[0]), "=r"(r[1]), "=r"(r[2]), "=r"(r[3]) : "r"(addr));
}
__device__ __forceinline__ void ldsm_x4_t(uint32_t* r, uint32_t addr) {
    asm volatile("ldmatrix.sync.aligned.m8n8.x4.trans.shared.b16 {%0,%1,%2,%3}, [%4];"
                 : "=r"(r[0]), "=r"(r[1]), "=r"(r[2]), "=r"(r[3]) : "r"(addr));
}
__device__ __forceinline__ void mma16816(float* d, const uint32_t* a, const uint32_t* b) {
    asm volatile(
        "mma.sync.aligned.m16n8k16.row.col.f32.f16.f16.f32 "
        "{%0,%1,%2,%3}, {%4,%5,%6,%7}, {%8,%9}, {%0,%1,%2,%3};"
        : "+f"(d[0]), "+f"(d[1]), "+f"(d[2]), "+f"(d[3])
        : "r"(a[0]), "r"(a[1]), "r"(a[2]), "r"(a[3]), "r"(b[0]), "r"(b[1]));
}

__device__ __forceinline__ float geluf(float x) {
    float inner = 0.7978845608028654f * (x + 0.044715f * x * x * x);
    return 0.5f * x * (1.f + tanhf(inner));
}
__device__ __forceinline__ void split_h(float v, __half& h, __half& l) {
    h = __float2half_rn(v);
    l = __float2half_rn(v - __half2float(h));
}

// ------- mma.sync fp16 GEMM: tile 128x128, 256 thr, warp tile 32x64 --------
// 2 CTAs/SM: barriers in one CTA are hidden by the other CTA's math.
#define BK 64
#define PITCHB 144
#define A_MAT (128 * PITCHB)              // 18432
#define B_MAT (128 * PITCHB)              // 18432
#define STAGE_BYTES (A_MAT + B_MAT)       // 36864
#define NSTG 3
#define GEMM_SMEM (NSTG * STAGE_BYTES)    // 110592

// 128 rows x 64 fp16 -> 1024 16B chunks, 4/thread (256 threads)
__device__ __forceinline__ void load_mat(uint32_t dst, const __half* g, int ld,
                                         int row0, int k0, int tid) {
    const __half* gp = g + (size_t)row0 * ld + k0;
#pragma unroll
    for (int i = 0; i < 4; i++) {
        int idx = tid + i * 256;
        int row = idx >> 3;
        int c = idx & 7;
        cpa16(dst + row * PITCHB + c * 16, gp + (size_t)row * ld + c * 8);
    }
}

template <int MODE>
__global__ __launch_bounds__(256, 2)
void gemm_mma(const __half* __restrict__ Ah,
              const __half* __restrict__ Bh,
              int Mtot, int Ktot, int lda, int ldb,
              const float* __restrict__ bias,
              float* __restrict__ Cf, int ldc,
              __half* __restrict__ Ch, int ldch, int ccol0,
              const float* __restrict__ hidden, const float* __restrict__ gate) {
    extern __shared__ char smem[];
    uint32_t sb = smem_u32(smem);
    int tid = threadIdx.x;
    int warp = tid >> 5, lane = tid & 31;
    int wm = warp & 3;        // 0..3 -> 32-row group
    int wn = warp >> 2;       // 0..1 -> 64-col group

    int mtiles = Mtot >> 7;
    int bm0 = (blockIdx.x % mtiles) << 7;
    int bn0 = (blockIdx.x / mtiles) << 7;

    float acc[2][8][4];
#pragma unroll
    for (int i = 0; i < 2; i++)
#pragma unroll
        for (int j = 0; j < 8; j++)
#pragma unroll
            for (int c = 0; c < 4; c++) acc[i][j][c] = 0.f;

    const int iters = Ktot / BK;

    // prologue: stages 0,1
#pragma unroll
    for (int s = 0; s < 2; s++) {
        uint32_t st = sb + s * STAGE_BYTES;
        load_mat(st, Ah, lda, bm0, s * BK, tid);
        load_mat(st + A_MAT, Bh, ldb, bn0, s * BK, tid);
        cpa_commit();
    }

    uint32_t a_off = (uint32_t)(wm * 32 + (lane & 15)) * PITCHB + ((lane >> 4) * 8) * 2;
    uint32_t b_off = (uint32_t)(wn * 64 + ((lane >> 4) & 1) * 8 + (lane & 7)) * PITCHB
                   + (((lane >> 3) & 1) * 8) * 2;

    for (int it = 0; it < iters; ++it) {
        int s = it % NSTG;
        if (it + 1 < iters) cpa_wait<1>(); else cpa_wait<0>();
        __syncthreads();

        if (it + 2 < iters) {
            int s2 = (it + 2) % NSTG;
            uint32_t st = sb + s2 * STAGE_BYTES;
            int k0 = (it + 2) * BK;
            load_mat(st, Ah, lda, bm0, k0, tid);
            load_mat(st + A_MAT, Bh, ldb, bn0, k0, tid);
            cpa_commit();
        }

        uint32_t stg = sb + s * STAGE_BYTES;
#pragma unroll
        for (int kk = 0; kk < 4; kk++) {
            uint32_t kb = kk * 32;
            uint32_t ah[2][4];
#pragma unroll
            for (int mi = 0; mi < 2; mi++)
                ldsm_x4(ah[mi], stg + a_off + (uint32_t)mi * 16 * PITCHB + kb);
#pragma unroll
            for (int p = 0; p < 4; p++) {
                uint32_t bh[4];
                ldsm_x4(bh, stg + A_MAT + b_off + (uint32_t)p * 16 * PITCHB + kb);
#pragma unroll
                for (int mi = 0; mi < 2; mi++) {
                    mma16816(acc[mi][2 * p + 0], ah[mi], bh + 0);
                    mma16816(acc[mi][2 * p + 1], ah[mi], bh + 2);
                }
            }
        }
    }

    int rq = lane >> 2;
    int cq = (lane & 3) * 2;
#pragma unroll
    for (int mi = 0; mi < 2; mi++) {
#pragma unroll
        for (int ni = 0; ni < 8; ni++) {
            int n = bn0 + wn * 64 + ni * 8 + cq;
#pragma unroll
            for (int half = 0; half < 2; half++) {
                size_t m = (size_t)bm0 + wm * 32 + mi * 16 + rq + half * 8;
                float v0 = acc[mi][ni][half * 2 + 0];
                float v1 = acc[mi][ni][half * 2 + 1];
                if (MODE == 0) {
                    float2 o = make_float2(v0 + bias[n], v1 + bias[n + 1]);
                    *(float2*)(Cf + m * ldc + n) = o;
                } else if (MODE == 1) {
                    float g0 = geluf(v0 + bias[n]);
                    float g1 = geluf(v1 + bias[n + 1]);
                    *(__half2*)(Ch + m * ldch + ccol0 + n) = __floats2half2_rn(g0, g1);
                } else {
                    const float* hp = hidden + m * ldc + n;
                    float2 hv = *(const float2*)hp;
                    float2 o;
                    o.x = hv.x + gate[n] * (v0 + bias[n]);
                    o.y = hv.y + gate[n + 1] * (v1 + bias[n + 1]);
                    *(float2*)(Cf + m * ldc + n) = o;
                }
            }
        }
    }
}

// ---------------- fused weight conversion + qkv bias concat ----------------
#define QW_N ((long)DIM * DIM)
#define CVT_TOTAL (3 * QW_N + (long)MLP_H * DIM + (long)DIM * CAT_K)

__global__ void cvt_all(const float* __restrict__ q_w, const float* __restrict__ k_w,
                        const float* __restrict__ v_w, const float* __restrict__ mlp_w,
                        const float* __restrict__ out_w,
                        __half* __restrict__ wqkv, __half* __restrict__ wm,
                        __half* __restrict__ wo,
                        const float* __restrict__ q_b, const float* __restrict__ k_b,
                        const float* __restrict__ v_b, float* __restrict__ bqkv) {
    long t = (long)blockIdx.x * blockDim.x + threadIdx.x;
    if (t < 3 * DIM / 4) {
        int i = (int)t * 4;
        const float* src = i < DIM ? q_b : (i < 2 * DIM ? k_b : v_b);
        *(float4*)(bqkv + i) = *(const float4*)(src + (i % DIM));
    }
    long i = t * 4;
    if (i >= CVT_TOTAL) return;
    const float* src;
    __half* dh;
    long off;
    if (i < QW_N) { src = q_w; off = i; dh = wqkv; }
    else if (i < 2 * QW_N) { src = k_w; off = i - QW_N; dh = wqkv + QW_N; }
    else if (i < 3 * QW_N) { src = v_w; off = i - 2 * QW_N; dh = wqkv + 2 * QW_N; }
    else if (i < 3 * QW_N + (long)MLP_H * DIM) { src = mlp_w; off = i - 3 * QW_N; dh = wm; }
    else { src = out_w; off = i - 3 * QW_N - (long)MLP_H * DIM; dh = wo; }
    float4 v = *(const float4*)(src + off);
    *(__half2*)(dh + off) = __floats2half2_rn(v.x, v.y);
    *(__half2*)(dh + off + 2) = __floats2half2_rn(v.z, v.w);
}

// ---------------- adaLN embedding GEMV with fused silu ----------------
__global__ __launch_bounds__(128) void emb_gemv(const float* __restrict__ temb,
                                                const float* __restrict__ w,
                                                const float* __restrict__ b,
                                                float* __restrict__ emb) {
    int jrow = blockIdx.x;
    const float* wr = w + (size_t)jrow * DIM;
    int tid = threadIdx.x;
    float s = 0.f;
    for (int i = tid * 4; i < DIM; i += 512) {
        float4 a = *(const float4*)(temb + i);
        float4 ww = *(const float4*)(wr + i);
        a.x = a.x / (1.f + __expf(-a.x));
        a.y = a.y / (1.f + __expf(-a.y));
        a.z = a.z / (1.f + __expf(-a.z));
        a.w = a.w / (1.f + __expf(-a.w));
        s += a.x * ww.x + a.y * ww.y + a.z * ww.z + a.w * ww.w;
    }
    for (int o = 16; o > 0; o >>= 1) s += __shfl_xor_sync(0xffffffffu, s, o);
    __shared__ float sm[4];
    if ((tid & 31) == 0) sm[tid >> 5] = s;
    __syncthreads();
    if (tid == 0) emb[jrow] = sm[0] + sm[1] + sm[2] + sm[3] + b[jrow];
}

// LayerNorm + adaLN modulate -> single fp16
__global__ __launch_bounds__(256) void ln_mod(const float* __restrict__ x,
                                              const float* __restrict__ emb,
                                              __half* __restrict__ nh) {
    int srow = blockIdx.x;
    int tid = threadIdx.x;
    const float* row = x + (size_t)srow * DIM;
    float sum = 0.f, sq = 0.f;
    for (int i = tid * 4; i < DIM; i += 1024) {
        float4 v = *(const float4*)(row + i);
        sum += v.x + v.y + v.z + v.w;
        sq += v.x * v.x + v.y * v.y + v.z * v.z + v.w * v.w;
    }
    for (int o = 16; o > 0; o >>= 1) {
        sum += __shfl_xor_sync(0xffffffffu, sum, o);
        sq += __shfl_xor_sync(0xffffffffu, sq, o);
    }
    __shared__ float s1[8], s2[8];
    if ((tid & 31) == 0) { s1[tid >> 5] = sum; s2[tid >> 5] = sq; }
    __syncthreads();
    sum = 0.f; sq = 0.f;
#pragma unroll
    for (int w = 0; w < 8; w++) { sum += s1[w]; sq += s2[w]; }
    float mean = sum * (1.f / DIM);
    float var = sq * (1.f / DIM) - mean * mean;
    float rstd = rsqrtf(var + 1e-6f);
    __half* oh = nh + (size_t)srow * DIM;
    for (int i = tid * 4; i < DIM; i += 1024) {
        float4 v = *(const float4*)(row + i);
        float4 sc = *(const float4*)(emb + DIM + i);
        float4 sh = *(const float4*)(emb + i);
        float o0 = (v.x - mean) * rstd * (1.f + sc.x) + sh.x;
        float o1 = (v.y - mean) * rstd * (1.f + sc.y) + sh.y;
        float o2 = (v.z - mean) * rstd * (1.f + sc.z) + sh.z;
        float o3 = (v.w - mean) * rstd * (1.f + sc.w) + sh.w;
        *(__half2*)(oh + i) = __floats2half2_rn(o0, o1);
        *(__half2*)(oh + i + 2) = __floats2half2_rn(o2, o3);
    }
}

// ---------------- RMSNorm + RoPE + fp16 hi/lo split (Q scaled) --------------
__global__ __launch_bounds__(128) void rmsrope_split(
        const float* __restrict__ QKV,
        const float* __restrict__ rc, const float* __restrict__ rs,
        const float* __restrict__ wq, const float* __restrict__ wk,
        __half* __restrict__ qh, __half* __restrict__ ql,
        __half* __restrict__ kh, __half* __restrict__ kl,
        __half* __restrict__ vh, __half* __restrict__ vl) {
    int s = blockIdx.x, hd = blockIdx.y;
    int d = threadIdx.x;
    int lane = d & 31, wid = d >> 5;
    __shared__ float red[4];
    float cosd = rc[s * HEAD_DIM + d];
    float sind = rs[s * HEAD_DIM + d];
    size_t gin = (size_t)s * QKV_N + hd * HEAD_DIM + d;
    size_t gout = (size_t)s * DIM + hd * HEAD_DIM + d;
    const float qscale = 0.08838834764831845f;
    {
        float v = QKV[gin];
        float ss = v * v;
        for (int o = 16; o > 0; o >>= 1) ss += __shfl_xor_sync(0xffffffffu, ss, o);
        if (lane == 0) red[wid] = ss;
        __syncthreads();
        float tot = red[0] + red[1] + red[2] + red[3];
        float xn = v * rsqrtf(tot * (1.f / HEAD_DIM) + 1e-6f) * wq[d];
        float part = __shfl_xor_sync(0xffffffffu, xn, 1);
        float rot = (d & 1) ? part : -part;
        float q = (xn * cosd + rot * sind) * qscale;
        __half h, l;
        split_h(q, h, l);
        qh[gout] = h; ql[gout] = l;
        __syncthreads();
    }
    {
        float v = QKV[gin + DIM];
        float ss = v * v;
        for (int o = 16; o > 0; o >>= 1) ss += __shfl_xor_sync(0xffffffffu, ss, o);
        if (lane == 0) red[wid] = ss;
        __syncthreads();
        float tot = red[0] + red[1] + red[2] + red[3];
        float xn = v * rsqrtf(tot * (1.f / HEAD_DIM) + 1e-6f) * wk[d];
        float part = __shfl_xor_sync(0xffffffffu, xn, 1);
        float rot = (d & 1) ? part : -part;
        float k = xn * cosd + rot * sind;
        __half h, l;
        split_h(k, h, l);
        kh[gout] = h; kl[gout] = l;
    }
    {
        float v = QKV[gin + 2 * DIM];
        __half h, l;
        split_h(v, h, l);
        vh[gout] = h; vl[gout] = l;
    }
}

// ---------------- HMMA flash attention ----------------
#define AT_PITCH 272
#define QMAT (128 * AT_PITCH)
#define KVMAT (64 * AT_PITCH)
#define KVSTG (4 * KVMAT)
#define FLASH_SMEM (2 * QMAT + 2 * KVSTG)  // 208896

__device__ __forceinline__ void load_kv_stage(uint32_t dst,
        const __half* Kh, const __half* Kl, const __half* Vh, const __half* Vl,
        int key0, int hd, int tid) {
#pragma unroll
    for (int i = 0; i < 16; i++) {
        int idx = tid + i * 256;
        int mat = idx >> 10;
        int rem = idx & 1023;
        int row = rem >> 4, c = rem & 15;
        const __half* src = (mat == 0) ? Kh : (mat == 1) ? Kl : (mat == 2) ? Vh : Vl;
        cpa16(dst + mat * KVMAT + row * AT_PITCH + c * 16,
              src + (size_t)(key0 + row) * DIM + hd * HEAD_DIM + c * 8);
    }
}

__global__ __launch_bounds__(256, 1) void flash_mma(
        const __half* __restrict__ Qh_, const __half* __restrict__ Ql_,
        const __half* __restrict__ Kh_, const __half* __restrict__ Kl_,
        const __half* __restrict__ Vh_, const __half* __restrict__ Vl_,
        __half* __restrict__ Ch) {
    extern __shared__ char smem[];
    uint32_t sb = smem_u32(smem);
    const uint32_t qbase = sb;
    const uint32_t kvbase = sb + 2 * QMAT;
    int tid = threadIdx.x, warp = tid >> 5, lane = tid & 31;
    int hd = blockIdx.y;
    int q0 = blockIdx.x * 128;

#pragma unroll
    for (int i = 0; i < 16; i++) {
        int idx = tid + i * 256;
        int mat = idx >> 11;
        int rem = idx & 2047;
        int row = rem >> 4, c = rem & 15;
        const __half* src = mat ? Ql_ : Qh_;
        cpa16(qbase + mat * QMAT + row * AT_PITCH + c * 16,
              src + (size_t)(q0 + row) * DIM + hd * HEAD_DIM + c * 8);
    }
    load_kv_stage(kvbase, Kh_, Kl_, Vh_, Vl_, 0, hd, tid);
    cpa_commit();
    load_kv_stage(kvbase + KVSTG, Kh_, Kl_, Vh_, Vl_, 64, hd, tid);
    cpa_commit();

    float out[16][4];
#pragma unroll
    for (int i = 0; i < 16; i++)
#pragma unroll
        for (int j = 0; j < 4; j++) out[i][j] = 0.f;
    float m0 = -1e30f, m1 = -1e30f, l0 = 0.f, l1 = 0.f;

    uint32_t a_off = (uint32_t)(warp * 16 + (lane & 15)) * AT_PITCH + ((lane >> 4) * 8) * 2;
    uint32_t kb_off = (uint32_t)(((lane >> 4) & 1) * 8 + (lane & 7)) * AT_PITCH
                    + (((lane >> 3) & 1) * 8) * 2;
    uint32_t v_off = (uint32_t)(((lane >> 3) & 1) * 8 + (lane & 7)) * AT_PITCH
                   + ((lane >> 4) * 8) * 2;

    const int iters = S_LEN / 64;
    for (int it = 0; it < iters; ++it) {
        int s = it & 1;
        if (it + 1 < iters) cpa_wait<1>(); else cpa_wait<0>();
        __syncthreads();

        uint32_t khb = kvbase + s * KVSTG;
        uint32_t vhb = khb + 2 * KVMAT;

        float C[8][4];
#pragma unroll
        for (int i = 0; i < 8; i++)
#pragma unroll
            for (int j = 0; j < 4; j++) C[i][j] = 0.f;

#pragma unroll
        for (int kt = 0; kt < 8; kt++) {
            uint32_t qa = qbase + a_off + kt * 32;
            uint32_t qh[4], ql[4];
            ldsm_x4(qh, qa);
            ldsm_x4(ql, qa + QMAT);
#pragma unroll
            for (int kb = 0; kb < 4; kb++) {
                uint32_t bh[4], bl[4];
                uint32_t ka = khb + kb_off + (uint32_t)kb * 16 * AT_PITCH + kt * 32;
                ldsm_x4(bh, ka);
                ldsm_x4(bl, ka + KVMAT);
                mma16816(C[2 * kb], qh, bh);
                mma16816(C[2 * kb], ql, bh);
                mma16816(C[2 * kb], qh, bl);
                mma16816(C[2 * kb + 1], qh, bh + 2);
                mma16816(C[2 * kb + 1], ql, bh + 2);
                mma16816(C[2 * kb + 1], qh, bl + 2);
            }
        }

        float t0 = -1e30f, t1 = -1e30f;
#pragma unroll
        for (int nt = 0; nt < 8; nt++) {
            t0 = fmaxf(t0, fmaxf(C[nt][0], C[nt][1]));
            t1 = fmaxf(t1, fmaxf(C[nt][2], C[nt][3]));
        }
        t0 = fmaxf(t0, __shfl_xor_sync(0xffffffffu, t0, 1));
        t0 = fmaxf(t0, __shfl_xor_sync(0xffffffffu, t0, 2));
        t1 = fmaxf(t1, __shfl_xor_sync(0xffffffffu, t1, 1));
        t1 = fmaxf(t1, __shfl_xor_sync(0xffffffffu, t1, 2));
        float mn0 = fmaxf(m0, t0), mn1 = fmaxf(m1, t1);
        float c0 = __expf(m0 - mn0), c1 = __expf(m1 - mn1);
        m0 = mn0; m1 = mn1;
        l0 *= c0; l1 *= c1;
#pragma unroll
        for (int nt = 0; nt < 16; nt++) {
            out[nt][0] *= c0; out[nt][1] *= c0;
            out[nt][2] *= c1; out[nt][3] *= c1;
        }
#pragma unroll
        for (int nt = 0; nt < 8; nt++) {
            C[nt][0] = __expf(C[nt][0] - m0);
            C[nt][1] = __expf(C[nt][1] - m0);
            C[nt][2] = __expf(C[nt][2] - m1);
            C[nt][3] = __expf(C[nt][3] - m1);
            l0 += C[nt][0] + C[nt][1];
            l1 += C[nt][2] + C[nt][3];
        }

#pragma unroll
        for (int ks = 0; ks < 4; ks++) {
            uint32_t ph[4], pl[4];
            {
                __half2 hh, ll;
                split_h(C[2 * ks][0], hh.x, ll.x); split_h(C[2 * ks][1], hh.y, ll.y);
                ph[0] = *(uint32_t*)&hh; pl[0] = *(uint32_t*)&ll;
                split_h(C[2 * ks][2], hh.x, ll.x); split_h(C[2 * ks][3], hh.y, ll.y);
                ph[1] = *(uint32_t*)&hh; pl[1] = *(uint32_t*)&ll;
                split_h(C[2 * ks + 1][0], hh.x, ll.x); split_h(C[2 * ks + 1][1], hh.y, ll.y);
                ph[2] = *(uint32_t*)&hh; pl[2] = *(uint32_t*)&ll;
                split_h(C[2 * ks + 1][2], hh.x, ll.x); split_h(C[2 * ks + 1][3], hh.y, ll.y);
                ph[3] = *(uint32_t*)&hh; pl[3] = *(uint32_t*)&ll;
            }
#pragma unroll
            for (int dp = 0; dp < 8; dp++) {
                uint32_t vh[4], vl[4];
                uint32_t va = vhb + v_off + (uint32_t)ks * 16 * AT_PITCH + dp * 32;
                ldsm_x4_t(vh, va);
                ldsm_x4_t(vl, va + KVMAT);
                mma16816(out[2 * dp], ph, vh);
                mma16816(out[2 * dp], pl, vh);
                mma16816(out[2 * dp], ph, vl);
                mma16816(out[2 * dp + 1], ph, vh + 2);
                mma16816(out[2 * dp + 1], pl, vh + 2);
                mma16816(out[2 * dp + 1], ph, vl + 2);
            }
        }

        __syncthreads();
        if (it + 2 < iters) {
            load_kv_stage(kvbase + s * KVSTG, Kh_, Kl_, Vh_, Vl_, (it + 2) * 64, hd, tid);
            cpa_commit();
        }
    }

    l0 += __shfl_xor_sync(0xffffffffu, l0, 1);
    l0 += __shfl_xor_sync(0xffffffffu, l0, 2);
    l1 += __shfl_xor_sync(0xffffffffu, l1, 1);
    l1 += __shfl_xor_sync(0xffffffffu, l1, 2);
    float i0 = 1.f / l0, i1 = 1.f / l1;
    int r0 = q0 + warp * 16 + (lane >> 2);
    int r1 = r0 + 8;
    int cb = hd * HEAD_DIM + (lane & 3) * 2;
#pragma unroll
    for (int nt = 0; nt < 16; nt++) {
        int col = cb + nt * 8;
        *(__half2*)(Ch + (size_t)r0 * CAT_K + col) =
            __floats2half2_rn(out[nt][0] * i0, out[nt][1] * i0);
        *(__half2*)(Ch + (size_t)r1 * CAT_K + col) =
            __floats2half2_rn(out[nt][2] * i1, out[nt][3] * i1);
    }
}

// ---------------- launch ----------------
extern "C" void kernel_launch(void* const* d_in, const int* in_sizes, int n_in,
                              void* d_out, int out_size) {
    const float* hidden = (const float*)d_in[0];
    const float* temb = (const float*)d_in[1];
    const float* rope_cos = (const float*)d_in[2];
    const float* rope_sin = (const float*)d_in[3];
    const float* norm_w = (const float*)d_in[4];
    const float* norm_b = (const float*)d_in[5];
    const float* mlp_w = (const float*)d_in[6];
    const float* mlp_b = (const float*)d_in[7];
    const float* q_w = (const float*)d_in[8];
    const float* q_b = (const float*)d_in[9];
    const float* k_w = (const float*)d_in[10];
    const float* k_b = (const float*)d_in[11];
    const float* v_w = (const float*)d_in[12];
    const float* v_b = (const float*)d_in[13];
    const float* rms_q_w = (const float*)d_in[14];
    const float* rms_k_w = (const float*)d_in[15];
    const float* out_w = (const float*)d_in[16];
    const float* out_b = (const float*)d_in[17];
    float* out = (float*)d_out;

    float *emb_p, *qkv_p, *bqkv_p;
    __half *nh, *wqkv, *wm, *wo, *cat;
    __half *qh, *ql, *kh, *kl, *vh, *vl;
    cudaGetSymbolAddress((void**)&emb_p, g_emb);
    cudaGetSymbolAddress((void**)&qkv_p, g_qkv);
    cudaGetSymbolAddress((void**)&bqkv_p, g_bqkv);
    cudaGetSymbolAddress((void**)&nh, g_nh);
    cudaGetSymbolAddress((void**)&wqkv, g_wqkv);
    cudaGetSymbolAddress((void**)&wm, g_wm);
    cudaGetSymbolAddress((void**)&wo, g_wo);
    cudaGetSymbolAddress((void**)&cat, g_cat);
    cudaGetSymbolAddress((void**)&qh, g_qh);
    cudaGetSymbolAddress((void**)&ql, g_ql);
    cudaGetSymbolAddress((void**)&kh, g_kh);
    cudaGetSymbolAddress((void**)&kl, g_kl);
    cudaGetSymbolAddress((void**)&vh, g_vh);
    cudaGetSymbolAddress((void**)&vl, g_vl);

    cudaFuncSetAttribute(gemm_mma<0>, cudaFuncAttributeMaxDynamicSharedMemorySize, GEMM_SMEM);
    cudaFuncSetAttribute(gemm_mma<1>, cudaFuncAttributeMaxDynamicSharedMemorySize, GEMM_SMEM);
    cudaFuncSetAttribute(gemm_mma<2>, cudaFuncAttributeMaxDynamicSharedMemorySize, GEMM_SMEM);
    cudaFuncSetAttribute(flash_mma, cudaFuncAttributeMaxDynamicSharedMemorySize, FLASH_SMEM);

    // 1. adaLN embedding (silu fused)
    emb_gemv<<<3 * DIM, 128>>>(temb, norm_w, norm_b, emb_p);
    // 2. weight conversions + qkv bias concat
    cvt_all<<<(unsigned)((CVT_TOTAL / 4 + 255) / 256), 256>>>(
        q_w, k_w, v_w, mlp_w, out_w, wqkv, wm, wo, q_b, k_b, v_b, bqkv_p);
    // 3. LayerNorm + modulate -> nh fp16
    ln_mod<<<S_LEN, 256>>>(hidden, emb_p, nh);
    // 4. fused QKV GEMM (N=9216)   <-- ncu profiles this launch
    gemm_mma<0><<<(S_LEN / 128) * (QKV_N / 128), 256, GEMM_SMEM>>>(
        nh, wqkv, S_LEN, DIM, DIM, DIM,
        bqkv_p, qkv_p, QKV_N, nullptr, 0, 0, nullptr, nullptr);
    // 5. RMSNorm + RoPE + split to fp16 hi/lo (Q pre-scaled)
    rmsrope_split<<<dim3(S_LEN, HEADS), HEAD_DIM>>>(
        qkv_p, rope_cos, rope_sin, rms_q_w, rms_k_w, qh, ql, kh, kl, vh, vl);
    // 6. HMMA flash attention -> cat[:, :DIM]
    flash_mma<<<dim3(S_LEN / 128, HEADS), 256, FLASH_SMEM>>>(
        qh, ql, kh, kl, vh, vl, cat);
    // 7. MLP GEMM (+bias+gelu) -> cat[:, DIM:]
    gemm_mma<1><<<(S_LEN / 128) * (MLP_H / 128), 256, GEMM_SMEM>>>(
        nh, wm, S_LEN, DIM, DIM, DIM,
        mlp_b, nullptr, 0, cat, CAT_K, DIM, nullptr, nullptr);
    // 8. out-proj GEMM over K=15360 + gated residual -> d_out
    gemm_mma<2><<<(S_LEN / 128) * (DIM / 128), 256, GEMM_SMEM>>>(
        cat, wo, S_LEN, CAT_K, CAT_K, CAT_K,
        out_b, out, DIM, nullptr, 0, 0, hidden, emb_p + 2 * DIM);
}